// round 7
// baseline (speedup 1.0000x reference)
#include <cuda_runtime.h>
#include <cuda_bf16.h>
#include <cstdint>
#include <math.h>

#define D_EMB 1024
#define HEADS 16
#define HD    64
#define SEQ   2048
#define NB    2
#define ROWS  (NB*SEQ)   // 4096
#define D_FF  4096

typedef __nv_bfloat16 bf16;

// ---------------- scratch (__device__ globals; no allocations allowed) ----------------
__device__ float g_Q1 [(size_t)ROWS*D_EMB];
__device__ float g_KV [(size_t)ROWS*D_EMB];
__device__ float g_TMP[(size_t)ROWS*D_EMB];
__device__ float g_X1 [(size_t)ROWS*D_EMB];
__device__ float g_X2 [(size_t)ROWS*D_EMB];
__device__ bf16 g_trgH[(size_t)ROWS*D_EMB],  g_trgL[(size_t)ROWS*D_EMB];
__device__ bf16 g_srcH[(size_t)ROWS*D_EMB],  g_srcL[(size_t)ROWS*D_EMB];
__device__ bf16 g_Q1H [(size_t)ROWS*D_EMB],  g_Q1L [(size_t)ROWS*D_EMB];
__device__ bf16 g_Q2H [(size_t)ROWS*D_EMB],  g_Q2L [(size_t)ROWS*D_EMB];
__device__ bf16 g_KVH [(size_t)ROWS*D_EMB],  g_KVL [(size_t)ROWS*D_EMB];
__device__ bf16 g_ATH [(size_t)ROWS*D_EMB],  g_ATL [(size_t)ROWS*D_EMB];
__device__ bf16 g_X1H [(size_t)ROWS*D_EMB],  g_X1L [(size_t)ROWS*D_EMB];
__device__ bf16 g_X2H [(size_t)ROWS*D_EMB],  g_X2L [(size_t)ROWS*D_EMB];
__device__ bf16 g_HH  [(size_t)ROWS*D_FF],   g_HL  [(size_t)ROWS*D_FF];
__device__ bf16 g_VTH [(size_t)NB*HEADS*HD*SEQ],  g_VTL[(size_t)NB*HEADS*HD*SEQ];
__device__ bf16 g_WqT1H[(size_t)D_EMB*D_EMB], g_WqT1L[(size_t)D_EMB*D_EMB];
__device__ bf16 g_WoT1H[(size_t)D_EMB*D_EMB], g_WoT1L[(size_t)D_EMB*D_EMB];
__device__ bf16 g_WqT2H[(size_t)D_EMB*D_EMB], g_WqT2L[(size_t)D_EMB*D_EMB];
__device__ bf16 g_WoT2H[(size_t)D_EMB*D_EMB], g_WoT2L[(size_t)D_EMB*D_EMB];
__device__ bf16 g_Wff1TH[(size_t)D_EMB*D_FF], g_Wff1TL[(size_t)D_EMB*D_FF];
__device__ bf16 g_Wff2TH[(size_t)D_EMB*D_FF], g_Wff2TL[(size_t)D_EMB*D_FF];

// ---------------- small helpers -------------------------------------------------------
__device__ __forceinline__ uint32_t pack_bf(bf16 a, bf16 b) {
    __nv_bfloat162 t = __halves2bfloat162(a, b);
    return *reinterpret_cast<uint32_t*>(&t);
}
__device__ __forceinline__ void split_bf(float v, bf16& h, bf16& l) {
    h = __float2bfloat16(v);
    l = __float2bfloat16(v - __bfloat162float(h));
}
__device__ __forceinline__ uint32_t smem_u32(const void* p) {
    uint32_t a;
    asm("{ .reg .u64 t; cvta.to.shared.u64 t, %1; cvt.u32.u64 %0, t; }" : "=r"(a) : "l"(p));
    return a;
}
__device__ __forceinline__ void mma16816(float* c, const uint32_t* a, const uint32_t* b) {
    asm volatile("mma.sync.aligned.m16n8k16.row.col.f32.bf16.bf16.f32 "
        "{%0,%1,%2,%3}, {%4,%5,%6,%7}, {%8,%9}, {%0,%1,%2,%3};"
        : "+f"(c[0]), "+f"(c[1]), "+f"(c[2]), "+f"(c[3])
        : "r"(a[0]), "r"(a[1]), "r"(a[2]), "r"(a[3]), "r"(b[0]), "r"(b[1]));
}
__device__ __forceinline__ void ldm_x4(uint32_t& r0, uint32_t& r1, uint32_t& r2, uint32_t& r3,
                                       uint32_t addr) {
    asm volatile("ldmatrix.sync.aligned.m8n8.x4.shared.b16 {%0,%1,%2,%3}, [%4];"
        : "=r"(r0), "=r"(r1), "=r"(r2), "=r"(r3) : "r"(addr));
}
#define CP16(dst, src) asm volatile("cp.async.cg.shared.global [%0], [%1], 16;" :: "r"(dst), "l"(src))
#define CP_COMMIT()    asm volatile("cp.async.commit_group;")
#define CP_WAIT0()     asm volatile("cp.async.wait_group 0;")
#define CP_WAIT1()     asm volatile("cp.async.wait_group 1;")

// ======================= tensor-core NT GEMM: C[M,N] = A[M,K] @ B[N,K]^T ==============
// Pre-split bf16 hi/lo; 3 mma passes issued PASS-MAJOR: all 8 independent accumulators
// get pass-1 before any acc is touched again (same-acc reuse distance 8 >= HMMA latency).
template<bool WC32, bool WC16>
__global__ __launch_bounds__(256, 2)
void mma_gemm(const bf16* __restrict__ Ah, const bf16* __restrict__ Al, int lda,
              const bf16* __restrict__ Bh, const bf16* __restrict__ Bl, int ldb,
              float* __restrict__ C32, bf16* __restrict__ C16h, bf16* __restrict__ C16l,
              int ldc, const float* __restrict__ bias, int K, int relu)
{
    constexpr int BN   = 64;
    constexpr int NT   = 4;
    constexpr int RSTR = 80;
    constexpr int AS   = 128 * RSTR;
    constexpr int BS   = BN * RSTR;
    constexpr int STG  = 2 * AS + 2 * BS;    // 30720; x3 stages = 92160 -> 2 CTAs/SM

    extern __shared__ __align__(16) char dsm[];
    const uint32_t sb = smem_u32(dsm);

    const int tid = threadIdx.x;
    const int lane = tid & 31, wid = tid >> 5;
    const int wm = wid & 3, wn = wid >> 2;
    const int g = lane >> 2, tig = lane & 3;
    const int lrow = lane & 7, seg = lane >> 3;

    const int bm = blockIdx.y * 128, bn = blockIdx.x * BN;

    float acc[2][NT][4];
    #pragma unroll
    for (int mt = 0; mt < 2; mt++)
        #pragma unroll
        for (int nt = 0; nt < NT; nt++)
            #pragma unroll
            for (int j = 0; j < 4; j++) acc[mt][nt][j] = 0.f;

    const int nc = K >> 5;

    auto load_stage = [&](int c) {
        const int k0 = c << 5;
        const uint32_t st = sb + (c % 3) * STG;
        #pragma unroll
        for (int i = 0; i < 2; i++) {
            int idx = tid + i * 256;
            int r = idx >> 2, sg = idx & 3;
            size_t go = (size_t)(bm + r) * lda + k0 + sg * 8;
            uint32_t so = r * RSTR + sg * 16;
            CP16(st + so, Ah + go);
            CP16(st + AS + so, Al + go);
        }
        {
            int r = tid >> 2, sg = tid & 3;
            size_t go = (size_t)(bn + r) * ldb + k0 + sg * 8;
            uint32_t so = r * RSTR + sg * 16;
            CP16(st + 2 * AS + so, Bh + go);
            CP16(st + 2 * AS + BS + so, Bl + go);
        }
    };

    load_stage(0); CP_COMMIT();
    load_stage(1); CP_COMMIT();

    for (int c = 0; c < nc; c++) {
        CP_WAIT1();
        __syncthreads();
        if (c + 2 < nc) { load_stage(c + 2); CP_COMMIT(); }

        const uint32_t st = sb + (c % 3) * STG;
        const uint32_t pAh = st, pAl = st + AS, pBh = st + 2 * AS, pBl = st + 2 * AS + BS;

        #pragma unroll
        for (int k16 = 0; k16 < 2; k16++) {
            const uint32_t koff = k16 * 32 + (seg >> 1) * 16;
            uint32_t ah[2][4], al[2][4];
            #pragma unroll
            for (int mt = 0; mt < 2; mt++) {
                uint32_t ro = (uint32_t)(wm * 32 + mt * 16 + (seg & 1) * 8 + lrow) * RSTR + koff;
                ldm_x4(ah[mt][0], ah[mt][1], ah[mt][2], ah[mt][3], pAh + ro);
                ldm_x4(al[mt][0], al[mt][1], al[mt][2], al[mt][3], pAl + ro);
            }
            uint32_t bh[NT][2], bl[NT][2];
            #pragma unroll
            for (int np = 0; np < NT / 2; np++) {
                uint32_t ro = (uint32_t)(wn * 32 + np * 16 + (seg & 1) * 8 + lrow) * RSTR + koff;
                uint32_t r0, r1, r2, r3;
                ldm_x4(r0, r1, r2, r3, pBh + ro);
                bh[2*np][0] = r0; bh[2*np][1] = r2; bh[2*np+1][0] = r1; bh[2*np+1][1] = r3;
                ldm_x4(r0, r1, r2, r3, pBl + ro);
                bl[2*np][0] = r0; bl[2*np][1] = r2; bl[2*np+1][0] = r1; bl[2*np+1][1] = r3;
            }
            // pass-major: 8 independent accs between same-acc reuses
            #pragma unroll
            for (int nt = 0; nt < NT; nt++)
                #pragma unroll
                for (int mt = 0; mt < 2; mt++)
                    mma16816(acc[mt][nt], ah[mt], bh[nt]);
            #pragma unroll
            for (int nt = 0; nt < NT; nt++)
                #pragma unroll
                for (int mt = 0; mt < 2; mt++)
                    mma16816(acc[mt][nt], ah[mt], bl[nt]);
            #pragma unroll
            for (int nt = 0; nt < NT; nt++)
                #pragma unroll
                for (int mt = 0; mt < 2; mt++)
                    mma16816(acc[mt][nt], al[mt], bh[nt]);
        }
    }

    #pragma unroll
    for (int mt = 0; mt < 2; mt++) {
        #pragma unroll
        for (int nt = 0; nt < NT; nt++) {
            int row = bm + wm * 32 + mt * 16 + g;
            int col = bn + wn * 32 + nt * 8 + tig * 2;
            float b0 = 0.f, b1 = 0.f;
            if (bias) { b0 = __ldg(bias + col); b1 = __ldg(bias + col + 1); }
            float v0 = acc[mt][nt][0] + b0, v1 = acc[mt][nt][1] + b1;
            float v2 = acc[mt][nt][2] + b0, v3 = acc[mt][nt][3] + b1;
            if (relu) {
                v0 = fmaxf(v0, 0.f); v1 = fmaxf(v1, 0.f);
                v2 = fmaxf(v2, 0.f); v3 = fmaxf(v3, 0.f);
            }
            size_t o0 = (size_t)row * ldc + col, o1 = (size_t)(row + 8) * ldc + col;
            if (WC32) {
                *(float2*)(C32 + o0) = make_float2(v0, v1);
                *(float2*)(C32 + o1) = make_float2(v2, v3);
            }
            if (WC16) {
                bf16 h0, l0, h1, l1;
                split_bf(v0, h0, l0); split_bf(v1, h1, l1);
                *(uint32_t*)(C16h + o0) = pack_bf(h0, h1);
                *(uint32_t*)(C16l + o0) = pack_bf(l0, l1);
                split_bf(v2, h0, l0); split_bf(v3, h1, l1);
                *(uint32_t*)(C16h + o1) = pack_bf(h0, h1);
                *(uint32_t*)(C16l + o1) = pack_bf(l0, l1);
            }
        }
    }
}

// ======================= fused flash attention ========================================
#define FQR 144
#define FPR 272
#define oQh 0
#define oQl 18432
#define oK0 36864
#define oVh 110592
#define oVl 128000
#define oPh 145408
#define oPl 180224
#define oRed 215040
#define FLASH_SMEM 217088

__global__ __launch_bounds__(256, 1)
void flash_attn(const bf16* __restrict__ Qh, const bf16* __restrict__ Ql,
                const bf16* __restrict__ Kh, const bf16* __restrict__ Kl,
                const bf16* __restrict__ Vth, const bf16* __restrict__ Vtl,
                bf16* __restrict__ Oh, bf16* __restrict__ Ol)
{
    extern __shared__ __align__(16) char dsm[];
    const uint32_t sb = smem_u32(dsm);
    float* red = (float*)(dsm + oRed);

    const int tid = threadIdx.x;
    const int lane = tid & 31, wid = tid >> 5;
    const int wm = wid & 3, wn = wid >> 2;
    const int g = lane >> 2, tig = lane & 3;
    const int lrow = lane & 7, seg = lane >> 3;

    const int z = blockIdx.y, n = z >> 4, h = z & 15;
    const int q0 = blockIdx.x * 128;
    const size_t qkbase = (size_t)n * SEQ * D_EMB + h * HD;
    const size_t vbase  = (size_t)z * HD * SEQ;

    #pragma unroll
    for (int i = 0; i < 4; i++) {
        int idx = tid + i * 256;
        int r = idx >> 3, sg = idx & 7;
        size_t gq = qkbase + (size_t)(q0 + r) * D_EMB + sg * 8;
        uint32_t so = r * FQR + sg * 16;
        CP16(sb + oQh + so, Qh + gq);
        CP16(sb + oQl + so, Ql + gq);
        size_t gk = qkbase + (size_t)r * D_EMB + sg * 8;
        CP16(sb + oK0 + so, Kh + gk);
        CP16(sb + oK0 + 18432 + so, Kl + gk);
    }
    CP_COMMIT();

    float m_prev[4], lsum[4], acc_o[2][4][4];
    #pragma unroll
    for (int i = 0; i < 4; i++) { m_prev[i] = -1e30f; lsum[i] = 0.f; }
    #pragma unroll
    for (int mt = 0; mt < 2; mt++)
        #pragma unroll
        for (int nt = 0; nt < 4; nt++)
            #pragma unroll
            for (int j = 0; j < 4; j++) acc_o[mt][nt][j] = 0.f;

    int myrow[4];
    #pragma unroll
    for (int mt = 0; mt < 2; mt++)
        #pragma unroll
        for (int hf = 0; hf < 2; hf++)
            myrow[mt*2+hf] = wm * 32 + mt * 16 + hf * 8 + g;

    for (int t = 0; t < 16; t++) {
        const int kv0 = t * 128;
        CP_WAIT0();
        __syncthreads();

        #pragma unroll
        for (int i = 0; i < 8; i++) {
            int p = i >> 2;
            int idx = tid + (i & 3) * 256;
            int r = idx >> 4, sg = idx & 15;
            size_t gv = vbase + (size_t)r * SEQ + kv0 + sg * 8;
            CP16(sb + (p ? oVl : oVh) + r * FPR + sg * 16, (p ? Vtl : Vth) + gv);
        }
        CP_COMMIT();
        {
            int tn = (t + 1 < 16) ? t + 1 : 15;
            uint32_t kst = oK0 + ((t + 1) & 1) * 36864;
            #pragma unroll
            for (int i = 0; i < 8; i++) {
                int p = i >> 2;
                int idx = tid + (i & 3) * 256;
                int r = idx >> 3, sg = idx & 7;
                size_t gk = qkbase + (size_t)(tn * 128 + r) * D_EMB + sg * 8;
                CP16(sb + kst + p * 18432 + r * FQR + sg * 16, (p ? Kl : Kh) + gk);
            }
        }
        CP_COMMIT();

        float s[2][8][4];
        #pragma unroll
        for (int mt = 0; mt < 2; mt++)
            #pragma unroll
            for (int nt = 0; nt < 8; nt++)
                #pragma unroll
                for (int j = 0; j < 4; j++) s[mt][nt][j] = 0.f;

        const uint32_t kst = sb + oK0 + (t & 1) * 36864;
        #pragma unroll
        for (int k16 = 0; k16 < 4; k16++) {
            const uint32_t koff = k16 * 32 + (seg >> 1) * 16;
            uint32_t ah[2][4], al[2][4];
            #pragma unroll
            for (int mt = 0; mt < 2; mt++) {
                uint32_t ro = (uint32_t)(wm * 32 + mt * 16 + (seg & 1) * 8 + lrow) * FQR + koff;
                ldm_x4(ah[mt][0], ah[mt][1], ah[mt][2], ah[mt][3], sb + oQh + ro);
                ldm_x4(al[mt][0], al[mt][1], al[mt][2], al[mt][3], sb + oQl + ro);
            }
            uint32_t bh[8][2], bl[8][2];
            #pragma unroll
            for (int np = 0; np < 4; np++) {
                uint32_t ro = (uint32_t)(wn * 64 + np * 16 + (seg & 1) * 8 + lrow) * FQR + koff;
                uint32_t r0, r1, r2, r3;
                ldm_x4(r0, r1, r2, r3, kst + ro);
                bh[2*np][0] = r0; bh[2*np][1] = r2; bh[2*np+1][0] = r1; bh[2*np+1][1] = r3;
                ldm_x4(r0, r1, r2, r3, kst + 18432 + ro);
                bl[2*np][0] = r0; bl[2*np][1] = r2; bl[2*np+1][0] = r1; bl[2*np+1][1] = r3;
            }
            // pass-major: 16 independent accumulators per pass
            #pragma unroll
            for (int nt = 0; nt < 8; nt++)
                #pragma unroll
                for (int mt = 0; mt < 2; mt++)
                    mma16816(s[mt][nt], ah[mt], bh[nt]);
            #pragma unroll
            for (int nt = 0; nt < 8; nt++)
                #pragma unroll
                for (int mt = 0; mt < 2; mt++)
                    mma16816(s[mt][nt], ah[mt], bl[nt]);
            #pragma unroll
            for (int nt = 0; nt < 8; nt++)
                #pragma unroll
                for (int mt = 0; mt < 2; mt++)
                    mma16816(s[mt][nt], al[mt], bh[nt]);
        }

        float mloc[4];
        #pragma unroll
        for (int i = 0; i < 4; i++) mloc[i] = -1e30f;
        #pragma unroll
        for (int mt = 0; mt < 2; mt++)
            #pragma unroll
            for (int nt = 0; nt < 8; nt++)
                #pragma unroll
                for (int hf = 0; hf < 2; hf++) {
                    mloc[mt*2+hf] = fmaxf(mloc[mt*2+hf], fmaxf(s[mt][nt][hf*2], s[mt][nt][hf*2+1]));
                }
        #pragma unroll
        for (int i = 0; i < 4; i++) {
            mloc[i] = fmaxf(mloc[i], __shfl_xor_sync(0xffffffffu, mloc[i], 1));
            mloc[i] = fmaxf(mloc[i], __shfl_xor_sync(0xffffffffu, mloc[i], 2));
        }
        if (tig == 0) {
            #pragma unroll
            for (int i = 0; i < 4; i++) red[wn * 128 + myrow[i]] = mloc[i];
        }
        __syncthreads();
        float m_new[4], alpha[4];
        #pragma unroll
        for (int i = 0; i < 4; i++) {
            float mt_raw = fmaxf(red[myrow[i]], red[128 + myrow[i]]);
            float mn = fmaxf(m_prev[i], mt_raw * 0.125f);
            alpha[i] = __expf(m_prev[i] - mn);
            m_new[i] = mn;
        }
        __syncthreads();

        float sl[4] = {0.f, 0.f, 0.f, 0.f};
        #pragma unroll
        for (int mt = 0; mt < 2; mt++)
            #pragma unroll
            for (int nt = 0; nt < 8; nt++)
                #pragma unroll
                for (int hf = 0; hf < 2; hf++) {
                    float p0 = __expf(s[mt][nt][hf*2]   * 0.125f - m_new[mt*2+hf]);
                    float p1 = __expf(s[mt][nt][hf*2+1] * 0.125f - m_new[mt*2+hf]);
                    s[mt][nt][hf*2] = p0; s[mt][nt][hf*2+1] = p1;
                    sl[mt*2+hf] += p0 + p1;
                }
        #pragma unroll
        for (int i = 0; i < 4; i++) {
            sl[i] += __shfl_xor_sync(0xffffffffu, sl[i], 1);
            sl[i] += __shfl_xor_sync(0xffffffffu, sl[i], 2);
        }
        if (tig == 0) {
            #pragma unroll
            for (int i = 0; i < 4; i++) red[wn * 128 + myrow[i]] = sl[i];
        }
        __syncthreads();
        #pragma unroll
        for (int i = 0; i < 4; i++) {
            lsum[i] = lsum[i] * alpha[i] + red[myrow[i]] + red[128 + myrow[i]];
            m_prev[i] = m_new[i];
        }
        #pragma unroll
        for (int mt = 0; mt < 2; mt++)
            #pragma unroll
            for (int nt = 0; nt < 4; nt++)
                #pragma unroll
                for (int hf = 0; hf < 2; hf++) {
                    acc_o[mt][nt][hf*2]   *= alpha[mt*2+hf];
                    acc_o[mt][nt][hf*2+1] *= alpha[mt*2+hf];
                }
        #pragma unroll
        for (int mt = 0; mt < 2; mt++)
            #pragma unroll
            for (int nt = 0; nt < 8; nt++)
                #pragma unroll
                for (int hf = 0; hf < 2; hf++) {
                    int row = wm * 32 + mt * 16 + hf * 8 + g;
                    int colb = (wn * 64 + nt * 8 + tig * 2) * 2;
                    bf16 h0, l0, h1, l1;
                    split_bf(s[mt][nt][hf*2],   h0, l0);
                    split_bf(s[mt][nt][hf*2+1], h1, l1);
                    *(uint32_t*)(dsm + oPh + row * FPR + colb) = pack_bf(h0, h1);
                    *(uint32_t*)(dsm + oPl + row * FPR + colb) = pack_bf(l0, l1);
                }
        CP_WAIT1();
        __syncthreads();

        #pragma unroll
        for (int k16 = 0; k16 < 8; k16++) {
            const uint32_t koff = k16 * 32 + (seg >> 1) * 16;
            uint32_t ah[2][4], al[2][4];
            #pragma unroll
            for (int mt = 0; mt < 2; mt++) {
                uint32_t ro = (uint32_t)(wm * 32 + mt * 16 + (seg & 1) * 8 + lrow) * FPR + koff;
                ldm_x4(ah[mt][0], ah[mt][1], ah[mt][2], ah[mt][3], sb + oPh + ro);
                ldm_x4(al[mt][0], al[mt][1], al[mt][2], al[mt][3], sb + oPl + ro);
            }
            uint32_t bh[4][2], bl[4][2];
            #pragma unroll
            for (int np = 0; np < 2; np++) {
                uint32_t ro = (uint32_t)(wn * 32 + np * 16 + (seg & 1) * 8 + lrow) * FPR + koff;
                uint32_t r0, r1, r2, r3;
                ldm_x4(r0, r1, r2, r3, sb + oVh + ro);
                bh[2*np][0] = r0; bh[2*np][1] = r2; bh[2*np+1][0] = r1; bh[2*np+1][1] = r3;
                ldm_x4(r0, r1, r2, r3, sb + oVl + ro);
                bl[2*np][0] = r0; bl[2*np][1] = r2; bl[2*np+1][0] = r1; bl[2*np+1][1] = r3;
            }
            // pass-major: 8 independent accumulators per pass
            #pragma unroll
            for (int nt = 0; nt < 4; nt++)
                #pragma unroll
                for (int mt = 0; mt < 2; mt++)
                    mma16816(acc_o[mt][nt], ah[mt], bh[nt]);
            #pragma unroll
            for (int nt = 0; nt < 4; nt++)
                #pragma unroll
                for (int mt = 0; mt < 2; mt++)
                    mma16816(acc_o[mt][nt], ah[mt], bl[nt]);
            #pragma unroll
            for (int nt = 0; nt < 4; nt++)
                #pragma unroll
                for (int mt = 0; mt < 2; mt++)
                    mma16816(acc_o[mt][nt], al[mt], bh[nt]);
        }
    }

    #pragma unroll
    for (int mt = 0; mt < 2; mt++)
        #pragma unroll
        for (int hf = 0; hf < 2; hf++) {
            int i = mt * 2 + hf;
            int row = myrow[i];
            float inv = 1.f / lsum[i];
            #pragma unroll
            for (int nt = 0; nt < 4; nt++) {
                float c0 = acc_o[mt][nt][hf*2]   * inv;
                float c1 = acc_o[mt][nt][hf*2+1] * inv;
                int col = wn * 32 + nt * 8 + tig * 2;
                size_t go = qkbase + (size_t)(q0 + row) * D_EMB + col;
                bf16 h0, l0, h1, l1;
                split_bf(c0, h0, l0); split_bf(c1, h1, l1);
                *(uint32_t*)(Oh + go) = pack_bf(h0, h1);
                *(uint32_t*)(Ol + go) = pack_bf(l0, l1);
            }
        }
}

// ======================= support kernels ==============================================
__global__ void cvt_split(const float* __restrict__ in, bf16* __restrict__ oh,
                          bf16* __restrict__ ol, size_t n4)
{
    size_t i = (size_t)blockIdx.x * blockDim.x + threadIdx.x;
    if (i >= n4) return;
    float4 v = *(const float4*)(in + i * 4);
    bf16 h0, l0, h1, l1, h2, l2, h3, l3;
    split_bf(v.x, h0, l0); split_bf(v.y, h1, l1);
    split_bf(v.z, h2, l2); split_bf(v.w, h3, l3);
    *(uint2*)(oh + i * 4) = make_uint2(pack_bf(h0, h1), pack_bf(h2, h3));
    *(uint2*)(ol + i * 4) = make_uint2(pack_bf(l0, l1), pack_bf(l2, l3));
}

__global__ void transpose_cvt(const float* __restrict__ in, bf16* __restrict__ oh,
                              bf16* __restrict__ ol, int R, int C)
{
    __shared__ float t[32][33];
    int r0 = blockIdx.y * 32, c0 = blockIdx.x * 32;
    t[threadIdx.y][threadIdx.x] = in[(size_t)(r0 + threadIdx.y) * C + c0 + threadIdx.x];
    __syncthreads();
    float v = t[threadIdx.x][threadIdx.y];
    bf16 h, l; split_bf(v, h, l);
    size_t o = (size_t)(c0 + threadIdx.y) * R + r0 + threadIdx.x;
    oh[o] = h; ol[o] = l;
}

__global__ void vt_build_cvt(const float* __restrict__ V, bf16* __restrict__ VTh,
                             bf16* __restrict__ VTl)
{
    __shared__ float t[32][33];
    int z = blockIdx.z, n = z >> 4, h = z & 15;
    int s0 = blockIdx.x * 32, d0 = blockIdx.y * 32;
    t[threadIdx.y][threadIdx.x] =
        V[(size_t)n * SEQ * D_EMB + (size_t)(s0 + threadIdx.y) * D_EMB + h * HD + d0 + threadIdx.x];
    __syncthreads();
    float v = t[threadIdx.x][threadIdx.y];
    bf16 hh, ll; split_bf(v, hh, ll);
    size_t o = ((size_t)z * HD + d0 + threadIdx.y) * SEQ + s0 + threadIdx.x;
    VTh[o] = hh; VTl[o] = ll;
}

__global__ void add_ln(const float* __restrict__ X, const float* __restrict__ R,
                       const float* __restrict__ g, const float* __restrict__ b,
                       float* __restrict__ Y, bf16* __restrict__ Yh, bf16* __restrict__ Yl)
{
    const int row = blockIdx.x;
    const float* px = X + (size_t)row * D_EMB;
    const float* pr = R + (size_t)row * D_EMB;
    const int tid = threadIdx.x;
    float v[4];
    float s = 0.f, s2 = 0.f;
    #pragma unroll
    for (int i = 0; i < 4; i++) {
        int c = tid + i*256;
        v[i] = px[c] + pr[c];
        s += v[i]; s2 += v[i]*v[i];
    }
    #pragma unroll
    for (int o = 16; o; o >>= 1) {
        s  += __shfl_xor_sync(0xffffffffu, s,  o);
        s2 += __shfl_xor_sync(0xffffffffu, s2, o);
    }
    __shared__ float sh[8], sh2[8];
    if ((tid & 31) == 0) { sh[tid >> 5] = s; sh2[tid >> 5] = s2; }
    __syncthreads();
    s = 0.f; s2 = 0.f;
    #pragma unroll
    for (int i = 0; i < 8; i++) { s += sh[i]; s2 += sh2[i]; }
    const float mean = s * (1.f / D_EMB);
    const float var  = s2 * (1.f / D_EMB) - mean * mean;
    const float rstd = rsqrtf(var + 1e-5f);
    #pragma unroll
    for (int i = 0; i < 4; i++) {
        int c = tid + i*256;
        float y = (v[i] - mean) * rstd * g[c] + b[c];
        Y[(size_t)row * D_EMB + c] = y;
        if (Yh) {
            bf16 hh, ll; split_bf(y, hh, ll);
            Yh[(size_t)row * D_EMB + c] = hh;
            Yl[(size_t)row * D_EMB + c] = ll;
        }
    }
}

// ======================================================================================
extern "C" void kernel_launch(void* const* d_in, const int* in_sizes, int n_in,
                              void* d_out, int out_size)
{
    const float* trg  = (const float*)d_in[0];
    const float* src  = (const float*)d_in[1];
    const float* Wq1  = (const float*)d_in[4];
    const float* bq1  = (const float*)d_in[5];
    const float* Wo1  = (const float*)d_in[6];
    const float* bo1  = (const float*)d_in[7];
    const float* Wq2  = (const float*)d_in[8];
    const float* bq2  = (const float*)d_in[9];
    const float* Wo2  = (const float*)d_in[10];
    const float* bo2  = (const float*)d_in[11];
    const float* Wff1 = (const float*)d_in[12];
    const float* bff1 = (const float*)d_in[13];
    const float* Wff2 = (const float*)d_in[14];
    const float* bff2 = (const float*)d_in[15];
    const float* ln1g = (const float*)d_in[16];
    const float* ln1b = (const float*)d_in[17];
    const float* ln2g = (const float*)d_in[18];
    const float* ln2b = (const float*)d_in[19];
    const float* ln3g = (const float*)d_in[20];
    const float* ln3b = (const float*)d_in[21];
    float* out = (float*)d_out;

    float *Q1, *KV, *TMP, *X1, *X2;
    cudaGetSymbolAddress((void**)&Q1,  g_Q1);
    cudaGetSymbolAddress((void**)&KV,  g_KV);
    cudaGetSymbolAddress((void**)&TMP, g_TMP);
    cudaGetSymbolAddress((void**)&X1,  g_X1);
    cudaGetSymbolAddress((void**)&X2,  g_X2);
    bf16 *trgH,*trgL,*srcH,*srcL,*Q1H,*Q1L,*Q2H,*Q2L,*KVH,*KVL,*ATH,*ATL;
    bf16 *X1H,*X1L,*X2H,*X2L,*HH,*HL,*VTH,*VTL;
    bf16 *WqT1H,*WqT1L,*WoT1H,*WoT1L,*WqT2H,*WqT2L,*WoT2H,*WoT2L;
    bf16 *Wff1TH,*Wff1TL,*Wff2TH,*Wff2TL;
    cudaGetSymbolAddress((void**)&trgH, g_trgH); cudaGetSymbolAddress((void**)&trgL, g_trgL);
    cudaGetSymbolAddress((void**)&srcH, g_srcH); cudaGetSymbolAddress((void**)&srcL, g_srcL);
    cudaGetSymbolAddress((void**)&Q1H,  g_Q1H);  cudaGetSymbolAddress((void**)&Q1L,  g_Q1L);
    cudaGetSymbolAddress((void**)&Q2H,  g_Q2H);  cudaGetSymbolAddress((void**)&Q2L,  g_Q2L);
    cudaGetSymbolAddress((void**)&KVH,  g_KVH);  cudaGetSymbolAddress((void**)&KVL,  g_KVL);
    cudaGetSymbolAddress((void**)&ATH,  g_ATH);  cudaGetSymbolAddress((void**)&ATL,  g_ATL);
    cudaGetSymbolAddress((void**)&X1H,  g_X1H);  cudaGetSymbolAddress((void**)&X1L,  g_X1L);
    cudaGetSymbolAddress((void**)&X2H,  g_X2H);  cudaGetSymbolAddress((void**)&X2L,  g_X2L);
    cudaGetSymbolAddress((void**)&HH,   g_HH);   cudaGetSymbolAddress((void**)&HL,   g_HL);
    cudaGetSymbolAddress((void**)&VTH,  g_VTH);  cudaGetSymbolAddress((void**)&VTL,  g_VTL);
    cudaGetSymbolAddress((void**)&WqT1H, g_WqT1H); cudaGetSymbolAddress((void**)&WqT1L, g_WqT1L);
    cudaGetSymbolAddress((void**)&WoT1H, g_WoT1H); cudaGetSymbolAddress((void**)&WoT1L, g_WoT1L);
    cudaGetSymbolAddress((void**)&WqT2H, g_WqT2H); cudaGetSymbolAddress((void**)&WqT2L, g_WqT2L);
    cudaGetSymbolAddress((void**)&WoT2H, g_WoT2H); cudaGetSymbolAddress((void**)&WoT2L, g_WoT2L);
    cudaGetSymbolAddress((void**)&Wff1TH, g_Wff1TH); cudaGetSymbolAddress((void**)&Wff1TL, g_Wff1TL);
    cudaGetSymbolAddress((void**)&Wff2TH, g_Wff2TH); cudaGetSymbolAddress((void**)&Wff2TL, g_Wff2TL);

    const int SMG = 3 * 30720;   // 92160 -> 2 CTAs/SM
    cudaFuncSetAttribute(mma_gemm<true ,true >, cudaFuncAttributeMaxDynamicSharedMemorySize, SMG);
    cudaFuncSetAttribute(mma_gemm<false,true >, cudaFuncAttributeMaxDynamicSharedMemorySize, SMG);
    cudaFuncSetAttribute(mma_gemm<true ,false>, cudaFuncAttributeMaxDynamicSharedMemorySize, SMG);
    cudaFuncSetAttribute(flash_attn, cudaFuncAttributeMaxDynamicSharedMemorySize, FLASH_SMEM);

    const dim3 t32(32, 32);
    const dim3 blk(256);
    const dim3 gP (D_EMB / 64, ROWS / 128);         // 16 x 32 = 512
    const dim3 gF1(D_FF / 64, ROWS / 128);          // 64 x 32 = 2048
    const dim3 gFA(SEQ / 128, NB*HEADS);            // 16 x 32
    const dim3 gVT(SEQ / 32, HD / 32, NB*HEADS);

    cvt_split<<<(ROWS*D_EMB/4 + 255)/256, 256>>>(trg, trgH, trgL, (size_t)ROWS*D_EMB/4);
    cvt_split<<<(ROWS*D_EMB/4 + 255)/256, 256>>>(src, srcH, srcL, (size_t)ROWS*D_EMB/4);
    transpose_cvt<<<dim3(32, 32), t32>>>(Wq1, WqT1H, WqT1L, D_EMB, D_EMB);

    // ---- self-attention: shared Wq1 on trg => qp==kp==vp, one projection
    mma_gemm<true ,true ><<<gP, blk, SMG>>>(trgH, trgL, D_EMB, WqT1H, WqT1L, D_EMB,
                                            Q1, Q1H, Q1L, D_EMB, bq1, D_EMB, 0);
    vt_build_cvt<<<gVT, t32>>>(Q1, VTH, VTL);
    flash_attn<<<gFA, blk, FLASH_SMEM>>>(Q1H, Q1L, Q1H, Q1L, VTH, VTL, ATH, ATL);
    transpose_cvt<<<dim3(32, 32), t32>>>(Wo1, WoT1H, WoT1L, D_EMB, D_EMB);
    mma_gemm<true ,false><<<gP, blk, SMG>>>(ATH, ATL, D_EMB, WoT1H, WoT1L, D_EMB,
                                            TMP, nullptr, nullptr, D_EMB, bo1, D_EMB, 0);
    add_ln<<<ROWS, 256>>>(trg, TMP, ln1g, ln1b, X1, X1H, X1L);

    // ---- cross-attention: K and V share the same projection of encoded_src
    transpose_cvt<<<dim3(32, 32), t32>>>(Wq2, WqT2H, WqT2L, D_EMB, D_EMB);
    mma_gemm<false,true ><<<gP, blk, SMG>>>(X1H, X1L, D_EMB, WqT2H, WqT2L, D_EMB,
                                            nullptr, Q2H, Q2L, D_EMB, bq2, D_EMB, 0);
    mma_gemm<true ,true ><<<gP, blk, SMG>>>(srcH, srcL, D_EMB, WqT2H, WqT2L, D_EMB,
                                            KV, KVH, KVL, D_EMB, bq2, D_EMB, 0);
    vt_build_cvt<<<gVT, t32>>>(KV, VTH, VTL);
    flash_attn<<<gFA, blk, FLASH_SMEM>>>(Q2H, Q2L, KVH, KVL, VTH, VTL, ATH, ATL);
    transpose_cvt<<<dim3(32, 32), t32>>>(Wo2, WoT2H, WoT2L, D_EMB, D_EMB);
    mma_gemm<true ,false><<<gP, blk, SMG>>>(ATH, ATL, D_EMB, WoT2H, WoT2L, D_EMB,
                                            TMP, nullptr, nullptr, D_EMB, bo2, D_EMB, 0);
    add_ln<<<ROWS, 256>>>(X1, TMP, ln2g, ln2b, X2, X2H, X2L);

    // ---- FFN
    transpose_cvt<<<dim3(128, 32), t32>>>(Wff1, Wff1TH, Wff1TL, D_EMB, D_FF);
    mma_gemm<false,true ><<<gF1, blk, SMG>>>(X2H, X2L, D_EMB, Wff1TH, Wff1TL, D_EMB,
                                             nullptr, HH, HL, D_FF, bff1, D_EMB, 1);
    transpose_cvt<<<dim3(32, 128), t32>>>(Wff2, Wff2TH, Wff2TL, D_FF, D_EMB);
    mma_gemm<true ,false><<<gP, blk, SMG>>>(HH, HL, D_FF, Wff2TH, Wff2TL, D_FF,
                                            TMP, nullptr, nullptr, D_EMB, bff2, D_FF, 0);
    add_ln<<<ROWS, 256>>>(X2, TMP, ln3g, ln3b, out, nullptr, nullptr);
}

// round 8
// speedup vs baseline: 1.0655x; 1.0655x over previous
#include <cuda_runtime.h>
#include <cuda_bf16.h>
#include <cstdint>
#include <math.h>

#define D_EMB 1024
#define HEADS 16
#define HD    64
#define SEQ   2048
#define NB    2
#define ROWS  (NB*SEQ)   // 4096
#define D_FF  4096

typedef __nv_bfloat16 bf16;

// ---------------- scratch (__device__ globals; no allocations allowed) ----------------
__device__ float g_Q1 [(size_t)ROWS*D_EMB];
__device__ float g_KV [(size_t)ROWS*D_EMB];
__device__ float g_TMP[(size_t)ROWS*D_EMB];
__device__ float g_X1 [(size_t)ROWS*D_EMB];
__device__ float g_X2 [(size_t)ROWS*D_EMB];
__device__ bf16 g_trgH[(size_t)ROWS*D_EMB],  g_trgL[(size_t)ROWS*D_EMB];
__device__ bf16 g_srcH[(size_t)ROWS*D_EMB],  g_srcL[(size_t)ROWS*D_EMB];
__device__ bf16 g_Q1H [(size_t)ROWS*D_EMB],  g_Q1L [(size_t)ROWS*D_EMB];
__device__ bf16 g_Q2H [(size_t)ROWS*D_EMB],  g_Q2L [(size_t)ROWS*D_EMB];
__device__ bf16 g_KVH [(size_t)ROWS*D_EMB],  g_KVL [(size_t)ROWS*D_EMB];
__device__ bf16 g_ATH [(size_t)ROWS*D_EMB],  g_ATL [(size_t)ROWS*D_EMB];
__device__ bf16 g_X1H [(size_t)ROWS*D_EMB],  g_X1L [(size_t)ROWS*D_EMB];
__device__ bf16 g_X2H [(size_t)ROWS*D_EMB],  g_X2L [(size_t)ROWS*D_EMB];
__device__ bf16 g_HH  [(size_t)ROWS*D_FF],   g_HL  [(size_t)ROWS*D_FF];
__device__ bf16 g_VTH [(size_t)NB*HEADS*HD*SEQ],  g_VTL[(size_t)NB*HEADS*HD*SEQ];
__device__ bf16 g_WqT1H[(size_t)D_EMB*D_EMB], g_WqT1L[(size_t)D_EMB*D_EMB];
__device__ bf16 g_WoT1H[(size_t)D_EMB*D_EMB], g_WoT1L[(size_t)D_EMB*D_EMB];
__device__ bf16 g_WqT2H[(size_t)D_EMB*D_EMB], g_WqT2L[(size_t)D_EMB*D_EMB];
__device__ bf16 g_WoT2H[(size_t)D_EMB*D_EMB], g_WoT2L[(size_t)D_EMB*D_EMB];
__device__ bf16 g_Wff1TH[(size_t)D_EMB*D_FF], g_Wff1TL[(size_t)D_EMB*D_FF];
__device__ bf16 g_Wff2TH[(size_t)D_EMB*D_FF], g_Wff2TL[(size_t)D_EMB*D_FF];

// ---------------- small helpers -------------------------------------------------------
__device__ __forceinline__ uint32_t pack_bf(bf16 a, bf16 b) {
    __nv_bfloat162 t = __halves2bfloat162(a, b);
    return *reinterpret_cast<uint32_t*>(&t);
}
__device__ __forceinline__ void split_bf(float v, bf16& h, bf16& l) {
    h = __float2bfloat16(v);
    l = __float2bfloat16(v - __bfloat162float(h));
}
__device__ __forceinline__ uint32_t smem_u32(const void* p) {
    uint32_t a;
    asm("{ .reg .u64 t; cvta.to.shared.u64 t, %1; cvt.u32.u64 %0, t; }" : "=r"(a) : "l"(p));
    return a;
}
__device__ __forceinline__ void mma16816(float* c, const uint32_t* a, const uint32_t* b) {
    asm volatile("mma.sync.aligned.m16n8k16.row.col.f32.bf16.bf16.f32 "
        "{%0,%1,%2,%3}, {%4,%5,%6,%7}, {%8,%9}, {%0,%1,%2,%3};"
        : "+f"(c[0]), "+f"(c[1]), "+f"(c[2]), "+f"(c[3])
        : "r"(a[0]), "r"(a[1]), "r"(a[2]), "r"(a[3]), "r"(b[0]), "r"(b[1]));
}
__device__ __forceinline__ void ldm_x4(uint32_t& r0, uint32_t& r1, uint32_t& r2, uint32_t& r3,
                                       uint32_t addr) {
    asm volatile("ldmatrix.sync.aligned.m8n8.x4.shared.b16 {%0,%1,%2,%3}, [%4];"
        : "=r"(r0), "=r"(r1), "=r"(r2), "=r"(r3) : "r"(addr));
}
#define CP16(dst, src) asm volatile("cp.async.cg.shared.global [%0], [%1], 16;" :: "r"(dst), "l"(src))
#define CP_COMMIT()    asm volatile("cp.async.commit_group;")
#define CP_WAIT0()     asm volatile("cp.async.wait_group 0;")
#define CP_WAIT1()     asm volatile("cp.async.wait_group 1;")

// ======================= tensor-core NT GEMM (round-5 proven config) ==================
// C[M,N] = A[M,K] @ B[N,K]^T. Pre-split bf16 hi/lo; 3 mma passes. BM=128, BN=128, BK=32.
// 2-stage cp.async pipeline, 2 CTAs/SM.
template<bool WC32, bool WC16>
__global__ __launch_bounds__(256, 2)
void mma_gemm(const bf16* __restrict__ Ah, const bf16* __restrict__ Al, int lda,
              const bf16* __restrict__ Bh, const bf16* __restrict__ Bl, int ldb,
              float* __restrict__ C32, bf16* __restrict__ C16h, bf16* __restrict__ C16l,
              int ldc, const float* __restrict__ bias, int K, int relu)
{
    constexpr int BN   = 128;
    constexpr int NT   = 8;
    constexpr int RSTR = 80;
    constexpr int AS   = 128 * RSTR;
    constexpr int BS   = BN * RSTR;
    constexpr int STG  = 2 * AS + 2 * BS;   // 40960; x2 = 81920 -> 2 CTAs/SM

    extern __shared__ __align__(16) char dsm[];
    const uint32_t sb = smem_u32(dsm);

    const int tid = threadIdx.x;
    const int lane = tid & 31, wid = tid >> 5;
    const int wm = wid & 3, wn = wid >> 2;
    const int g = lane >> 2, tig = lane & 3;
    const int lrow = lane & 7, seg = lane >> 3;

    const int bm = blockIdx.y * 128, bn = blockIdx.x * BN;

    float acc[2][NT][4];
    #pragma unroll
    for (int mt = 0; mt < 2; mt++)
        #pragma unroll
        for (int nt = 0; nt < NT; nt++)
            #pragma unroll
            for (int j = 0; j < 4; j++) acc[mt][nt][j] = 0.f;

    const int nc = K >> 5;

    auto load_stage = [&](int c) {
        const int k0 = c << 5;
        const uint32_t st = sb + (c & 1) * STG;
        #pragma unroll
        for (int i = 0; i < 2; i++) {
            int idx = tid + i * 256;
            int r = idx >> 2, sg = idx & 3;
            size_t go = (size_t)(bm + r) * lda + k0 + sg * 8;
            uint32_t so = r * RSTR + sg * 16;
            CP16(st + so, Ah + go);
            CP16(st + AS + so, Al + go);
        }
        #pragma unroll
        for (int i = 0; i < 2; i++) {
            int idx = tid + i * 256;
            int r = idx >> 2, sg = idx & 3;
            size_t go = (size_t)(bn + r) * ldb + k0 + sg * 8;
            uint32_t so = r * RSTR + sg * 16;
            CP16(st + 2 * AS + so, Bh + go);
            CP16(st + 2 * AS + BS + so, Bl + go);
        }
    };

    load_stage(0);
    CP_COMMIT();

    for (int c = 0; c < nc; c++) {
        if (c + 1 < nc) { load_stage(c + 1); CP_COMMIT(); CP_WAIT1(); }
        else            { CP_WAIT0(); }
        __syncthreads();

        const uint32_t st = sb + (c & 1) * STG;
        const uint32_t pAh = st, pAl = st + AS, pBh = st + 2 * AS, pBl = st + 2 * AS + BS;

        #pragma unroll
        for (int k16 = 0; k16 < 2; k16++) {
            const uint32_t koff = k16 * 32 + (seg >> 1) * 16;
            uint32_t ah[2][4], al[2][4];
            #pragma unroll
            for (int mt = 0; mt < 2; mt++) {
                uint32_t ro = (uint32_t)(wm * 32 + mt * 16 + (seg & 1) * 8 + lrow) * RSTR + koff;
                ldm_x4(ah[mt][0], ah[mt][1], ah[mt][2], ah[mt][3], pAh + ro);
                ldm_x4(al[mt][0], al[mt][1], al[mt][2], al[mt][3], pAl + ro);
            }
            uint32_t bh[NT][2], bl[NT][2];
            #pragma unroll
            for (int np = 0; np < NT / 2; np++) {
                uint32_t ro = (uint32_t)(wn * 64 + np * 16 + (seg & 1) * 8 + lrow) * RSTR + koff;
                uint32_t r0, r1, r2, r3;
                ldm_x4(r0, r1, r2, r3, pBh + ro);
                bh[2*np][0] = r0; bh[2*np][1] = r2; bh[2*np+1][0] = r1; bh[2*np+1][1] = r3;
                ldm_x4(r0, r1, r2, r3, pBl + ro);
                bl[2*np][0] = r0; bl[2*np][1] = r2; bl[2*np+1][0] = r1; bl[2*np+1][1] = r3;
            }
            #pragma unroll
            for (int nt = 0; nt < NT; nt++)
                #pragma unroll
                for (int mt = 0; mt < 2; mt++) {
                    mma16816(acc[mt][nt], ah[mt], bh[nt]);
                    mma16816(acc[mt][nt], ah[mt], bl[nt]);
                    mma16816(acc[mt][nt], al[mt], bh[nt]);
                }
        }
        __syncthreads();
    }

    #pragma unroll
    for (int mt = 0; mt < 2; mt++) {
        #pragma unroll
        for (int nt = 0; nt < NT; nt++) {
            int row = bm + wm * 32 + mt * 16 + g;
            int col = bn + wn * 64 + nt * 8 + tig * 2;
            float b0 = 0.f, b1 = 0.f;
            if (bias) { b0 = __ldg(bias + col); b1 = __ldg(bias + col + 1); }
            float v0 = acc[mt][nt][0] + b0, v1 = acc[mt][nt][1] + b1;
            float v2 = acc[mt][nt][2] + b0, v3 = acc[mt][nt][3] + b1;
            if (relu) {
                v0 = fmaxf(v0, 0.f); v1 = fmaxf(v1, 0.f);
                v2 = fmaxf(v2, 0.f); v3 = fmaxf(v3, 0.f);
            }
            size_t o0 = (size_t)row * ldc + col, o1 = (size_t)(row + 8) * ldc + col;
            if (WC32) {
                *(float2*)(C32 + o0) = make_float2(v0, v1);
                *(float2*)(C32 + o1) = make_float2(v2, v3);
            }
            if (WC16) {
                bf16 h0, l0, h1, l1;
                split_bf(v0, h0, l0); split_bf(v1, h1, l1);
                *(uint32_t*)(C16h + o0) = pack_bf(h0, h1);
                *(uint32_t*)(C16l + o0) = pack_bf(l0, l1);
                split_bf(v2, h0, l0); split_bf(v3, h1, l1);
                *(uint32_t*)(C16h + o1) = pack_bf(h0, h1);
                *(uint32_t*)(C16l + o1) = pack_bf(l0, l1);
            }
        }
    }
}

// ======================= fused flash attention (512 threads, 16 warps) ================
// Warp grid 4(m) x 4(n). Scores warp tile 32x32 (nt=4); PV warp tile 32x16 (nt=2).
#define FQR 144
#define FPR 272
#define oQh 0
#define oQl 18432
#define oK0 36864
#define oVh 110592
#define oVl 128000
#define oPh 145408
#define oPl 180224
#define oRed 215040          // 4 x 128 floats = 2048 bytes
#define FLASH_SMEM 217088

__global__ __launch_bounds__(512, 1)
void flash_attn(const bf16* __restrict__ Qh, const bf16* __restrict__ Ql,
                const bf16* __restrict__ Kh, const bf16* __restrict__ Kl,
                const bf16* __restrict__ Vth, const bf16* __restrict__ Vtl,
                bf16* __restrict__ Oh, bf16* __restrict__ Ol)
{
    extern __shared__ __align__(16) char dsm[];
    const uint32_t sb = smem_u32(dsm);
    float* red = (float*)(dsm + oRed);

    const int tid = threadIdx.x;
    const int lane = tid & 31, wid = tid >> 5;
    const int wm = wid & 3, wn = wid >> 2;       // 4 x 4 warps
    const int g = lane >> 2, tig = lane & 3;
    const int lrow = lane & 7, seg = lane >> 3;

    const int z = blockIdx.y, n = z >> 4, h = z & 15;
    const int q0 = blockIdx.x * 128;
    const size_t qkbase = (size_t)n * SEQ * D_EMB + h * HD;
    const size_t vbase  = (size_t)z * HD * SEQ;

    // ---- preload Q tile + K tile 0 ----
    #pragma unroll
    for (int i = 0; i < 2; i++) {
        int idx = tid + i * 512;                  // 1024 slots: 128 rows x 8 segs
        int r = idx >> 3, sg = idx & 7;
        size_t gq = qkbase + (size_t)(q0 + r) * D_EMB + sg * 8;
        uint32_t so = r * FQR + sg * 16;
        CP16(sb + oQh + so, Qh + gq);
        CP16(sb + oQl + so, Ql + gq);
        size_t gk = qkbase + (size_t)r * D_EMB + sg * 8;
        CP16(sb + oK0 + so, Kh + gk);
        CP16(sb + oK0 + 18432 + so, Kl + gk);
    }
    CP_COMMIT();

    float m_prev[4], lsum[4], acc_o[2][2][4];
    #pragma unroll
    for (int i = 0; i < 4; i++) { m_prev[i] = -1e30f; lsum[i] = 0.f; }
    #pragma unroll
    for (int mt = 0; mt < 2; mt++)
        #pragma unroll
        for (int nt = 0; nt < 2; nt++)
            #pragma unroll
            for (int j = 0; j < 4; j++) acc_o[mt][nt][j] = 0.f;

    int myrow[4];
    #pragma unroll
    for (int mt = 0; mt < 2; mt++)
        #pragma unroll
        for (int hf = 0; hf < 2; hf++)
            myrow[mt*2+hf] = wm * 32 + mt * 16 + hf * 8 + g;

    for (int t = 0; t < 16; t++) {
        const int kv0 = t * 128;
        CP_WAIT0();
        __syncthreads();

        // V(t)
        #pragma unroll
        for (int i = 0; i < 4; i++) {
            int p = i >> 1;
            int idx = tid + (i & 1) * 512;        // 1024 slots: 64 rows x 16 segs
            int r = idx >> 4, sg = idx & 15;
            size_t gv = vbase + (size_t)r * SEQ + kv0 + sg * 8;
            CP16(sb + (p ? oVl : oVh) + r * FPR + sg * 16, (p ? Vtl : Vth) + gv);
        }
        CP_COMMIT();
        // K(t+1) prefetch (clamped on last tile)
        {
            int tn = (t + 1 < 16) ? t + 1 : 15;
            uint32_t kst = oK0 + ((t + 1) & 1) * 36864;
            #pragma unroll
            for (int i = 0; i < 4; i++) {
                int p = i >> 1;
                int idx = tid + (i & 1) * 512;
                int r = idx >> 3, sg = idx & 7;
                size_t gk = qkbase + (size_t)(tn * 128 + r) * D_EMB + sg * 8;
                CP16(sb + kst + p * 18432 + r * FQR + sg * 16, (p ? Kl : Kh) + gk);
            }
        }
        CP_COMMIT();

        // ---- scores: S = Q @ K(t)^T, warp tile 32x32 ----
        float s[2][4][4];
        #pragma unroll
        for (int mt = 0; mt < 2; mt++)
            #pragma unroll
            for (int nt = 0; nt < 4; nt++)
                #pragma unroll
                for (int j = 0; j < 4; j++) s[mt][nt][j] = 0.f;

        const uint32_t kst = sb + oK0 + (t & 1) * 36864;
        #pragma unroll
        for (int k16 = 0; k16 < 4; k16++) {
            const uint32_t koff = k16 * 32 + (seg >> 1) * 16;
            uint32_t ah[2][4], al[2][4];
            #pragma unroll
            for (int mt = 0; mt < 2; mt++) {
                uint32_t ro = (uint32_t)(wm * 32 + mt * 16 + (seg & 1) * 8 + lrow) * FQR + koff;
                ldm_x4(ah[mt][0], ah[mt][1], ah[mt][2], ah[mt][3], sb + oQh + ro);
                ldm_x4(al[mt][0], al[mt][1], al[mt][2], al[mt][3], sb + oQl + ro);
            }
            uint32_t bh[4][2], bl[4][2];
            #pragma unroll
            for (int np = 0; np < 2; np++) {
                uint32_t ro = (uint32_t)(wn * 32 + np * 16 + (seg & 1) * 8 + lrow) * FQR + koff;
                uint32_t r0, r1, r2, r3;
                ldm_x4(r0, r1, r2, r3, kst + ro);
                bh[2*np][0] = r0; bh[2*np][1] = r2; bh[2*np+1][0] = r1; bh[2*np+1][1] = r3;
                ldm_x4(r0, r1, r2, r3, kst + 18432 + ro);
                bl[2*np][0] = r0; bl[2*np][1] = r2; bl[2*np+1][0] = r1; bl[2*np+1][1] = r3;
            }
            #pragma unroll
            for (int nt = 0; nt < 4; nt++)
                #pragma unroll
                for (int mt = 0; mt < 2; mt++) {
                    mma16816(s[mt][nt], ah[mt], bh[nt]);
                    mma16816(s[mt][nt], ah[mt], bl[nt]);
                    mma16816(s[mt][nt], al[mt], bh[nt]);
                }
        }

        // ---- online softmax; row stats across 4 wn-groups ----
        float mloc[4];
        #pragma unroll
        for (int i = 0; i < 4; i++) mloc[i] = -1e30f;
        #pragma unroll
        for (int mt = 0; mt < 2; mt++)
            #pragma unroll
            for (int nt = 0; nt < 4; nt++)
                #pragma unroll
                for (int hf = 0; hf < 2; hf++)
                    mloc[mt*2+hf] = fmaxf(mloc[mt*2+hf], fmaxf(s[mt][nt][hf*2], s[mt][nt][hf*2+1]));
        #pragma unroll
        for (int i = 0; i < 4; i++) {
            mloc[i] = fmaxf(mloc[i], __shfl_xor_sync(0xffffffffu, mloc[i], 1));
            mloc[i] = fmaxf(mloc[i], __shfl_xor_sync(0xffffffffu, mloc[i], 2));
        }
        if (tig == 0) {
            #pragma unroll
            for (int i = 0; i < 4; i++) red[wn * 128 + myrow[i]] = mloc[i];
        }
        __syncthreads();
        float m_new[4], alpha[4];
        #pragma unroll
        for (int i = 0; i < 4; i++) {
            float mr = fmaxf(fmaxf(red[myrow[i]], red[128 + myrow[i]]),
                             fmaxf(red[256 + myrow[i]], red[384 + myrow[i]]));
            float mn = fmaxf(m_prev[i], mr * 0.125f);
            alpha[i] = __expf(m_prev[i] - mn);
            m_new[i] = mn;
        }
        __syncthreads();

        float sl[4] = {0.f, 0.f, 0.f, 0.f};
        #pragma unroll
        for (int mt = 0; mt < 2; mt++)
            #pragma unroll
            for (int nt = 0; nt < 4; nt++)
                #pragma unroll
                for (int hf = 0; hf < 2; hf++) {
                    float p0 = __expf(s[mt][nt][hf*2]   * 0.125f - m_new[mt*2+hf]);
                    float p1 = __expf(s[mt][nt][hf*2+1] * 0.125f - m_new[mt*2+hf]);
                    s[mt][nt][hf*2] = p0; s[mt][nt][hf*2+1] = p1;
                    sl[mt*2+hf] += p0 + p1;
                }
        #pragma unroll
        for (int i = 0; i < 4; i++) {
            sl[i] += __shfl_xor_sync(0xffffffffu, sl[i], 1);
            sl[i] += __shfl_xor_sync(0xffffffffu, sl[i], 2);
        }
        if (tig == 0) {
            #pragma unroll
            for (int i = 0; i < 4; i++) red[wn * 128 + myrow[i]] = sl[i];
        }
        __syncthreads();
        #pragma unroll
        for (int i = 0; i < 4; i++) {
            lsum[i] = lsum[i] * alpha[i] + red[myrow[i]] + red[128 + myrow[i]]
                                         + red[256 + myrow[i]] + red[384 + myrow[i]];
            m_prev[i] = m_new[i];
        }
        #pragma unroll
        for (int mt = 0; mt < 2; mt++)
            #pragma unroll
            for (int nt = 0; nt < 2; nt++)
                #pragma unroll
                for (int hf = 0; hf < 2; hf++) {
                    acc_o[mt][nt][hf*2]   *= alpha[mt*2+hf];
                    acc_o[mt][nt][hf*2+1] *= alpha[mt*2+hf];
                }
        // P -> smem (each warp writes its 32-col slice)
        #pragma unroll
        for (int mt = 0; mt < 2; mt++)
            #pragma unroll
            for (int nt = 0; nt < 4; nt++)
                #pragma unroll
                for (int hf = 0; hf < 2; hf++) {
                    int row = wm * 32 + mt * 16 + hf * 8 + g;
                    int colb = (wn * 32 + nt * 8 + tig * 2) * 2;
                    bf16 h0, l0, h1, l1;
                    split_bf(s[mt][nt][hf*2],   h0, l0);
                    split_bf(s[mt][nt][hf*2+1], h1, l1);
                    *(uint32_t*)(dsm + oPh + row * FPR + colb) = pack_bf(h0, h1);
                    *(uint32_t*)(dsm + oPl + row * FPR + colb) = pack_bf(l0, l1);
                }
        CP_WAIT1();
        __syncthreads();

        // ---- O += P @ V, warp tile 32x16 ----
        #pragma unroll
        for (int k16 = 0; k16 < 8; k16++) {
            const uint32_t koff = k16 * 32 + (seg >> 1) * 16;
            uint32_t ah[2][4], al[2][4];
            #pragma unroll
            for (int mt = 0; mt < 2; mt++) {
                uint32_t ro = (uint32_t)(wm * 32 + mt * 16 + (seg & 1) * 8 + lrow) * FPR + koff;
                ldm_x4(ah[mt][0], ah[mt][1], ah[mt][2], ah[mt][3], sb + oPh + ro);
                ldm_x4(al[mt][0], al[mt][1], al[mt][2], al[mt][3], sb + oPl + ro);
            }
            uint32_t bh[2][2], bl[2][2];
            {
                uint32_t ro = (uint32_t)(wn * 16 + (seg & 1) * 8 + lrow) * FPR + koff;
                uint32_t r0, r1, r2, r3;
                ldm_x4(r0, r1, r2, r3, sb + oVh + ro);
                bh[0][0] = r0; bh[0][1] = r2; bh[1][0] = r1; bh[1][1] = r3;
                ldm_x4(r0, r1, r2, r3, sb + oVl + ro);
                bl[0][0] = r0; bl[0][1] = r2; bl[1][0] = r1; bl[1][1] = r3;
            }
            #pragma unroll
            for (int nt = 0; nt < 2; nt++)
                #pragma unroll
                for (int mt = 0; mt < 2; mt++) {
                    mma16816(acc_o[mt][nt], ah[mt], bh[nt]);
                    mma16816(acc_o[mt][nt], ah[mt], bl[nt]);
                    mma16816(acc_o[mt][nt], al[mt], bh[nt]);
                }
        }
    }

    // ---- epilogue: O / l -> bf16 hi/lo ----
    #pragma unroll
    for (int mt = 0; mt < 2; mt++)
        #pragma unroll
        for (int hf = 0; hf < 2; hf++) {
            int i = mt * 2 + hf;
            int row = myrow[i];
            float inv = 1.f / lsum[i];
            #pragma unroll
            for (int nt = 0; nt < 2; nt++) {
                float c0 = acc_o[mt][nt][hf*2]   * inv;
                float c1 = acc_o[mt][nt][hf*2+1] * inv;
                int col = wn * 16 + nt * 8 + tig * 2;
                size_t go = qkbase + (size_t)(q0 + row) * D_EMB + col;
                bf16 h0, l0, h1, l1;
                split_bf(c0, h0, l0); split_bf(c1, h1, l1);
                *(uint32_t*)(Oh + go) = pack_bf(h0, h1);
                *(uint32_t*)(Ol + go) = pack_bf(l0, l1);
            }
        }
}

// ======================= support kernels ==============================================
__global__ void cvt_split(const float* __restrict__ in, bf16* __restrict__ oh,
                          bf16* __restrict__ ol, size_t n4)
{
    size_t i = (size_t)blockIdx.x * blockDim.x + threadIdx.x;
    if (i >= n4) return;
    float4 v = *(const float4*)(in + i * 4);
    bf16 h0, l0, h1, l1, h2, l2, h3, l3;
    split_bf(v.x, h0, l0); split_bf(v.y, h1, l1);
    split_bf(v.z, h2, l2); split_bf(v.w, h3, l3);
    *(uint2*)(oh + i * 4) = make_uint2(pack_bf(h0, h1), pack_bf(h2, h3));
    *(uint2*)(ol + i * 4) = make_uint2(pack_bf(l0, l1), pack_bf(l2, l3));
}

__global__ void transpose_cvt(const float* __restrict__ in, bf16* __restrict__ oh,
                              bf16* __restrict__ ol, int R, int C)
{
    __shared__ float t[32][33];
    int r0 = blockIdx.y * 32, c0 = blockIdx.x * 32;
    t[threadIdx.y][threadIdx.x] = in[(size_t)(r0 + threadIdx.y) * C + c0 + threadIdx.x];
    __syncthreads();
    float v = t[threadIdx.x][threadIdx.y];
    bf16 h, l; split_bf(v, h, l);
    size_t o = (size_t)(c0 + threadIdx.y) * R + r0 + threadIdx.x;
    oh[o] = h; ol[o] = l;
}

__global__ void vt_build_cvt(const float* __restrict__ V, bf16* __restrict__ VTh,
                             bf16* __restrict__ VTl)
{
    __shared__ float t[32][33];
    int z = blockIdx.z, n = z >> 4, h = z & 15;
    int s0 = blockIdx.x * 32, d0 = blockIdx.y * 32;
    t[threadIdx.y][threadIdx.x] =
        V[(size_t)n * SEQ * D_EMB + (size_t)(s0 + threadIdx.y) * D_EMB + h * HD + d0 + threadIdx.x];
    __syncthreads();
    float v = t[threadIdx.x][threadIdx.y];
    bf16 hh, ll; split_bf(v, hh, ll);
    size_t o = ((size_t)z * HD + d0 + threadIdx.y) * SEQ + s0 + threadIdx.x;
    VTh[o] = hh; VTl[o] = ll;
}

__global__ void add_ln(const float* __restrict__ X, const float* __restrict__ R,
                       const float* __restrict__ g, const float* __restrict__ b,
                       float* __restrict__ Y, bf16* __restrict__ Yh, bf16* __restrict__ Yl)
{
    const int row = blockIdx.x;
    const float* px = X + (size_t)row * D_EMB;
    const float* pr = R + (size_t)row * D_EMB;
    const int tid = threadIdx.x;
    float v[4];
    float s = 0.f, s2 = 0.f;
    #pragma unroll
    for (int i = 0; i < 4; i++) {
        int c = tid + i*256;
        v[i] = px[c] + pr[c];
        s += v[i]; s2 += v[i]*v[i];
    }
    #pragma unroll
    for (int o = 16; o; o >>= 1) {
        s  += __shfl_xor_sync(0xffffffffu, s,  o);
        s2 += __shfl_xor_sync(0xffffffffu, s2, o);
    }
    __shared__ float sh[8], sh2[8];
    if ((tid & 31) == 0) { sh[tid >> 5] = s; sh2[tid >> 5] = s2; }
    __syncthreads();
    s = 0.f; s2 = 0.f;
    #pragma unroll
    for (int i = 0; i < 8; i++) { s += sh[i]; s2 += sh2[i]; }
    const float mean = s * (1.f / D_EMB);
    const float var  = s2 * (1.f / D_EMB) - mean * mean;
    const float rstd = rsqrtf(var + 1e-5f);
    #pragma unroll
    for (int i = 0; i < 4; i++) {
        int c = tid + i*256;
        float y = (v[i] - mean) * rstd * g[c] + b[c];
        Y[(size_t)row * D_EMB + c] = y;
        if (Yh) {
            bf16 hh, ll; split_bf(y, hh, ll);
            Yh[(size_t)row * D_EMB + c] = hh;
            Yl[(size_t)row * D_EMB + c] = ll;
        }
    }
}

// ======================================================================================
extern "C" void kernel_launch(void* const* d_in, const int* in_sizes, int n_in,
                              void* d_out, int out_size)
{
    const float* trg  = (const float*)d_in[0];
    const float* src  = (const float*)d_in[1];
    const float* Wq1  = (const float*)d_in[4];
    const float* bq1  = (const float*)d_in[5];
    const float* Wo1  = (const float*)d_in[6];
    const float* bo1  = (const float*)d_in[7];
    const float* Wq2  = (const float*)d_in[8];
    const float* bq2  = (const float*)d_in[9];
    const float* Wo2  = (const float*)d_in[10];
    const float* bo2  = (const float*)d_in[11];
    const float* Wff1 = (const float*)d_in[12];
    const float* bff1 = (const float*)d_in[13];
    const float* Wff2 = (const float*)d_in[14];
    const float* bff2 = (const float*)d_in[15];
    const float* ln1g = (const float*)d_in[16];
    const float* ln1b = (const float*)d_in[17];
    const float* ln2g = (const float*)d_in[18];
    const float* ln2b = (const float*)d_in[19];
    const float* ln3g = (const float*)d_in[20];
    const float* ln3b = (const float*)d_in[21];
    float* out = (float*)d_out;

    float *Q1, *KV, *TMP, *X1, *X2;
    cudaGetSymbolAddress((void**)&Q1,  g_Q1);
    cudaGetSymbolAddress((void**)&KV,  g_KV);
    cudaGetSymbolAddress((void**)&TMP, g_TMP);
    cudaGetSymbolAddress((void**)&X1,  g_X1);
    cudaGetSymbolAddress((void**)&X2,  g_X2);
    bf16 *trgH,*trgL,*srcH,*srcL,*Q1H,*Q1L,*Q2H,*Q2L,*KVH,*KVL,*ATH,*ATL;
    bf16 *X1H,*X1L,*X2H,*X2L,*HH,*HL,*VTH,*VTL;
    bf16 *WqT1H,*WqT1L,*WoT1H,*WoT1L,*WqT2H,*WqT2L,*WoT2H,*WoT2L;
    bf16 *Wff1TH,*Wff1TL,*Wff2TH,*Wff2TL;
    cudaGetSymbolAddress((void**)&trgH, g_trgH); cudaGetSymbolAddress((void**)&trgL, g_trgL);
    cudaGetSymbolAddress((void**)&srcH, g_srcH); cudaGetSymbolAddress((void**)&srcL, g_srcL);
    cudaGetSymbolAddress((void**)&Q1H,  g_Q1H);  cudaGetSymbolAddress((void**)&Q1L,  g_Q1L);
    cudaGetSymbolAddress((void**)&Q2H,  g_Q2H);  cudaGetSymbolAddress((void**)&Q2L,  g_Q2L);
    cudaGetSymbolAddress((void**)&KVH,  g_KVH);  cudaGetSymbolAddress((void**)&KVL,  g_KVL);
    cudaGetSymbolAddress((void**)&ATH,  g_ATH);  cudaGetSymbolAddress((void**)&ATL,  g_ATL);
    cudaGetSymbolAddress((void**)&X1H,  g_X1H);  cudaGetSymbolAddress((void**)&X1L,  g_X1L);
    cudaGetSymbolAddress((void**)&X2H,  g_X2H);  cudaGetSymbolAddress((void**)&X2L,  g_X2L);
    cudaGetSymbolAddress((void**)&HH,   g_HH);   cudaGetSymbolAddress((void**)&HL,   g_HL);
    cudaGetSymbolAddress((void**)&VTH,  g_VTH);  cudaGetSymbolAddress((void**)&VTL,  g_VTL);
    cudaGetSymbolAddress((void**)&WqT1H, g_WqT1H); cudaGetSymbolAddress((void**)&WqT1L, g_WqT1L);
    cudaGetSymbolAddress((void**)&WoT1H, g_WoT1H); cudaGetSymbolAddress((void**)&WoT1L, g_WoT1L);
    cudaGetSymbolAddress((void**)&WqT2H, g_WqT2H); cudaGetSymbolAddress((void**)&WqT2L, g_WqT2L);
    cudaGetSymbolAddress((void**)&WoT2H, g_WoT2H); cudaGetSymbolAddress((void**)&WoT2L, g_WoT2L);
    cudaGetSymbolAddress((void**)&Wff1TH, g_Wff1TH); cudaGetSymbolAddress((void**)&Wff1TL, g_Wff1TL);
    cudaGetSymbolAddress((void**)&Wff2TH, g_Wff2TH); cudaGetSymbolAddress((void**)&Wff2TL, g_Wff2TL);

    const int SMG = 2 * 40960;   // 81920 -> 2 CTAs/SM (round-5 proven)
    cudaFuncSetAttribute(mma_gemm<true ,true >, cudaFuncAttributeMaxDynamicSharedMemorySize, SMG);
    cudaFuncSetAttribute(mma_gemm<false,true >, cudaFuncAttributeMaxDynamicSharedMemorySize, SMG);
    cudaFuncSetAttribute(mma_gemm<true ,false>, cudaFuncAttributeMaxDynamicSharedMemorySize, SMG);
    cudaFuncSetAttribute(flash_attn, cudaFuncAttributeMaxDynamicSharedMemorySize, FLASH_SMEM);

    const dim3 t32(32, 32);
    const dim3 blk(256);
    const dim3 gP (D_EMB / 128, ROWS / 128);        // 8 x 32
    const dim3 gF1(D_FF / 128, ROWS / 128);         // 32 x 32
    const dim3 gFA(SEQ / 128, NB*HEADS);            // 16 x 32
    const dim3 gVT(SEQ / 32, HD / 32, NB*HEADS);

    cvt_split<<<(ROWS*D_EMB/4 + 255)/256, 256>>>(trg, trgH, trgL, (size_t)ROWS*D_EMB/4);
    cvt_split<<<(ROWS*D_EMB/4 + 255)/256, 256>>>(src, srcH, srcL, (size_t)ROWS*D_EMB/4);
    transpose_cvt<<<dim3(32, 32), t32>>>(Wq1, WqT1H, WqT1L, D_EMB, D_EMB);

    // ---- self-attention: shared Wq1 on trg => qp==kp==vp, one projection
    mma_gemm<true ,true ><<<gP, blk, SMG>>>(trgH, trgL, D_EMB, WqT1H, WqT1L, D_EMB,
                                            Q1, Q1H, Q1L, D_EMB, bq1, D_EMB, 0);
    vt_build_cvt<<<gVT, t32>>>(Q1, VTH, VTL);
    flash_attn<<<gFA, 512, FLASH_SMEM>>>(Q1H, Q1L, Q1H, Q1L, VTH, VTL, ATH, ATL);
    transpose_cvt<<<dim3(32, 32), t32>>>(Wo1, WoT1H, WoT1L, D_EMB, D_EMB);
    mma_gemm<true ,false><<<gP, blk, SMG>>>(ATH, ATL, D_EMB, WoT1H, WoT1L, D_EMB,
                                            TMP, nullptr, nullptr, D_EMB, bo1, D_EMB, 0);
    add_ln<<<ROWS, 256>>>(trg, TMP, ln1g, ln1b, X1, X1H, X1L);

    // ---- cross-attention: K and V share the same projection of encoded_src
    transpose_cvt<<<dim3(32, 32), t32>>>(Wq2, WqT2H, WqT2L, D_EMB, D_EMB);
    mma_gemm<false,true ><<<gP, blk, SMG>>>(X1H, X1L, D_EMB, WqT2H, WqT2L, D_EMB,
                                            nullptr, Q2H, Q2L, D_EMB, bq2, D_EMB, 0);
    mma_gemm<true ,true ><<<gP, blk, SMG>>>(srcH, srcL, D_EMB, WqT2H, WqT2L, D_EMB,
                                            KV, KVH, KVL, D_EMB, bq2, D_EMB, 0);
    vt_build_cvt<<<gVT, t32>>>(KV, VTH, VTL);
    flash_attn<<<gFA, 512, FLASH_SMEM>>>(Q2H, Q2L, KVH, KVL, VTH, VTL, ATH, ATL);
    transpose_cvt<<<dim3(32, 32), t32>>>(Wo2, WoT2H, WoT2L, D_EMB, D_EMB);
    mma_gemm<true ,false><<<gP, blk, SMG>>>(ATH, ATL, D_EMB, WoT2H, WoT2L, D_EMB,
                                            TMP, nullptr, nullptr, D_EMB, bo2, D_EMB, 0);
    add_ln<<<ROWS, 256>>>(X1, TMP, ln2g, ln2b, X2, X2H, X2L);

    // ---- FFN
    transpose_cvt<<<dim3(128, 32), t32>>>(Wff1, Wff1TH, Wff1TL, D_EMB, D_FF);
    mma_gemm<false,true ><<<gF1, blk, SMG>>>(X2H, X2L, D_EMB, Wff1TH, Wff1TL, D_EMB,
                                             nullptr, HH, HL, D_FF, bff1, D_EMB, 1);
    transpose_cvt<<<dim3(32, 128), t32>>>(Wff2, Wff2TH, Wff2TL, D_FF, D_EMB);
    mma_gemm<true ,false><<<gP, blk, SMG>>>(HH, HL, D_FF, Wff2TH, Wff2TL, D_FF,
                                            TMP, nullptr, nullptr, D_EMB, bff2, D_FF, 0);
    add_ln<<<ROWS, 256>>>(X2, TMP, ln3g, ln3b, out, nullptr, nullptr);
}

// round 9
// speedup vs baseline: 1.5189x; 1.4256x over previous
#include <cuda_runtime.h>
#include <cuda_fp16.h>
#include <cstdint>
#include <math.h>

#define D_EMB 1024
#define HEADS 16
#define HD    64
#define SEQ   2048
#define NB    2
#define ROWS  (NB*SEQ)   // 4096
#define D_FF  4096

typedef __half hlf;

// ---------------- scratch (__device__ globals; no allocations allowed) ----------------
__device__ float g_Q1 [(size_t)ROWS*D_EMB];
__device__ float g_KV [(size_t)ROWS*D_EMB];
__device__ float g_TMP[(size_t)ROWS*D_EMB];
__device__ float g_X1 [(size_t)ROWS*D_EMB];
__device__ float g_X2 [(size_t)ROWS*D_EMB];
__device__ hlf g_trgH[(size_t)ROWS*D_EMB];
__device__ hlf g_srcH[(size_t)ROWS*D_EMB];
__device__ hlf g_Q1H [(size_t)ROWS*D_EMB],  g_Q1L [(size_t)ROWS*D_EMB];
__device__ hlf g_Q2H [(size_t)ROWS*D_EMB],  g_Q2L [(size_t)ROWS*D_EMB];
__device__ hlf g_KVH [(size_t)ROWS*D_EMB],  g_KVL [(size_t)ROWS*D_EMB];
__device__ hlf g_ATH [(size_t)ROWS*D_EMB],  g_ATL [(size_t)ROWS*D_EMB];
__device__ hlf g_X1H [(size_t)ROWS*D_EMB],  g_X1L [(size_t)ROWS*D_EMB];
__device__ hlf g_X2H [(size_t)ROWS*D_EMB],  g_X2L [(size_t)ROWS*D_EMB];
__device__ hlf g_HH  [(size_t)ROWS*D_FF],   g_HL  [(size_t)ROWS*D_FF];
__device__ hlf g_VTH [(size_t)NB*HEADS*HD*SEQ],  g_VTL[(size_t)NB*HEADS*HD*SEQ];
__device__ hlf g_WqT1H[(size_t)D_EMB*D_EMB], g_WqT1L[(size_t)D_EMB*D_EMB];
__device__ hlf g_WoT1H[(size_t)D_EMB*D_EMB], g_WoT1L[(size_t)D_EMB*D_EMB];
__device__ hlf g_WqT2H[(size_t)D_EMB*D_EMB], g_WqT2L[(size_t)D_EMB*D_EMB];
__device__ hlf g_WoT2H[(size_t)D_EMB*D_EMB], g_WoT2L[(size_t)D_EMB*D_EMB];
__device__ hlf g_Wff1TH[(size_t)D_EMB*D_FF], g_Wff1TL[(size_t)D_EMB*D_FF];
__device__ hlf g_Wff2TH[(size_t)D_EMB*D_FF], g_Wff2TL[(size_t)D_EMB*D_FF];

// ---------------- small helpers -------------------------------------------------------
__device__ __forceinline__ uint32_t pack_h(hlf a, hlf b) {
    __half2 t = __halves2half2(a, b);
    return *reinterpret_cast<uint32_t*>(&t);
}
__device__ __forceinline__ void split_h(float v, hlf& h, hlf& l) {
    h = __float2half(v);
    l = __float2half(v - __half2float(h));
}
__device__ __forceinline__ uint32_t smem_u32(const void* p) {
    uint32_t a;
    asm("{ .reg .u64 t; cvta.to.shared.u64 t, %1; cvt.u32.u64 %0, t; }" : "=r"(a) : "l"(p));
    return a;
}
__device__ __forceinline__ void mma16816(float* c, const uint32_t* a, const uint32_t* b) {
    asm volatile("mma.sync.aligned.m16n8k16.row.col.f32.f16.f16.f32 "
        "{%0,%1,%2,%3}, {%4,%5,%6,%7}, {%8,%9}, {%0,%1,%2,%3};"
        : "+f"(c[0]), "+f"(c[1]), "+f"(c[2]), "+f"(c[3])
        : "r"(a[0]), "r"(a[1]), "r"(a[2]), "r"(a[3]), "r"(b[0]), "r"(b[1]));
}
__device__ __forceinline__ void ldm_x4(uint32_t& r0, uint32_t& r1, uint32_t& r2, uint32_t& r3,
                                       uint32_t addr) {
    asm volatile("ldmatrix.sync.aligned.m8n8.x4.shared.b16 {%0,%1,%2,%3}, [%4];"
        : "=r"(r0), "=r"(r1), "=r"(r2), "=r"(r3) : "r"(addr));
}
#define CP16(dst, src) asm volatile("cp.async.cg.shared.global [%0], [%1], 16;" :: "r"(dst), "l"(src))
#define CP_COMMIT()    asm volatile("cp.async.commit_group;")
#define CP_WAIT0()     asm volatile("cp.async.wait_group 0;")
#define CP_WAIT1()     asm volatile("cp.async.wait_group 1;")

// ======================= tensor-core NT GEMM: C[M,N] = A[M,K] @ B[N,K]^T ==============
// fp16 2-pass: C = Ah*Bh + Ah*Bl (A needs hi only). BM=128, BN=128, BK=32, 2-stage.
template<bool WC32, bool WC16>
__global__ __launch_bounds__(256, 2)
void mma_gemm(const hlf* __restrict__ Ah, int lda,
              const hlf* __restrict__ Bh, const hlf* __restrict__ Bl, int ldb,
              float* __restrict__ C32, hlf* __restrict__ C16h, hlf* __restrict__ C16l,
              int ldc, const float* __restrict__ bias, int K, int relu)
{
    constexpr int BN   = 128;
    constexpr int NT   = 8;
    constexpr int RSTR = 80;
    constexpr int AS   = 128 * RSTR;        // 10240 (A hi only)
    constexpr int BS   = BN * RSTR;         // 10240
    constexpr int STG  = AS + 2 * BS;       // 30720; x2 = 61440

    extern __shared__ __align__(16) char dsm[];
    const uint32_t sb = smem_u32(dsm);

    const int tid = threadIdx.x;
    const int lane = tid & 31, wid = tid >> 5;
    const int wm = wid & 3, wn = wid >> 2;
    const int g = lane >> 2, tig = lane & 3;
    const int lrow = lane & 7, seg = lane >> 3;

    const int bm = blockIdx.y * 128, bn = blockIdx.x * BN;

    float acc[2][NT][4];
    #pragma unroll
    for (int mt = 0; mt < 2; mt++)
        #pragma unroll
        for (int nt = 0; nt < NT; nt++)
            #pragma unroll
            for (int j = 0; j < 4; j++) acc[mt][nt][j] = 0.f;

    const int nc = K >> 5;

    auto load_stage = [&](int c) {
        const int k0 = c << 5;
        const uint32_t st = sb + (c & 1) * STG;
        #pragma unroll
        for (int i = 0; i < 2; i++) {
            int idx = tid + i * 256;
            int r = idx >> 2, sg = idx & 3;
            size_t go = (size_t)(bm + r) * lda + k0 + sg * 8;
            CP16(st + r * RSTR + sg * 16, Ah + go);
        }
        #pragma unroll
        for (int i = 0; i < 2; i++) {
            int idx = tid + i * 256;
            int r = idx >> 2, sg = idx & 3;
            size_t go = (size_t)(bn + r) * ldb + k0 + sg * 8;
            uint32_t so = r * RSTR + sg * 16;
            CP16(st + AS + so, Bh + go);
            CP16(st + AS + BS + so, Bl + go);
        }
    };

    load_stage(0);
    CP_COMMIT();

    for (int c = 0; c < nc; c++) {
        if (c + 1 < nc) { load_stage(c + 1); CP_COMMIT(); CP_WAIT1(); }
        else            { CP_WAIT0(); }
        __syncthreads();

        const uint32_t st = sb + (c & 1) * STG;
        const uint32_t pA = st, pBh = st + AS, pBl = st + AS + BS;

        #pragma unroll
        for (int k16 = 0; k16 < 2; k16++) {
            const uint32_t koff = k16 * 32 + (seg >> 1) * 16;
            uint32_t a[2][4];
            #pragma unroll
            for (int mt = 0; mt < 2; mt++) {
                uint32_t ro = (uint32_t)(wm * 32 + mt * 16 + (seg & 1) * 8 + lrow) * RSTR + koff;
                ldm_x4(a[mt][0], a[mt][1], a[mt][2], a[mt][3], pA + ro);
            }
            uint32_t bh[NT][2], bl[NT][2];
            #pragma unroll
            for (int np = 0; np < NT / 2; np++) {
                uint32_t ro = (uint32_t)(wn * 64 + np * 16 + (seg & 1) * 8 + lrow) * RSTR + koff;
                uint32_t r0, r1, r2, r3;
                ldm_x4(r0, r1, r2, r3, pBh + ro);
                bh[2*np][0] = r0; bh[2*np][1] = r2; bh[2*np+1][0] = r1; bh[2*np+1][1] = r3;
                ldm_x4(r0, r1, r2, r3, pBl + ro);
                bl[2*np][0] = r0; bl[2*np][1] = r2; bl[2*np+1][0] = r1; bl[2*np+1][1] = r3;
            }
            #pragma unroll
            for (int nt = 0; nt < NT; nt++)
                #pragma unroll
                for (int mt = 0; mt < 2; mt++) {
                    mma16816(acc[mt][nt], a[mt], bh[nt]);
                    mma16816(acc[mt][nt], a[mt], bl[nt]);
                }
        }
        __syncthreads();
    }

    #pragma unroll
    for (int mt = 0; mt < 2; mt++) {
        #pragma unroll
        for (int nt = 0; nt < NT; nt++) {
            int row = bm + wm * 32 + mt * 16 + g;
            int col = bn + wn * 64 + nt * 8 + tig * 2;
            float b0 = 0.f, b1 = 0.f;
            if (bias) { b0 = __ldg(bias + col); b1 = __ldg(bias + col + 1); }
            float v0 = acc[mt][nt][0] + b0, v1 = acc[mt][nt][1] + b1;
            float v2 = acc[mt][nt][2] + b0, v3 = acc[mt][nt][3] + b1;
            if (relu) {
                v0 = fmaxf(v0, 0.f); v1 = fmaxf(v1, 0.f);
                v2 = fmaxf(v2, 0.f); v3 = fmaxf(v3, 0.f);
            }
            size_t o0 = (size_t)row * ldc + col, o1 = (size_t)(row + 8) * ldc + col;
            if (WC32) {
                *(float2*)(C32 + o0) = make_float2(v0, v1);
                *(float2*)(C32 + o1) = make_float2(v2, v3);
            }
            if (WC16) {
                hlf h0, l0, h1, l1;
                split_h(v0, h0, l0); split_h(v1, h1, l1);
                *(uint32_t*)(C16h + o0) = pack_h(h0, h1);
                *(uint32_t*)(C16l + o0) = pack_h(l0, l1);
                split_h(v2, h0, l0); split_h(v3, h1, l1);
                *(uint32_t*)(C16h + o1) = pack_h(h0, h1);
                *(uint32_t*)(C16l + o1) = pack_h(l0, l1);
            }
        }
    }
}

// ======================= fused flash attention (256 thr, fp16 2-pass) ================
// S = Qh@(Kh+Kl)^T; online softmax fp32; O += Ph@(Vh+Vl). Q/P hi-only.
#define FQR 144
#define FPR 272
#define oQh 0
#define oK0 18432
#define oVh 92160
#define oVl 109568
#define oPh 126976
#define oRed 161792
#define FLASH_SMEM 162816

__global__ __launch_bounds__(256, 1)
void flash_attn(const hlf* __restrict__ Qh,
                const hlf* __restrict__ Kh, const hlf* __restrict__ Kl,
                const hlf* __restrict__ Vth, const hlf* __restrict__ Vtl,
                hlf* __restrict__ Oh)
{
    extern __shared__ __align__(16) char dsm[];
    const uint32_t sb = smem_u32(dsm);
    float* red = (float*)(dsm + oRed);

    const int tid = threadIdx.x;
    const int lane = tid & 31, wid = tid >> 5;
    const int wm = wid & 3, wn = wid >> 2;       // 4 x 2 warps
    const int g = lane >> 2, tig = lane & 3;
    const int lrow = lane & 7, seg = lane >> 3;

    const int z = blockIdx.y, n = z >> 4, h = z & 15;
    const int q0 = blockIdx.x * 128;
    const size_t qkbase = (size_t)n * SEQ * D_EMB + h * HD;
    const size_t vbase  = (size_t)z * HD * SEQ;

    // ---- preload Q (hi) + K tile 0 (hi+lo) ----
    #pragma unroll
    for (int i = 0; i < 4; i++) {
        int idx = tid + i * 256;                  // 1024 slots: 128 rows x 8 segs
        int r = idx >> 3, sg = idx & 7;
        uint32_t so = r * FQR + sg * 16;
        CP16(sb + oQh + so, Qh + qkbase + (size_t)(q0 + r) * D_EMB + sg * 8);
        size_t gk = qkbase + (size_t)r * D_EMB + sg * 8;
        CP16(sb + oK0 + so, Kh + gk);
        CP16(sb + oK0 + 18432 + so, Kl + gk);
    }
    CP_COMMIT();

    float m_prev[4], lsum[4], acc_o[2][4][4];
    #pragma unroll
    for (int i = 0; i < 4; i++) { m_prev[i] = -1e30f; lsum[i] = 0.f; }
    #pragma unroll
    for (int mt = 0; mt < 2; mt++)
        #pragma unroll
        for (int nt = 0; nt < 4; nt++)
            #pragma unroll
            for (int j = 0; j < 4; j++) acc_o[mt][nt][j] = 0.f;

    int myrow[4];
    #pragma unroll
    for (int mt = 0; mt < 2; mt++)
        #pragma unroll
        for (int hf = 0; hf < 2; hf++)
            myrow[mt*2+hf] = wm * 32 + mt * 16 + hf * 8 + g;

    for (int t = 0; t < 16; t++) {
        const int kv0 = t * 128;
        CP_WAIT0();
        __syncthreads();

        // V(t) hi+lo
        #pragma unroll
        for (int i = 0; i < 8; i++) {
            int p = i >> 2;
            int idx = tid + (i & 3) * 256;        // 1024 slots: 64 rows x 16 segs
            int r = idx >> 4, sg = idx & 15;
            size_t gv = vbase + (size_t)r * SEQ + kv0 + sg * 8;
            CP16(sb + (p ? oVl : oVh) + r * FPR + sg * 16, (p ? Vtl : Vth) + gv);
        }
        CP_COMMIT();
        // K(t+1) prefetch (clamped)
        {
            int tn = (t + 1 < 16) ? t + 1 : 15;
            uint32_t kst = oK0 + ((t + 1) & 1) * 36864;
            #pragma unroll
            for (int i = 0; i < 8; i++) {
                int p = i >> 2;
                int idx = tid + (i & 3) * 256;
                int r = idx >> 3, sg = idx & 7;
                size_t gk = qkbase + (size_t)(tn * 128 + r) * D_EMB + sg * 8;
                CP16(sb + kst + p * 18432 + r * FQR + sg * 16, (p ? Kl : Kh) + gk);
            }
        }
        CP_COMMIT();

        // ---- scores ----
        float s[2][8][4];
        #pragma unroll
        for (int mt = 0; mt < 2; mt++)
            #pragma unroll
            for (int nt = 0; nt < 8; nt++)
                #pragma unroll
                for (int j = 0; j < 4; j++) s[mt][nt][j] = 0.f;

        const uint32_t kst = sb + oK0 + (t & 1) * 36864;
        #pragma unroll
        for (int k16 = 0; k16 < 4; k16++) {
            const uint32_t koff = k16 * 32 + (seg >> 1) * 16;
            uint32_t a[2][4];
            #pragma unroll
            for (int mt = 0; mt < 2; mt++) {
                uint32_t ro = (uint32_t)(wm * 32 + mt * 16 + (seg & 1) * 8 + lrow) * FQR + koff;
                ldm_x4(a[mt][0], a[mt][1], a[mt][2], a[mt][3], sb + oQh + ro);
            }
            uint32_t bh[8][2], bl[8][2];
            #pragma unroll
            for (int np = 0; np < 4; np++) {
                uint32_t ro = (uint32_t)(wn * 64 + np * 16 + (seg & 1) * 8 + lrow) * FQR + koff;
                uint32_t r0, r1, r2, r3;
                ldm_x4(r0, r1, r2, r3, kst + ro);
                bh[2*np][0] = r0; bh[2*np][1] = r2; bh[2*np+1][0] = r1; bh[2*np+1][1] = r3;
                ldm_x4(r0, r1, r2, r3, kst + 18432 + ro);
                bl[2*np][0] = r0; bl[2*np][1] = r2; bl[2*np+1][0] = r1; bl[2*np+1][1] = r3;
            }
            #pragma unroll
            for (int nt = 0; nt < 8; nt++)
                #pragma unroll
                for (int mt = 0; mt < 2; mt++) {
                    mma16816(s[mt][nt], a[mt], bh[nt]);
                    mma16816(s[mt][nt], a[mt], bl[nt]);
                }
        }

        // ---- online softmax (fp32), scale 0.125 ----
        float mloc[4];
        #pragma unroll
        for (int i = 0; i < 4; i++) mloc[i] = -1e30f;
        #pragma unroll
        for (int mt = 0; mt < 2; mt++)
            #pragma unroll
            for (int nt = 0; nt < 8; nt++)
                #pragma unroll
                for (int hf = 0; hf < 2; hf++)
                    mloc[mt*2+hf] = fmaxf(mloc[mt*2+hf], fmaxf(s[mt][nt][hf*2], s[mt][nt][hf*2+1]));
        #pragma unroll
        for (int i = 0; i < 4; i++) {
            mloc[i] = fmaxf(mloc[i], __shfl_xor_sync(0xffffffffu, mloc[i], 1));
            mloc[i] = fmaxf(mloc[i], __shfl_xor_sync(0xffffffffu, mloc[i], 2));
        }
        if (tig == 0) {
            #pragma unroll
            for (int i = 0; i < 4; i++) red[wn * 128 + myrow[i]] = mloc[i];
        }
        __syncthreads();
        float m_new[4], alpha[4];
        #pragma unroll
        for (int i = 0; i < 4; i++) {
            float mr = fmaxf(red[myrow[i]], red[128 + myrow[i]]);
            float mn = fmaxf(m_prev[i], mr * 0.125f);
            alpha[i] = __expf(m_prev[i] - mn);
            m_new[i] = mn;
        }
        __syncthreads();

        float sl[4] = {0.f, 0.f, 0.f, 0.f};
        #pragma unroll
        for (int mt = 0; mt < 2; mt++)
            #pragma unroll
            for (int nt = 0; nt < 8; nt++)
                #pragma unroll
                for (int hf = 0; hf < 2; hf++) {
                    float p0 = __expf(s[mt][nt][hf*2]   * 0.125f - m_new[mt*2+hf]);
                    float p1 = __expf(s[mt][nt][hf*2+1] * 0.125f - m_new[mt*2+hf]);
                    s[mt][nt][hf*2] = p0; s[mt][nt][hf*2+1] = p1;
                    sl[mt*2+hf] += p0 + p1;
                }
        #pragma unroll
        for (int i = 0; i < 4; i++) {
            sl[i] += __shfl_xor_sync(0xffffffffu, sl[i], 1);
            sl[i] += __shfl_xor_sync(0xffffffffu, sl[i], 2);
        }
        if (tig == 0) {
            #pragma unroll
            for (int i = 0; i < 4; i++) red[wn * 128 + myrow[i]] = sl[i];
        }
        __syncthreads();
        #pragma unroll
        for (int i = 0; i < 4; i++) {
            lsum[i] = lsum[i] * alpha[i] + red[myrow[i]] + red[128 + myrow[i]];
            m_prev[i] = m_new[i];
        }
        #pragma unroll
        for (int mt = 0; mt < 2; mt++)
            #pragma unroll
            for (int nt = 0; nt < 4; nt++)
                #pragma unroll
                for (int hf = 0; hf < 2; hf++) {
                    acc_o[mt][nt][hf*2]   *= alpha[mt*2+hf];
                    acc_o[mt][nt][hf*2+1] *= alpha[mt*2+hf];
                }
        // P -> smem (hi only)
        #pragma unroll
        for (int mt = 0; mt < 2; mt++)
            #pragma unroll
            for (int nt = 0; nt < 8; nt++)
                #pragma unroll
                for (int hf = 0; hf < 2; hf++) {
                    int row = wm * 32 + mt * 16 + hf * 8 + g;
                    int colb = (wn * 64 + nt * 8 + tig * 2) * 2;
                    *(uint32_t*)(dsm + oPh + row * FPR + colb) =
                        pack_h(__float2half(s[mt][nt][hf*2]), __float2half(s[mt][nt][hf*2+1]));
                }
        CP_WAIT1();
        __syncthreads();

        // ---- O += P @ V ----
        #pragma unroll
        for (int k16 = 0; k16 < 8; k16++) {
            const uint32_t koff = k16 * 32 + (seg >> 1) * 16;
            uint32_t a[2][4];
            #pragma unroll
            for (int mt = 0; mt < 2; mt++) {
                uint32_t ro = (uint32_t)(wm * 32 + mt * 16 + (seg & 1) * 8 + lrow) * FPR + koff;
                ldm_x4(a[mt][0], a[mt][1], a[mt][2], a[mt][3], sb + oPh + ro);
            }
            uint32_t bh[4][2], bl[4][2];
            #pragma unroll
            for (int np = 0; np < 2; np++) {
                uint32_t ro = (uint32_t)(wn * 32 + np * 16 + (seg & 1) * 8 + lrow) * FPR + koff;
                uint32_t r0, r1, r2, r3;
                ldm_x4(r0, r1, r2, r3, sb + oVh + ro);
                bh[2*np][0] = r0; bh[2*np][1] = r2; bh[2*np+1][0] = r1; bh[2*np+1][1] = r3;
                ldm_x4(r0, r1, r2, r3, sb + oVl + ro);
                bl[2*np][0] = r0; bl[2*np][1] = r2; bl[2*np+1][0] = r1; bl[2*np+1][1] = r3;
            }
            #pragma unroll
            for (int nt = 0; nt < 4; nt++)
                #pragma unroll
                for (int mt = 0; mt < 2; mt++) {
                    mma16816(acc_o[mt][nt], a[mt], bh[nt]);
                    mma16816(acc_o[mt][nt], a[mt], bl[nt]);
                }
        }
    }

    // ---- epilogue: O / l -> fp16 hi only ----
    #pragma unroll
    for (int mt = 0; mt < 2; mt++)
        #pragma unroll
        for (int hf = 0; hf < 2; hf++) {
            int i = mt * 2 + hf;
            int row = myrow[i];
            float inv = 1.f / lsum[i];
            #pragma unroll
            for (int nt = 0; nt < 4; nt++) {
                float c0 = acc_o[mt][nt][hf*2]   * inv;
                float c1 = acc_o[mt][nt][hf*2+1] * inv;
                int col = wn * 32 + nt * 8 + tig * 2;
                size_t go = qkbase + (size_t)(q0 + row) * D_EMB + col;
                *(uint32_t*)(Oh + go) = pack_h(__float2half(c0), __float2half(c1));
            }
        }
}

// ======================= support kernels ==============================================
// fp32 -> fp16 hi (no lo needed: A-side only)
__global__ void cvt_hi(const float* __restrict__ in, hlf* __restrict__ oh, size_t n4)
{
    size_t i = (size_t)blockIdx.x * blockDim.x + threadIdx.x;
    if (i >= n4) return;
    float4 v = *(const float4*)(in + i * 4);
    *(uint2*)(oh + i * 4) = make_uint2(pack_h(__float2half(v.x), __float2half(v.y)),
                                       pack_h(__float2half(v.z), __float2half(v.w)));
}

__global__ void transpose_cvt(const float* __restrict__ in, hlf* __restrict__ oh,
                              hlf* __restrict__ ol, int R, int C)
{
    __shared__ float t[32][33];
    int r0 = blockIdx.y * 32, c0 = blockIdx.x * 32;
    t[threadIdx.y][threadIdx.x] = in[(size_t)(r0 + threadIdx.y) * C + c0 + threadIdx.x];
    __syncthreads();
    float v = t[threadIdx.x][threadIdx.y];
    hlf h, l; split_h(v, h, l);
    size_t o = (size_t)(c0 + threadIdx.y) * R + r0 + threadIdx.x;
    oh[o] = h; ol[o] = l;
}

__global__ void vt_build_cvt(const float* __restrict__ V, hlf* __restrict__ VTh,
                             hlf* __restrict__ VTl)
{
    __shared__ float t[32][33];
    int z = blockIdx.z, n = z >> 4, h = z & 15;
    int s0 = blockIdx.x * 32, d0 = blockIdx.y * 32;
    t[threadIdx.y][threadIdx.x] =
        V[(size_t)n * SEQ * D_EMB + (size_t)(s0 + threadIdx.y) * D_EMB + h * HD + d0 + threadIdx.x];
    __syncthreads();
    float v = t[threadIdx.x][threadIdx.y];
    hlf hh, ll; split_h(v, hh, ll);
    size_t o = ((size_t)z * HD + d0 + threadIdx.y) * SEQ + s0 + threadIdx.x;
    VTh[o] = hh; VTl[o] = ll;
}

__global__ void add_ln(const float* __restrict__ X, const float* __restrict__ R,
                       const float* __restrict__ g, const float* __restrict__ b,
                       float* __restrict__ Y, hlf* __restrict__ Yh)
{
    const int row = blockIdx.x;
    const float* px = X + (size_t)row * D_EMB;
    const float* pr = R + (size_t)row * D_EMB;
    const int tid = threadIdx.x;
    float v[4];
    float s = 0.f, s2 = 0.f;
    #pragma unroll
    for (int i = 0; i < 4; i++) {
        int c = tid + i*256;
        v[i] = px[c] + pr[c];
        s += v[i]; s2 += v[i]*v[i];
    }
    #pragma unroll
    for (int o = 16; o; o >>= 1) {
        s  += __shfl_xor_sync(0xffffffffu, s,  o);
        s2 += __shfl_xor_sync(0xffffffffu, s2, o);
    }
    __shared__ float sh[8], sh2[8];
    if ((tid & 31) == 0) { sh[tid >> 5] = s; sh2[tid >> 5] = s2; }
    __syncthreads();
    s = 0.f; s2 = 0.f;
    #pragma unroll
    for (int i = 0; i < 8; i++) { s += sh[i]; s2 += sh2[i]; }
    const float mean = s * (1.f / D_EMB);
    const float var  = s2 * (1.f / D_EMB) - mean * mean;
    const float rstd = rsqrtf(var + 1e-5f);
    #pragma unroll
    for (int i = 0; i < 4; i++) {
        int c = tid + i*256;
        float y = (v[i] - mean) * rstd * g[c] + b[c];
        Y[(size_t)row * D_EMB + c] = y;
        if (Yh) Yh[(size_t)row * D_EMB + c] = __float2half(y);
    }
}

// ======================================================================================
extern "C" void kernel_launch(void* const* d_in, const int* in_sizes, int n_in,
                              void* d_out, int out_size)
{
    const float* trg  = (const float*)d_in[0];
    const float* src  = (const float*)d_in[1];
    const float* Wq1  = (const float*)d_in[4];
    const float* bq1  = (const float*)d_in[5];
    const float* Wo1  = (const float*)d_in[6];
    const float* bo1  = (const float*)d_in[7];
    const float* Wq2  = (const float*)d_in[8];
    const float* bq2  = (const float*)d_in[9];
    const float* Wo2  = (const float*)d_in[10];
    const float* bo2  = (const float*)d_in[11];
    const float* Wff1 = (const float*)d_in[12];
    const float* bff1 = (const float*)d_in[13];
    const float* Wff2 = (const float*)d_in[14];
    const float* bff2 = (const float*)d_in[15];
    const float* ln1g = (const float*)d_in[16];
    const float* ln1b = (const float*)d_in[17];
    const float* ln2g = (const float*)d_in[18];
    const float* ln2b = (const float*)d_in[19];
    const float* ln3g = (const float*)d_in[20];
    const float* ln3b = (const float*)d_in[21];
    float* out = (float*)d_out;

    float *Q1, *KV, *TMP, *X1, *X2;
    cudaGetSymbolAddress((void**)&Q1,  g_Q1);
    cudaGetSymbolAddress((void**)&KV,  g_KV);
    cudaGetSymbolAddress((void**)&TMP, g_TMP);
    cudaGetSymbolAddress((void**)&X1,  g_X1);
    cudaGetSymbolAddress((void**)&X2,  g_X2);
    hlf *trgH,*srcH,*Q1H,*Q1L,*Q2H,*Q2L,*KVH,*KVL,*ATH,*ATL;
    hlf *X1H,*X1L,*X2H,*X2L,*HH,*HL,*VTH,*VTL;
    hlf *WqT1H,*WqT1L,*WoT1H,*WoT1L,*WqT2H,*WqT2L,*WoT2H,*WoT2L;
    hlf *Wff1TH,*Wff1TL,*Wff2TH,*Wff2TL;
    cudaGetSymbolAddress((void**)&trgH, g_trgH);
    cudaGetSymbolAddress((void**)&srcH, g_srcH);
    cudaGetSymbolAddress((void**)&Q1H,  g_Q1H);  cudaGetSymbolAddress((void**)&Q1L,  g_Q1L);
    cudaGetSymbolAddress((void**)&Q2H,  g_Q2H);  cudaGetSymbolAddress((void**)&Q2L,  g_Q2L);
    cudaGetSymbolAddress((void**)&KVH,  g_KVH);  cudaGetSymbolAddress((void**)&KVL,  g_KVL);
    cudaGetSymbolAddress((void**)&ATH,  g_ATH);  cudaGetSymbolAddress((void**)&ATL,  g_ATL);
    cudaGetSymbolAddress((void**)&X1H,  g_X1H);  cudaGetSymbolAddress((void**)&X1L,  g_X1L);
    cudaGetSymbolAddress((void**)&X2H,  g_X2H);  cudaGetSymbolAddress((void**)&X2L,  g_X2L);
    cudaGetSymbolAddress((void**)&HH,   g_HH);   cudaGetSymbolAddress((void**)&HL,   g_HL);
    cudaGetSymbolAddress((void**)&VTH,  g_VTH);  cudaGetSymbolAddress((void**)&VTL,  g_VTL);
    cudaGetSymbolAddress((void**)&WqT1H, g_WqT1H); cudaGetSymbolAddress((void**)&WqT1L, g_WqT1L);
    cudaGetSymbolAddress((void**)&WoT1H, g_WoT1H); cudaGetSymbolAddress((void**)&WoT1L, g_WoT1L);
    cudaGetSymbolAddress((void**)&WqT2H, g_WqT2H); cudaGetSymbolAddress((void**)&WqT2L, g_WqT2L);
    cudaGetSymbolAddress((void**)&WoT2H, g_WoT2H); cudaGetSymbolAddress((void**)&WoT2L, g_WoT2L);
    cudaGetSymbolAddress((void**)&Wff1TH, g_Wff1TH); cudaGetSymbolAddress((void**)&Wff1TL, g_Wff1TL);
    cudaGetSymbolAddress((void**)&Wff2TH, g_Wff2TH); cudaGetSymbolAddress((void**)&Wff2TL, g_Wff2TL);

    const int SMG = 2 * 30720;   // 61440
    cudaFuncSetAttribute(mma_gemm<true ,true >, cudaFuncAttributeMaxDynamicSharedMemorySize, SMG);
    cudaFuncSetAttribute(mma_gemm<false,true >, cudaFuncAttributeMaxDynamicSharedMemorySize, SMG);
    cudaFuncSetAttribute(mma_gemm<true ,false>, cudaFuncAttributeMaxDynamicSharedMemorySize, SMG);
    cudaFuncSetAttribute(flash_attn, cudaFuncAttributeMaxDynamicSharedMemorySize, FLASH_SMEM);

    const dim3 t32(32, 32);
    const dim3 blk(256);
    const dim3 gP (D_EMB / 128, ROWS / 128);        // 8 x 32
    const dim3 gF1(D_FF / 128, ROWS / 128);         // 32 x 32
    const dim3 gFA(SEQ / 128, NB*HEADS);            // 16 x 32
    const dim3 gVT(SEQ / 32, HD / 32, NB*HEADS);

    cvt_hi<<<(ROWS*D_EMB/4 + 255)/256, 256>>>(trg, trgH, (size_t)ROWS*D_EMB/4);
    cvt_hi<<<(ROWS*D_EMB/4 + 255)/256, 256>>>(src, srcH, (size_t)ROWS*D_EMB/4);
    transpose_cvt<<<dim3(32, 32), t32>>>(Wq1, WqT1H, WqT1L, D_EMB, D_EMB);

    // ---- self-attention: shared Wq1 on trg => qp==kp==vp, one projection
    mma_gemm<true ,true ><<<gP, blk, SMG>>>(trgH, D_EMB, WqT1H, WqT1L, D_EMB,
                                            Q1, Q1H, Q1L, D_EMB, bq1, D_EMB, 0);
    vt_build_cvt<<<gVT, t32>>>(Q1, VTH, VTL);
    flash_attn<<<gFA, blk, FLASH_SMEM>>>(Q1H, Q1H, Q1L, VTH, VTL, ATH);
    transpose_cvt<<<dim3(32, 32), t32>>>(Wo1, WoT1H, WoT1L, D_EMB, D_EMB);
    mma_gemm<true ,false><<<gP, blk, SMG>>>(ATH, D_EMB, WoT1H, WoT1L, D_EMB,
                                            TMP, nullptr, nullptr, D_EMB, bo1, D_EMB, 0);
    add_ln<<<ROWS, 256>>>(trg, TMP, ln1g, ln1b, X1, X1H);

    // ---- cross-attention: K and V share the same projection of encoded_src
    transpose_cvt<<<dim3(32, 32), t32>>>(Wq2, WqT2H, WqT2L, D_EMB, D_EMB);
    mma_gemm<false,true ><<<gP, blk, SMG>>>(X1H, D_EMB, WqT2H, WqT2L, D_EMB,
                                            nullptr, Q2H, Q2L, D_EMB, bq2, D_EMB, 0);
    mma_gemm<true ,true ><<<gP, blk, SMG>>>(srcH, D_EMB, WqT2H, WqT2L, D_EMB,
                                            KV, KVH, KVL, D_EMB, bq2, D_EMB, 0);
    vt_build_cvt<<<gVT, t32>>>(KV, VTH, VTL);
    flash_attn<<<gFA, blk, FLASH_SMEM>>>(Q2H, KVH, KVL, VTH, VTL, ATH);
    transpose_cvt<<<dim3(32, 32), t32>>>(Wo2, WoT2H, WoT2L, D_EMB, D_EMB);
    mma_gemm<true ,false><<<gP, blk, SMG>>>(ATH, D_EMB, WoT2H, WoT2L, D_EMB,
                                            TMP, nullptr, nullptr, D_EMB, bo2, D_EMB, 0);
    add_ln<<<ROWS, 256>>>(X1, TMP, ln2g, ln2b, X2, X2H);

    // ---- FFN
    transpose_cvt<<<dim3(128, 32), t32>>>(Wff1, Wff1TH, Wff1TL, D_EMB, D_FF);
    mma_gemm<false,true ><<<gF1, blk, SMG>>>(X2H, D_EMB, Wff1TH, Wff1TL, D_EMB,
                                             nullptr, HH, HL, D_FF, bff1, D_EMB, 1);
    transpose_cvt<<<dim3(32, 128), t32>>>(Wff2, Wff2TH, Wff2TL, D_FF, D_EMB);
    mma_gemm<true ,false><<<gP, blk, SMG>>>(HH, D_FF, Wff2TH, Wff2TL, D_FF,
                                            TMP, nullptr, nullptr, D_EMB, bff2, D_FF, 0);
    add_ln<<<ROWS, 256>>>(X2, TMP, ln3g, ln3b, out, nullptr);
}

// round 10
// speedup vs baseline: 2.4541x; 1.6157x over previous
#include <cuda_runtime.h>
#include <cuda_fp16.h>
#include <cstdint>
#include <math.h>

#define D_EMB 1024
#define HEADS 16
#define HD    64
#define SEQ   2048
#define NB    2
#define ROWS  (NB*SEQ)   // 4096
#define D_FF  4096

typedef __half hlf;

// ---------------- scratch (__device__ globals; no allocations allowed) ----------------
__device__ float g_Q1 [(size_t)ROWS*D_EMB];
__device__ float g_KV [(size_t)ROWS*D_EMB];
__device__ float g_TMP[(size_t)ROWS*D_EMB];
__device__ float g_X1 [(size_t)ROWS*D_EMB];
__device__ float g_X2 [(size_t)ROWS*D_EMB];
__device__ hlf g_trgH[(size_t)ROWS*D_EMB];
__device__ hlf g_srcH[(size_t)ROWS*D_EMB];
__device__ hlf g_Q1H [(size_t)ROWS*D_EMB];
__device__ hlf g_Q2H [(size_t)ROWS*D_EMB];
__device__ hlf g_KVH [(size_t)ROWS*D_EMB];
__device__ hlf g_ATH [(size_t)ROWS*D_EMB];
__device__ hlf g_X1H [(size_t)ROWS*D_EMB];
__device__ hlf g_X2H [(size_t)ROWS*D_EMB];
__device__ hlf g_HH  [(size_t)ROWS*D_FF];
__device__ hlf g_VTH [(size_t)NB*HEADS*HD*SEQ];
__device__ hlf g_WqT1H[(size_t)D_EMB*D_EMB];
__device__ hlf g_WoT1H[(size_t)D_EMB*D_EMB];
__device__ hlf g_WqT2H[(size_t)D_EMB*D_EMB];
__device__ hlf g_WoT2H[(size_t)D_EMB*D_EMB];
__device__ hlf g_Wff1TH[(size_t)D_EMB*D_FF];
__device__ hlf g_Wff2TH[(size_t)D_EMB*D_FF];

// ---------------- small helpers -------------------------------------------------------
__device__ __forceinline__ uint32_t pack_h(hlf a, hlf b) {
    __half2 t = __halves2half2(a, b);
    return *reinterpret_cast<uint32_t*>(&t);
}
__device__ __forceinline__ uint32_t smem_u32(const void* p) {
    uint32_t a;
    asm("{ .reg .u64 t; cvta.to.shared.u64 t, %1; cvt.u32.u64 %0, t; }" : "=r"(a) : "l"(p));
    return a;
}
__device__ __forceinline__ void mma16816(float* c, const uint32_t* a, const uint32_t* b) {
    asm volatile("mma.sync.aligned.m16n8k16.row.col.f32.f16.f16.f32 "
        "{%0,%1,%2,%3}, {%4,%5,%6,%7}, {%8,%9}, {%0,%1,%2,%3};"
        : "+f"(c[0]), "+f"(c[1]), "+f"(c[2]), "+f"(c[3])
        : "r"(a[0]), "r"(a[1]), "r"(a[2]), "r"(a[3]), "r"(b[0]), "r"(b[1]));
}
__device__ __forceinline__ void ldm_x4(uint32_t& r0, uint32_t& r1, uint32_t& r2, uint32_t& r3,
                                       uint32_t addr) {
    asm volatile("ldmatrix.sync.aligned.m8n8.x4.shared.b16 {%0,%1,%2,%3}, [%4];"
        : "=r"(r0), "=r"(r1), "=r"(r2), "=r"(r3) : "r"(addr));
}
#define CP16(dst, src) asm volatile("cp.async.cg.shared.global [%0], [%1], 16;" :: "r"(dst), "l"(src))
#define CP_COMMIT()    asm volatile("cp.async.commit_group;")
#define CP_WAIT0()     asm volatile("cp.async.wait_group 0;")
#define CP_WAIT1()     asm volatile("cp.async.wait_group 1;")

// ======================= tensor-core NT GEMM: C[M,N] = A[M,K] @ B[N,K]^T ==============
// Plain fp16 single pass. BM=128, BN=128, BK=32, 2-stage cp.async, 2 CTAs/SM.
template<bool WC32, bool WC16>
__global__ __launch_bounds__(256, 2)
void mma_gemm(const hlf* __restrict__ Ah, int lda,
              const hlf* __restrict__ Bh, int ldb,
              float* __restrict__ C32, hlf* __restrict__ C16h,
              int ldc, const float* __restrict__ bias, int K, int relu)
{
    constexpr int BN   = 128;
    constexpr int NT   = 8;
    constexpr int RSTR = 80;
    constexpr int AS   = 128 * RSTR;        // 10240
    constexpr int BS   = BN * RSTR;         // 10240
    constexpr int STG  = AS + BS;           // 20480; x2 = 40960

    extern __shared__ __align__(16) char dsm[];
    const uint32_t sb = smem_u32(dsm);

    const int tid = threadIdx.x;
    const int lane = tid & 31, wid = tid >> 5;
    const int wm = wid & 3, wn = wid >> 2;
    const int g = lane >> 2, tig = lane & 3;
    const int lrow = lane & 7, seg = lane >> 3;

    const int bm = blockIdx.y * 128, bn = blockIdx.x * BN;

    float acc[2][NT][4];
    #pragma unroll
    for (int mt = 0; mt < 2; mt++)
        #pragma unroll
        for (int nt = 0; nt < NT; nt++)
            #pragma unroll
            for (int j = 0; j < 4; j++) acc[mt][nt][j] = 0.f;

    const int nc = K >> 5;

    auto load_stage = [&](int c) {
        const int k0 = c << 5;
        const uint32_t st = sb + (c & 1) * STG;
        #pragma unroll
        for (int i = 0; i < 2; i++) {
            int idx = tid + i * 256;
            int r = idx >> 2, sg = idx & 3;
            CP16(st + r * RSTR + sg * 16, Ah + (size_t)(bm + r) * lda + k0 + sg * 8);
        }
        #pragma unroll
        for (int i = 0; i < 2; i++) {
            int idx = tid + i * 256;
            int r = idx >> 2, sg = idx & 3;
            CP16(st + AS + r * RSTR + sg * 16, Bh + (size_t)(bn + r) * ldb + k0 + sg * 8);
        }
    };

    load_stage(0);
    CP_COMMIT();

    for (int c = 0; c < nc; c++) {
        if (c + 1 < nc) { load_stage(c + 1); CP_COMMIT(); CP_WAIT1(); }
        else            { CP_WAIT0(); }
        __syncthreads();

        const uint32_t st = sb + (c & 1) * STG;
        const uint32_t pA = st, pB = st + AS;

        #pragma unroll
        for (int k16 = 0; k16 < 2; k16++) {
            const uint32_t koff = k16 * 32 + (seg >> 1) * 16;
            uint32_t a[2][4];
            #pragma unroll
            for (int mt = 0; mt < 2; mt++) {
                uint32_t ro = (uint32_t)(wm * 32 + mt * 16 + (seg & 1) * 8 + lrow) * RSTR + koff;
                ldm_x4(a[mt][0], a[mt][1], a[mt][2], a[mt][3], pA + ro);
            }
            uint32_t b[NT][2];
            #pragma unroll
            for (int np = 0; np < NT / 2; np++) {
                uint32_t ro = (uint32_t)(wn * 64 + np * 16 + (seg & 1) * 8 + lrow) * RSTR + koff;
                uint32_t r0, r1, r2, r3;
                ldm_x4(r0, r1, r2, r3, pB + ro);
                b[2*np][0] = r0; b[2*np][1] = r2; b[2*np+1][0] = r1; b[2*np+1][1] = r3;
            }
            #pragma unroll
            for (int nt = 0; nt < NT; nt++)
                #pragma unroll
                for (int mt = 0; mt < 2; mt++)
                    mma16816(acc[mt][nt], a[mt], b[nt]);
        }
        __syncthreads();
    }

    #pragma unroll
    for (int mt = 0; mt < 2; mt++) {
        #pragma unroll
        for (int nt = 0; nt < NT; nt++) {
            int row = bm + wm * 32 + mt * 16 + g;
            int col = bn + wn * 64 + nt * 8 + tig * 2;
            float b0 = 0.f, b1 = 0.f;
            if (bias) { b0 = __ldg(bias + col); b1 = __ldg(bias + col + 1); }
            float v0 = acc[mt][nt][0] + b0, v1 = acc[mt][nt][1] + b1;
            float v2 = acc[mt][nt][2] + b0, v3 = acc[mt][nt][3] + b1;
            if (relu) {
                v0 = fmaxf(v0, 0.f); v1 = fmaxf(v1, 0.f);
                v2 = fmaxf(v2, 0.f); v3 = fmaxf(v3, 0.f);
            }
            size_t o0 = (size_t)row * ldc + col, o1 = (size_t)(row + 8) * ldc + col;
            if (WC32) {
                *(float2*)(C32 + o0) = make_float2(v0, v1);
                *(float2*)(C32 + o1) = make_float2(v2, v3);
            }
            if (WC16) {
                *(uint32_t*)(C16h + o0) = pack_h(__float2half(v0), __float2half(v1));
                *(uint32_t*)(C16h + o1) = pack_h(__float2half(v2), __float2half(v3));
            }
        }
    }
}

// ======================= fused flash attention (fp16 single pass) =====================
// smem: Q 18432 | K x2 stages 36864 | V 17408 | P 34816 | red 1024 = 108544 -> 2 CTAs/SM
#define FQR 144
#define FPR 272
#define oQ  0
#define oK0 18432
#define oV  55296
#define oP  72704
#define oRed 107520
#define FLASH_SMEM 108544

__global__ __launch_bounds__(256, 2)
void flash_attn(const hlf* __restrict__ Qh,
                const hlf* __restrict__ Kh,
                const hlf* __restrict__ Vth,
                hlf* __restrict__ Oh)
{
    extern __shared__ __align__(16) char dsm[];
    const uint32_t sb = smem_u32(dsm);
    float* red = (float*)(dsm + oRed);

    const int tid = threadIdx.x;
    const int lane = tid & 31, wid = tid >> 5;
    const int wm = wid & 3, wn = wid >> 2;       // 4 x 2 warps
    const int g = lane >> 2, tig = lane & 3;
    const int lrow = lane & 7, seg = lane >> 3;

    const int z = blockIdx.y, n = z >> 4, h = z & 15;
    const int q0 = blockIdx.x * 128;
    const size_t qkbase = (size_t)n * SEQ * D_EMB + h * HD;
    const size_t vbase  = (size_t)z * HD * SEQ;

    // ---- preload Q + K tile 0 ----
    #pragma unroll
    for (int i = 0; i < 4; i++) {
        int idx = tid + i * 256;                  // 1024 slots: 128 rows x 8 segs
        int r = idx >> 3, sg = idx & 7;
        uint32_t so = r * FQR + sg * 16;
        CP16(sb + oQ + so, Qh + qkbase + (size_t)(q0 + r) * D_EMB + sg * 8);
        CP16(sb + oK0 + so, Kh + qkbase + (size_t)r * D_EMB + sg * 8);
    }
    CP_COMMIT();

    float m_prev[4], lsum[4], acc_o[2][4][4];
    #pragma unroll
    for (int i = 0; i < 4; i++) { m_prev[i] = -1e30f; lsum[i] = 0.f; }
    #pragma unroll
    for (int mt = 0; mt < 2; mt++)
        #pragma unroll
        for (int nt = 0; nt < 4; nt++)
            #pragma unroll
            for (int j = 0; j < 4; j++) acc_o[mt][nt][j] = 0.f;

    int myrow[4];
    #pragma unroll
    for (int mt = 0; mt < 2; mt++)
        #pragma unroll
        for (int hf = 0; hf < 2; hf++)
            myrow[mt*2+hf] = wm * 32 + mt * 16 + hf * 8 + g;

    for (int t = 0; t < 16; t++) {
        const int kv0 = t * 128;
        CP_WAIT0();
        __syncthreads();

        // V(t)
        #pragma unroll
        for (int i = 0; i < 4; i++) {
            int idx = tid + i * 256;              // 1024 slots: 64 rows x 16 segs
            int r = idx >> 4, sg = idx & 15;
            CP16(sb + oV + r * FPR + sg * 16, Vth + vbase + (size_t)r * SEQ + kv0 + sg * 8);
        }
        CP_COMMIT();
        // K(t+1) prefetch (clamped)
        {
            int tn = (t + 1 < 16) ? t + 1 : 15;
            uint32_t kst = oK0 + ((t + 1) & 1) * 18432;
            #pragma unroll
            for (int i = 0; i < 4; i++) {
                int idx = tid + i * 256;
                int r = idx >> 3, sg = idx & 7;
                CP16(sb + kst + r * FQR + sg * 16,
                     Kh + qkbase + (size_t)(tn * 128 + r) * D_EMB + sg * 8);
            }
        }
        CP_COMMIT();

        // ---- scores: S = Q @ K(t)^T ----
        float s[2][8][4];
        #pragma unroll
        for (int mt = 0; mt < 2; mt++)
            #pragma unroll
            for (int nt = 0; nt < 8; nt++)
                #pragma unroll
                for (int j = 0; j < 4; j++) s[mt][nt][j] = 0.f;

        const uint32_t kst = sb + oK0 + (t & 1) * 18432;
        #pragma unroll
        for (int k16 = 0; k16 < 4; k16++) {
            const uint32_t koff = k16 * 32 + (seg >> 1) * 16;
            uint32_t a[2][4];
            #pragma unroll
            for (int mt = 0; mt < 2; mt++) {
                uint32_t ro = (uint32_t)(wm * 32 + mt * 16 + (seg & 1) * 8 + lrow) * FQR + koff;
                ldm_x4(a[mt][0], a[mt][1], a[mt][2], a[mt][3], sb + oQ + ro);
            }
            uint32_t b[8][2];
            #pragma unroll
            for (int np = 0; np < 4; np++) {
                uint32_t ro = (uint32_t)(wn * 64 + np * 16 + (seg & 1) * 8 + lrow) * FQR + koff;
                uint32_t r0, r1, r2, r3;
                ldm_x4(r0, r1, r2, r3, kst + ro);
                b[2*np][0] = r0; b[2*np][1] = r2; b[2*np+1][0] = r1; b[2*np+1][1] = r3;
            }
            #pragma unroll
            for (int nt = 0; nt < 8; nt++)
                #pragma unroll
                for (int mt = 0; mt < 2; mt++)
                    mma16816(s[mt][nt], a[mt], b[nt]);
        }

        // ---- online softmax (fp32), scale 0.125 ----
        float mloc[4];
        #pragma unroll
        for (int i = 0; i < 4; i++) mloc[i] = -1e30f;
        #pragma unroll
        for (int mt = 0; mt < 2; mt++)
            #pragma unroll
            for (int nt = 0; nt < 8; nt++)
                #pragma unroll
                for (int hf = 0; hf < 2; hf++)
                    mloc[mt*2+hf] = fmaxf(mloc[mt*2+hf], fmaxf(s[mt][nt][hf*2], s[mt][nt][hf*2+1]));
        #pragma unroll
        for (int i = 0; i < 4; i++) {
            mloc[i] = fmaxf(mloc[i], __shfl_xor_sync(0xffffffffu, mloc[i], 1));
            mloc[i] = fmaxf(mloc[i], __shfl_xor_sync(0xffffffffu, mloc[i], 2));
        }
        if (tig == 0) {
            #pragma unroll
            for (int i = 0; i < 4; i++) red[wn * 128 + myrow[i]] = mloc[i];
        }
        __syncthreads();
        float m_new[4], alpha[4];
        #pragma unroll
        for (int i = 0; i < 4; i++) {
            float mr = fmaxf(red[myrow[i]], red[128 + myrow[i]]);
            float mn = fmaxf(m_prev[i], mr * 0.125f);
            alpha[i] = __expf(m_prev[i] - mn);
            m_new[i] = mn;
        }
        __syncthreads();

        float sl[4] = {0.f, 0.f, 0.f, 0.f};
        #pragma unroll
        for (int mt = 0; mt < 2; mt++)
            #pragma unroll
            for (int nt = 0; nt < 8; nt++)
                #pragma unroll
                for (int hf = 0; hf < 2; hf++) {
                    float p0 = __expf(s[mt][nt][hf*2]   * 0.125f - m_new[mt*2+hf]);
                    float p1 = __expf(s[mt][nt][hf*2+1] * 0.125f - m_new[mt*2+hf]);
                    s[mt][nt][hf*2] = p0; s[mt][nt][hf*2+1] = p1;
                    sl[mt*2+hf] += p0 + p1;
                }
        #pragma unroll
        for (int i = 0; i < 4; i++) {
            sl[i] += __shfl_xor_sync(0xffffffffu, sl[i], 1);
            sl[i] += __shfl_xor_sync(0xffffffffu, sl[i], 2);
        }
        if (tig == 0) {
            #pragma unroll
            for (int i = 0; i < 4; i++) red[wn * 128 + myrow[i]] = sl[i];
        }
        __syncthreads();
        #pragma unroll
        for (int i = 0; i < 4; i++) {
            lsum[i] = lsum[i] * alpha[i] + red[myrow[i]] + red[128 + myrow[i]];
            m_prev[i] = m_new[i];
        }
        #pragma unroll
        for (int mt = 0; mt < 2; mt++)
            #pragma unroll
            for (int nt = 0; nt < 4; nt++)
                #pragma unroll
                for (int hf = 0; hf < 2; hf++) {
                    acc_o[mt][nt][hf*2]   *= alpha[mt*2+hf];
                    acc_o[mt][nt][hf*2+1] *= alpha[mt*2+hf];
                }
        // P -> smem (fp16)
        #pragma unroll
        for (int mt = 0; mt < 2; mt++)
            #pragma unroll
            for (int nt = 0; nt < 8; nt++)
                #pragma unroll
                for (int hf = 0; hf < 2; hf++) {
                    int row = wm * 32 + mt * 16 + hf * 8 + g;
                    int colb = (wn * 64 + nt * 8 + tig * 2) * 2;
                    *(uint32_t*)(dsm + oP + row * FPR + colb) =
                        pack_h(__float2half(s[mt][nt][hf*2]), __float2half(s[mt][nt][hf*2+1]));
                }
        CP_WAIT1();        // V(t) complete (K(t+1) still in flight)
        __syncthreads();

        // ---- O += P @ V ----
        #pragma unroll
        for (int k16 = 0; k16 < 8; k16++) {
            const uint32_t koff = k16 * 32 + (seg >> 1) * 16;
            uint32_t a[2][4];
            #pragma unroll
            for (int mt = 0; mt < 2; mt++) {
                uint32_t ro = (uint32_t)(wm * 32 + mt * 16 + (seg & 1) * 8 + lrow) * FPR + koff;
                ldm_x4(a[mt][0], a[mt][1], a[mt][2], a[mt][3], sb + oP + ro);
            }
            uint32_t b[4][2];
            #pragma unroll
            for (int np = 0; np < 2; np++) {
                uint32_t ro = (uint32_t)(wn * 32 + np * 16 + (seg & 1) * 8 + lrow) * FPR + koff;
                uint32_t r0, r1, r2, r3;
                ldm_x4(r0, r1, r2, r3, sb + oV + ro);
                b[2*np][0] = r0; b[2*np][1] = r2; b[2*np+1][0] = r1; b[2*np+1][1] = r3;
            }
            #pragma unroll
            for (int nt = 0; nt < 4; nt++)
                #pragma unroll
                for (int mt = 0; mt < 2; mt++)
                    mma16816(acc_o[mt][nt], a[mt], b[nt]);
        }
    }

    // ---- epilogue: O / l -> fp16 ----
    #pragma unroll
    for (int mt = 0; mt < 2; mt++)
        #pragma unroll
        for (int hf = 0; hf < 2; hf++) {
            int i = mt * 2 + hf;
            int row = myrow[i];
            float inv = 1.f / lsum[i];
            #pragma unroll
            for (int nt = 0; nt < 4; nt++) {
                float c0 = acc_o[mt][nt][hf*2]   * inv;
                float c1 = acc_o[mt][nt][hf*2+1] * inv;
                int col = wn * 32 + nt * 8 + tig * 2;
                size_t go = qkbase + (size_t)(q0 + row) * D_EMB + col;
                *(uint32_t*)(Oh + go) = pack_h(__float2half(c0), __float2half(c1));
            }
        }
}

// ======================= support kernels ==============================================
__global__ void cvt_hi(const float* __restrict__ in, hlf* __restrict__ oh, size_t n4)
{
    size_t i = (size_t)blockIdx.x * blockDim.x + threadIdx.x;
    if (i >= n4) return;
    float4 v = *(const float4*)(in + i * 4);
    *(uint2*)(oh + i * 4) = make_uint2(pack_h(__float2half(v.x), __float2half(v.y)),
                                       pack_h(__float2half(v.z), __float2half(v.w)));
}

__global__ void transpose_cvt(const float* __restrict__ in, hlf* __restrict__ oh,
                              int R, int C)
{
    __shared__ float t[32][33];
    int r0 = blockIdx.y * 32, c0 = blockIdx.x * 32;
    t[threadIdx.y][threadIdx.x] = in[(size_t)(r0 + threadIdx.y) * C + c0 + threadIdx.x];
    __syncthreads();
    oh[(size_t)(c0 + threadIdx.y) * R + r0 + threadIdx.x] = __float2half(t[threadIdx.x][threadIdx.y]);
}

__global__ void vt_build_cvt(const float* __restrict__ V, hlf* __restrict__ VTh)
{
    __shared__ float t[32][33];
    int z = blockIdx.z, n = z >> 4, h = z & 15;
    int s0 = blockIdx.x * 32, d0 = blockIdx.y * 32;
    t[threadIdx.y][threadIdx.x] =
        V[(size_t)n * SEQ * D_EMB + (size_t)(s0 + threadIdx.y) * D_EMB + h * HD + d0 + threadIdx.x];
    __syncthreads();
    VTh[((size_t)z * HD + d0 + threadIdx.y) * SEQ + s0 + threadIdx.x] =
        __float2half(t[threadIdx.x][threadIdx.y]);
}

__global__ void add_ln(const float* __restrict__ X, const float* __restrict__ R,
                       const float* __restrict__ g, const float* __restrict__ b,
                       float* __restrict__ Y, hlf* __restrict__ Yh)
{
    const int row = blockIdx.x;
    const float* px = X + (size_t)row * D_EMB;
    const float* pr = R + (size_t)row * D_EMB;
    const int tid = threadIdx.x;
    float v[4];
    float s = 0.f, s2 = 0.f;
    #pragma unroll
    for (int i = 0; i < 4; i++) {
        int c = tid + i*256;
        v[i] = px[c] + pr[c];
        s += v[i]; s2 += v[i]*v[i];
    }
    #pragma unroll
    for (int o = 16; o; o >>= 1) {
        s  += __shfl_xor_sync(0xffffffffu, s,  o);
        s2 += __shfl_xor_sync(0xffffffffu, s2, o);
    }
    __shared__ float sh[8], sh2[8];
    if ((tid & 31) == 0) { sh[tid >> 5] = s; sh2[tid >> 5] = s2; }
    __syncthreads();
    s = 0.f; s2 = 0.f;
    #pragma unroll
    for (int i = 0; i < 8; i++) { s += sh[i]; s2 += sh2[i]; }
    const float mean = s * (1.f / D_EMB);
    const float var  = s2 * (1.f / D_EMB) - mean * mean;
    const float rstd = rsqrtf(var + 1e-5f);
    #pragma unroll
    for (int i = 0; i < 4; i++) {
        int c = tid + i*256;
        float y = (v[i] - mean) * rstd * g[c] + b[c];
        Y[(size_t)row * D_EMB + c] = y;
        if (Yh) Yh[(size_t)row * D_EMB + c] = __float2half(y);
    }
}

// ======================================================================================
extern "C" void kernel_launch(void* const* d_in, const int* in_sizes, int n_in,
                              void* d_out, int out_size)
{
    const float* trg  = (const float*)d_in[0];
    const float* src  = (const float*)d_in[1];
    const float* Wq1  = (const float*)d_in[4];
    const float* bq1  = (const float*)d_in[5];
    const float* Wo1  = (const float*)d_in[6];
    const float* bo1  = (const float*)d_in[7];
    const float* Wq2  = (const float*)d_in[8];
    const float* bq2  = (const float*)d_in[9];
    const float* Wo2  = (const float*)d_in[10];
    const float* bo2  = (const float*)d_in[11];
    const float* Wff1 = (const float*)d_in[12];
    const float* bff1 = (const float*)d_in[13];
    const float* Wff2 = (const float*)d_in[14];
    const float* bff2 = (const float*)d_in[15];
    const float* ln1g = (const float*)d_in[16];
    const float* ln1b = (const float*)d_in[17];
    const float* ln2g = (const float*)d_in[18];
    const float* ln2b = (const float*)d_in[19];
    const float* ln3g = (const float*)d_in[20];
    const float* ln3b = (const float*)d_in[21];
    float* out = (float*)d_out;

    float *Q1, *KV, *TMP, *X1, *X2;
    cudaGetSymbolAddress((void**)&Q1,  g_Q1);
    cudaGetSymbolAddress((void**)&KV,  g_KV);
    cudaGetSymbolAddress((void**)&TMP, g_TMP);
    cudaGetSymbolAddress((void**)&X1,  g_X1);
    cudaGetSymbolAddress((void**)&X2,  g_X2);
    hlf *trgH,*srcH,*Q1H,*Q2H,*KVH,*ATH,*X1H,*X2H,*HH,*VTH;
    hlf *WqT1H,*WoT1H,*WqT2H,*WoT2H,*Wff1TH,*Wff2TH;
    cudaGetSymbolAddress((void**)&trgH, g_trgH);
    cudaGetSymbolAddress((void**)&srcH, g_srcH);
    cudaGetSymbolAddress((void**)&Q1H,  g_Q1H);
    cudaGetSymbolAddress((void**)&Q2H,  g_Q2H);
    cudaGetSymbolAddress((void**)&KVH,  g_KVH);
    cudaGetSymbolAddress((void**)&ATH,  g_ATH);
    cudaGetSymbolAddress((void**)&X1H,  g_X1H);
    cudaGetSymbolAddress((void**)&X2H,  g_X2H);
    cudaGetSymbolAddress((void**)&HH,   g_HH);
    cudaGetSymbolAddress((void**)&VTH,  g_VTH);
    cudaGetSymbolAddress((void**)&WqT1H, g_WqT1H);
    cudaGetSymbolAddress((void**)&WoT1H, g_WoT1H);
    cudaGetSymbolAddress((void**)&WqT2H, g_WqT2H);
    cudaGetSymbolAddress((void**)&WoT2H, g_WoT2H);
    cudaGetSymbolAddress((void**)&Wff1TH, g_Wff1TH);
    cudaGetSymbolAddress((void**)&Wff2TH, g_Wff2TH);

    const int SMG = 2 * 20480;   // 40960
    cudaFuncSetAttribute(mma_gemm<true ,true >, cudaFuncAttributeMaxDynamicSharedMemorySize, SMG);
    cudaFuncSetAttribute(mma_gemm<false,true >, cudaFuncAttributeMaxDynamicSharedMemorySize, SMG);
    cudaFuncSetAttribute(mma_gemm<true ,false>, cudaFuncAttributeMaxDynamicSharedMemorySize, SMG);
    cudaFuncSetAttribute(flash_attn, cudaFuncAttributeMaxDynamicSharedMemorySize, FLASH_SMEM);

    const dim3 t32(32, 32);
    const dim3 blk(256);
    const dim3 gP (D_EMB / 128, ROWS / 128);        // 8 x 32
    const dim3 gF1(D_FF / 128, ROWS / 128);         // 32 x 32
    const dim3 gFA(SEQ / 128, NB*HEADS);            // 16 x 32
    const dim3 gVT(SEQ / 32, HD / 32, NB*HEADS);

    cvt_hi<<<(ROWS*D_EMB/4 + 255)/256, 256>>>(trg, trgH, (size_t)ROWS*D_EMB/4);
    cvt_hi<<<(ROWS*D_EMB/4 + 255)/256, 256>>>(src, srcH, (size_t)ROWS*D_EMB/4);
    transpose_cvt<<<dim3(32, 32), t32>>>(Wq1, WqT1H, D_EMB, D_EMB);

    // ---- self-attention: shared Wq1 on trg => qp==kp==vp, one projection
    mma_gemm<true ,true ><<<gP, blk, SMG>>>(trgH, D_EMB, WqT1H, D_EMB,
                                            Q1, Q1H, D_EMB, bq1, D_EMB, 0);
    vt_build_cvt<<<gVT, t32>>>(Q1, VTH);
    flash_attn<<<gFA, blk, FLASH_SMEM>>>(Q1H, Q1H, VTH, ATH);
    transpose_cvt<<<dim3(32, 32), t32>>>(Wo1, WoT1H, D_EMB, D_EMB);
    mma_gemm<true ,false><<<gP, blk, SMG>>>(ATH, D_EMB, WoT1H, D_EMB,
                                            TMP, nullptr, D_EMB, bo1, D_EMB, 0);
    add_ln<<<ROWS, 256>>>(trg, TMP, ln1g, ln1b, X1, X1H);

    // ---- cross-attention: K and V share the same projection of encoded_src
    transpose_cvt<<<dim3(32, 32), t32>>>(Wq2, WqT2H, D_EMB, D_EMB);
    mma_gemm<false,true ><<<gP, blk, SMG>>>(X1H, D_EMB, WqT2H, D_EMB,
                                            nullptr, Q2H, D_EMB, bq2, D_EMB, 0);
    mma_gemm<true ,true ><<<gP, blk, SMG>>>(srcH, D_EMB, WqT2H, D_EMB,
                                            KV, KVH, D_EMB, bq2, D_EMB, 0);
    vt_build_cvt<<<gVT, t32>>>(KV, VTH);
    flash_attn<<<gFA, blk, FLASH_SMEM>>>(Q2H, KVH, VTH, ATH);
    transpose_cvt<<<dim3(32, 32), t32>>>(Wo2, WoT2H, D_EMB, D_EMB);
    mma_gemm<true ,false><<<gP, blk, SMG>>>(ATH, D_EMB, WoT2H, D_EMB,
                                            TMP, nullptr, D_EMB, bo2, D_EMB, 0);
    add_ln<<<ROWS, 256>>>(X1, TMP, ln2g, ln2b, X2, X2H);

    // ---- FFN
    transpose_cvt<<<dim3(128, 32), t32>>>(Wff1, Wff1TH, D_EMB, D_FF);
    mma_gemm<false,true ><<<gF1, blk, SMG>>>(X2H, D_EMB, Wff1TH, D_EMB,
                                             nullptr, HH, D_FF, bff1, D_EMB, 1);
    transpose_cvt<<<dim3(32, 128), t32>>>(Wff2, Wff2TH, D_FF, D_EMB);
    mma_gemm<true ,false><<<gP, blk, SMG>>>(HH, D_FF, Wff2TH, D_FF,
                                            TMP, nullptr, D_EMB, bff2, D_FF, 0);
    add_ln<<<ROWS, 256>>>(X2, TMP, ln3g, ln3b, out, nullptr);
}

// round 11
// speedup vs baseline: 2.6005x; 1.0597x over previous
#include <cuda_runtime.h>
#include <cuda_fp16.h>
#include <cstdint>
#include <math.h>

#define D_EMB 1024
#define HEADS 16
#define HD    64
#define SEQ   2048
#define NB    2
#define ROWS  (NB*SEQ)   // 4096
#define D_FF  4096

typedef __half hlf;

// ---------------- scratch (__device__ globals; no allocations allowed) ----------------
__device__ float g_Q1 [(size_t)ROWS*D_EMB];
__device__ float g_KV [(size_t)ROWS*D_EMB];
__device__ float g_TMP[(size_t)ROWS*D_EMB];
__device__ float g_X1 [(size_t)ROWS*D_EMB];
__device__ float g_X2 [(size_t)ROWS*D_EMB];
__device__ hlf g_trgH[(size_t)ROWS*D_EMB];
__device__ hlf g_srcH[(size_t)ROWS*D_EMB];
__device__ hlf g_Q1H [(size_t)ROWS*D_EMB];
__device__ hlf g_Q2H [(size_t)ROWS*D_EMB];
__device__ hlf g_KVH [(size_t)ROWS*D_EMB];
__device__ hlf g_ATH [(size_t)ROWS*D_EMB];
__device__ hlf g_X1H [(size_t)ROWS*D_EMB];
__device__ hlf g_X2H [(size_t)ROWS*D_EMB];
__device__ hlf g_HH  [(size_t)ROWS*D_FF];
__device__ hlf g_VTH [(size_t)NB*HEADS*HD*SEQ];
__device__ hlf g_WqT1H[(size_t)D_EMB*D_EMB];
__device__ hlf g_WoT1H[(size_t)D_EMB*D_EMB];
__device__ hlf g_WqT2H[(size_t)D_EMB*D_EMB];
__device__ hlf g_WoT2H[(size_t)D_EMB*D_EMB];
__device__ hlf g_Wff1TH[(size_t)D_EMB*D_FF];
__device__ hlf g_Wff2TH[(size_t)D_EMB*D_FF];

// ---------------- small helpers -------------------------------------------------------
__device__ __forceinline__ uint32_t pack_h(hlf a, hlf b) {
    __half2 t = __halves2half2(a, b);
    return *reinterpret_cast<uint32_t*>(&t);
}
__device__ __forceinline__ uint32_t smem_u32(const void* p) {
    uint32_t a;
    asm("{ .reg .u64 t; cvta.to.shared.u64 t, %1; cvt.u32.u64 %0, t; }" : "=r"(a) : "l"(p));
    return a;
}
__device__ __forceinline__ void mma16816(float* c, const uint32_t* a, const uint32_t* b) {
    asm volatile("mma.sync.aligned.m16n8k16.row.col.f32.f16.f16.f32 "
        "{%0,%1,%2,%3}, {%4,%5,%6,%7}, {%8,%9}, {%0,%1,%2,%3};"
        : "+f"(c[0]), "+f"(c[1]), "+f"(c[2]), "+f"(c[3])
        : "r"(a[0]), "r"(a[1]), "r"(a[2]), "r"(a[3]), "r"(b[0]), "r"(b[1]));
}
__device__ __forceinline__ void ldm_x4(uint32_t& r0, uint32_t& r1, uint32_t& r2, uint32_t& r3,
                                       uint32_t addr) {
    asm volatile("ldmatrix.sync.aligned.m8n8.x4.shared.b16 {%0,%1,%2,%3}, [%4];"
        : "=r"(r0), "=r"(r1), "=r"(r2), "=r"(r3) : "r"(addr));
}
#define CP16(dst, src) asm volatile("cp.async.cg.shared.global [%0], [%1], 16;" :: "r"(dst), "l"(src))
#define CP_COMMIT()    asm volatile("cp.async.commit_group;")
#define CP_WAIT0()     asm volatile("cp.async.wait_group 0;")
#define CP_WAIT1()     asm volatile("cp.async.wait_group 1;")

// ======================= tensor-core NT GEMM: C[M,N] = A[M,K] @ B[N,K]^T ==============
// Plain fp16 single pass. BM=128, BN=128, BK=64 (halved barrier/chunk overhead),
// 2-stage cp.async, 2 CTAs/SM. Row stride 144B -> ldmatrix conflict-free.
template<bool WC32, bool WC16>
__global__ __launch_bounds__(256, 2)
void mma_gemm(const hlf* __restrict__ Ah, int lda,
              const hlf* __restrict__ Bh, int ldb,
              float* __restrict__ C32, hlf* __restrict__ C16h,
              int ldc, const float* __restrict__ bias, int K, int relu)
{
    constexpr int BN   = 128;
    constexpr int NT   = 8;
    constexpr int RSTR = 144;               // 128B data + 16B pad
    constexpr int AS   = 128 * RSTR;        // 18432
    constexpr int BS   = BN * RSTR;         // 18432
    constexpr int STG  = AS + BS;           // 36864; x2 = 73728

    extern __shared__ __align__(16) char dsm[];
    const uint32_t sb = smem_u32(dsm);

    const int tid = threadIdx.x;
    const int lane = tid & 31, wid = tid >> 5;
    const int wm = wid & 3, wn = wid >> 2;
    const int g = lane >> 2, tig = lane & 3;
    const int lrow = lane & 7, seg = lane >> 3;

    const int bm = blockIdx.y * 128, bn = blockIdx.x * BN;

    float acc[2][NT][4];
    #pragma unroll
    for (int mt = 0; mt < 2; mt++)
        #pragma unroll
        for (int nt = 0; nt < NT; nt++)
            #pragma unroll
            for (int j = 0; j < 4; j++) acc[mt][nt][j] = 0.f;

    const int nc = K >> 6;                  // K chunks of 64

    auto load_stage = [&](int c) {
        const int k0 = c << 6;
        const uint32_t st = sb + (c & 1) * STG;
        #pragma unroll
        for (int i = 0; i < 4; i++) {       // A: 128 rows x 8 segs of 16B = 1024 slots
            int idx = tid + i * 256;
            int r = idx >> 3, sg = idx & 7;
            CP16(st + r * RSTR + sg * 16, Ah + (size_t)(bm + r) * lda + k0 + sg * 8);
        }
        #pragma unroll
        for (int i = 0; i < 4; i++) {       // B: 128 rows x 8 segs
            int idx = tid + i * 256;
            int r = idx >> 3, sg = idx & 7;
            CP16(st + AS + r * RSTR + sg * 16, Bh + (size_t)(bn + r) * ldb + k0 + sg * 8);
        }
    };

    load_stage(0);
    CP_COMMIT();

    for (int c = 0; c < nc; c++) {
        if (c + 1 < nc) { load_stage(c + 1); CP_COMMIT(); CP_WAIT1(); }
        else            { CP_WAIT0(); }
        __syncthreads();

        const uint32_t st = sb + (c & 1) * STG;
        const uint32_t pA = st, pB = st + AS;

        #pragma unroll
        for (int k16 = 0; k16 < 4; k16++) {
            const uint32_t koff = k16 * 32 + (seg >> 1) * 16;
            uint32_t a[2][4];
            #pragma unroll
            for (int mt = 0; mt < 2; mt++) {
                uint32_t ro = (uint32_t)(wm * 32 + mt * 16 + (seg & 1) * 8 + lrow) * RSTR + koff;
                ldm_x4(a[mt][0], a[mt][1], a[mt][2], a[mt][3], pA + ro);
            }
            uint32_t b[NT][2];
            #pragma unroll
            for (int np = 0; np < NT / 2; np++) {
                uint32_t ro = (uint32_t)(wn * 64 + np * 16 + (seg & 1) * 8 + lrow) * RSTR + koff;
                uint32_t r0, r1, r2, r3;
                ldm_x4(r0, r1, r2, r3, pB + ro);
                b[2*np][0] = r0; b[2*np][1] = r2; b[2*np+1][0] = r1; b[2*np+1][1] = r3;
            }
            #pragma unroll
            for (int nt = 0; nt < NT; nt++)
                #pragma unroll
                for (int mt = 0; mt < 2; mt++)
                    mma16816(acc[mt][nt], a[mt], b[nt]);
        }
        __syncthreads();
    }

    #pragma unroll
    for (int mt = 0; mt < 2; mt++) {
        #pragma unroll
        for (int nt = 0; nt < NT; nt++) {
            int row = bm + wm * 32 + mt * 16 + g;
            int col = bn + wn * 64 + nt * 8 + tig * 2;
            float b0 = 0.f, b1 = 0.f;
            if (bias) { b0 = __ldg(bias + col); b1 = __ldg(bias + col + 1); }
            float v0 = acc[mt][nt][0] + b0, v1 = acc[mt][nt][1] + b1;
            float v2 = acc[mt][nt][2] + b0, v3 = acc[mt][nt][3] + b1;
            if (relu) {
                v0 = fmaxf(v0, 0.f); v1 = fmaxf(v1, 0.f);
                v2 = fmaxf(v2, 0.f); v3 = fmaxf(v3, 0.f);
            }
            size_t o0 = (size_t)row * ldc + col, o1 = (size_t)(row + 8) * ldc + col;
            if (WC32) {
                *(float2*)(C32 + o0) = make_float2(v0, v1);
                *(float2*)(C32 + o1) = make_float2(v2, v3);
            }
            if (WC16) {
                *(uint32_t*)(C16h + o0) = pack_h(__float2half(v0), __float2half(v1));
                *(uint32_t*)(C16h + o1) = pack_h(__float2half(v2), __float2half(v3));
            }
        }
    }
}

// ======================= fused flash attention (fp16 single pass) =====================
// smem: Q 18432 | K x2 stages 36864 | V 17408 | P 34816 | red 1024 = 108544 -> 2 CTAs/SM
#define FQR 144
#define FPR 272
#define oQ  0
#define oK0 18432
#define oV  55296
#define oP  72704
#define oRed 107520
#define FLASH_SMEM 108544

__global__ __launch_bounds__(256, 2)
void flash_attn(const hlf* __restrict__ Qh,
                const hlf* __restrict__ Kh,
                const hlf* __restrict__ Vth,
                hlf* __restrict__ Oh)
{
    extern __shared__ __align__(16) char dsm[];
    const uint32_t sb = smem_u32(dsm);
    float* red = (float*)(dsm + oRed);

    const int tid = threadIdx.x;
    const int lane = tid & 31, wid = tid >> 5;
    const int wm = wid & 3, wn = wid >> 2;       // 4 x 2 warps
    const int g = lane >> 2, tig = lane & 3;
    const int lrow = lane & 7, seg = lane >> 3;

    const int z = blockIdx.y, n = z >> 4, h = z & 15;
    const int q0 = blockIdx.x * 128;
    const size_t qkbase = (size_t)n * SEQ * D_EMB + h * HD;
    const size_t vbase  = (size_t)z * HD * SEQ;

    // ---- preload Q + K tile 0 ----
    #pragma unroll
    for (int i = 0; i < 4; i++) {
        int idx = tid + i * 256;                  // 1024 slots: 128 rows x 8 segs
        int r = idx >> 3, sg = idx & 7;
        uint32_t so = r * FQR + sg * 16;
        CP16(sb + oQ + so, Qh + qkbase + (size_t)(q0 + r) * D_EMB + sg * 8);
        CP16(sb + oK0 + so, Kh + qkbase + (size_t)r * D_EMB + sg * 8);
    }
    CP_COMMIT();

    float m_prev[4], lsum[4], acc_o[2][4][4];
    #pragma unroll
    for (int i = 0; i < 4; i++) { m_prev[i] = -1e30f; lsum[i] = 0.f; }
    #pragma unroll
    for (int mt = 0; mt < 2; mt++)
        #pragma unroll
        for (int nt = 0; nt < 4; nt++)
            #pragma unroll
            for (int j = 0; j < 4; j++) acc_o[mt][nt][j] = 0.f;

    int myrow[4];
    #pragma unroll
    for (int mt = 0; mt < 2; mt++)
        #pragma unroll
        for (int hf = 0; hf < 2; hf++)
            myrow[mt*2+hf] = wm * 32 + mt * 16 + hf * 8 + g;

    for (int t = 0; t < 16; t++) {
        const int kv0 = t * 128;
        CP_WAIT0();
        __syncthreads();

        // V(t)
        #pragma unroll
        for (int i = 0; i < 4; i++) {
            int idx = tid + i * 256;              // 1024 slots: 64 rows x 16 segs
            int r = idx >> 4, sg = idx & 15;
            CP16(sb + oV + r * FPR + sg * 16, Vth + vbase + (size_t)r * SEQ + kv0 + sg * 8);
        }
        CP_COMMIT();
        // K(t+1) prefetch (clamped)
        {
            int tn = (t + 1 < 16) ? t + 1 : 15;
            uint32_t kst = oK0 + ((t + 1) & 1) * 18432;
            #pragma unroll
            for (int i = 0; i < 4; i++) {
                int idx = tid + i * 256;
                int r = idx >> 3, sg = idx & 7;
                CP16(sb + kst + r * FQR + sg * 16,
                     Kh + qkbase + (size_t)(tn * 128 + r) * D_EMB + sg * 8);
            }
        }
        CP_COMMIT();

        // ---- scores: S = Q @ K(t)^T ----
        float s[2][8][4];
        #pragma unroll
        for (int mt = 0; mt < 2; mt++)
            #pragma unroll
            for (int nt = 0; nt < 8; nt++)
                #pragma unroll
                for (int j = 0; j < 4; j++) s[mt][nt][j] = 0.f;

        const uint32_t kst = sb + oK0 + (t & 1) * 18432;
        #pragma unroll
        for (int k16 = 0; k16 < 4; k16++) {
            const uint32_t koff = k16 * 32 + (seg >> 1) * 16;
            uint32_t a[2][4];
            #pragma unroll
            for (int mt = 0; mt < 2; mt++) {
                uint32_t ro = (uint32_t)(wm * 32 + mt * 16 + (seg & 1) * 8 + lrow) * FQR + koff;
                ldm_x4(a[mt][0], a[mt][1], a[mt][2], a[mt][3], sb + oQ + ro);
            }
            uint32_t b[8][2];
            #pragma unroll
            for (int np = 0; np < 4; np++) {
                uint32_t ro = (uint32_t)(wn * 64 + np * 16 + (seg & 1) * 8 + lrow) * FQR + koff;
                uint32_t r0, r1, r2, r3;
                ldm_x4(r0, r1, r2, r3, kst + ro);
                b[2*np][0] = r0; b[2*np][1] = r2; b[2*np+1][0] = r1; b[2*np+1][1] = r3;
            }
            #pragma unroll
            for (int nt = 0; nt < 8; nt++)
                #pragma unroll
                for (int mt = 0; mt < 2; mt++)
                    mma16816(s[mt][nt], a[mt], b[nt]);
        }

        // ---- online softmax (fp32), scale 0.125 ----
        float mloc[4];
        #pragma unroll
        for (int i = 0; i < 4; i++) mloc[i] = -1e30f;
        #pragma unroll
        for (int mt = 0; mt < 2; mt++)
            #pragma unroll
            for (int nt = 0; nt < 8; nt++)
                #pragma unroll
                for (int hf = 0; hf < 2; hf++)
                    mloc[mt*2+hf] = fmaxf(mloc[mt*2+hf], fmaxf(s[mt][nt][hf*2], s[mt][nt][hf*2+1]));
        #pragma unroll
        for (int i = 0; i < 4; i++) {
            mloc[i] = fmaxf(mloc[i], __shfl_xor_sync(0xffffffffu, mloc[i], 1));
            mloc[i] = fmaxf(mloc[i], __shfl_xor_sync(0xffffffffu, mloc[i], 2));
        }
        if (tig == 0) {
            #pragma unroll
            for (int i = 0; i < 4; i++) red[wn * 128 + myrow[i]] = mloc[i];
        }
        __syncthreads();
        float m_new[4], alpha[4];
        #pragma unroll
        for (int i = 0; i < 4; i++) {
            float mr = fmaxf(red[myrow[i]], red[128 + myrow[i]]);
            float mn = fmaxf(m_prev[i], mr * 0.125f);
            alpha[i] = __expf(m_prev[i] - mn);
            m_new[i] = mn;
        }
        __syncthreads();

        float sl[4] = {0.f, 0.f, 0.f, 0.f};
        #pragma unroll
        for (int mt = 0; mt < 2; mt++)
            #pragma unroll
            for (int nt = 0; nt < 8; nt++)
                #pragma unroll
                for (int hf = 0; hf < 2; hf++) {
                    float p0 = __expf(s[mt][nt][hf*2]   * 0.125f - m_new[mt*2+hf]);
                    float p1 = __expf(s[mt][nt][hf*2+1] * 0.125f - m_new[mt*2+hf]);
                    s[mt][nt][hf*2] = p0; s[mt][nt][hf*2+1] = p1;
                    sl[mt*2+hf] += p0 + p1;
                }
        #pragma unroll
        for (int i = 0; i < 4; i++) {
            sl[i] += __shfl_xor_sync(0xffffffffu, sl[i], 1);
            sl[i] += __shfl_xor_sync(0xffffffffu, sl[i], 2);
        }
        if (tig == 0) {
            #pragma unroll
            for (int i = 0; i < 4; i++) red[wn * 128 + myrow[i]] = sl[i];
        }
        __syncthreads();
        #pragma unroll
        for (int i = 0; i < 4; i++) {
            lsum[i] = lsum[i] * alpha[i] + red[myrow[i]] + red[128 + myrow[i]];
            m_prev[i] = m_new[i];
        }
        #pragma unroll
        for (int mt = 0; mt < 2; mt++)
            #pragma unroll
            for (int nt = 0; nt < 4; nt++)
                #pragma unroll
                for (int hf = 0; hf < 2; hf++) {
                    acc_o[mt][nt][hf*2]   *= alpha[mt*2+hf];
                    acc_o[mt][nt][hf*2+1] *= alpha[mt*2+hf];
                }
        // P -> smem (fp16)
        #pragma unroll
        for (int mt = 0; mt < 2; mt++)
            #pragma unroll
            for (int nt = 0; nt < 8; nt++)
                #pragma unroll
                for (int hf = 0; hf < 2; hf++) {
                    int row = wm * 32 + mt * 16 + hf * 8 + g;
                    int colb = (wn * 64 + nt * 8 + tig * 2) * 2;
                    *(uint32_t*)(dsm + oP + row * FPR + colb) =
                        pack_h(__float2half(s[mt][nt][hf*2]), __float2half(s[mt][nt][hf*2+1]));
                }
        CP_WAIT1();        // V(t) complete (K(t+1) still in flight)
        __syncthreads();

        // ---- O += P @ V ----
        #pragma unroll
        for (int k16 = 0; k16 < 8; k16++) {
            const uint32_t koff = k16 * 32 + (seg >> 1) * 16;
            uint32_t a[2][4];
            #pragma unroll
            for (int mt = 0; mt < 2; mt++) {
                uint32_t ro = (uint32_t)(wm * 32 + mt * 16 + (seg & 1) * 8 + lrow) * FPR + koff;
                ldm_x4(a[mt][0], a[mt][1], a[mt][2], a[mt][3], sb + oP + ro);
            }
            uint32_t b[4][2];
            #pragma unroll
            for (int np = 0; np < 2; np++) {
                uint32_t ro = (uint32_t)(wn * 32 + np * 16 + (seg & 1) * 8 + lrow) * FPR + koff;
                uint32_t r0, r1, r2, r3;
                ldm_x4(r0, r1, r2, r3, sb + oV + ro);
                b[2*np][0] = r0; b[2*np][1] = r2; b[2*np+1][0] = r1; b[2*np+1][1] = r3;
            }
            #pragma unroll
            for (int nt = 0; nt < 4; nt++)
                #pragma unroll
                for (int mt = 0; mt < 2; mt++)
                    mma16816(acc_o[mt][nt], a[mt], b[nt]);
        }
    }

    // ---- epilogue: O / l -> fp16 ----
    #pragma unroll
    for (int mt = 0; mt < 2; mt++)
        #pragma unroll
        for (int hf = 0; hf < 2; hf++) {
            int i = mt * 2 + hf;
            int row = myrow[i];
            float inv = 1.f / lsum[i];
            #pragma unroll
            for (int nt = 0; nt < 4; nt++) {
                float c0 = acc_o[mt][nt][hf*2]   * inv;
                float c1 = acc_o[mt][nt][hf*2+1] * inv;
                int col = wn * 32 + nt * 8 + tig * 2;
                size_t go = qkbase + (size_t)(q0 + row) * D_EMB + col;
                *(uint32_t*)(Oh + go) = pack_h(__float2half(c0), __float2half(c1));
            }
        }
}

// ======================= support kernels ==============================================
__global__ void cvt_hi(const float* __restrict__ in, hlf* __restrict__ oh, size_t n4)
{
    size_t i = (size_t)blockIdx.x * blockDim.x + threadIdx.x;
    if (i >= n4) return;
    float4 v = *(const float4*)(in + i * 4);
    *(uint2*)(oh + i * 4) = make_uint2(pack_h(__float2half(v.x), __float2half(v.y)),
                                       pack_h(__float2half(v.z), __float2half(v.w)));
}

__global__ void transpose_cvt(const float* __restrict__ in, hlf* __restrict__ oh,
                              int R, int C)
{
    __shared__ float t[32][33];
    int r0 = blockIdx.y * 32, c0 = blockIdx.x * 32;
    t[threadIdx.y][threadIdx.x] = in[(size_t)(r0 + threadIdx.y) * C + c0 + threadIdx.x];
    __syncthreads();
    oh[(size_t)(c0 + threadIdx.y) * R + r0 + threadIdx.x] = __float2half(t[threadIdx.x][threadIdx.y]);
}

__global__ void vt_build_cvt(const float* __restrict__ V, hlf* __restrict__ VTh)
{
    __shared__ float t[32][33];
    int z = blockIdx.z, n = z >> 4, h = z & 15;
    int s0 = blockIdx.x * 32, d0 = blockIdx.y * 32;
    t[threadIdx.y][threadIdx.x] =
        V[(size_t)n * SEQ * D_EMB + (size_t)(s0 + threadIdx.y) * D_EMB + h * HD + d0 + threadIdx.x];
    __syncthreads();
    VTh[((size_t)z * HD + d0 + threadIdx.y) * SEQ + s0 + threadIdx.x] =
        __float2half(t[threadIdx.x][threadIdx.y]);
}

__global__ void add_ln(const float* __restrict__ X, const float* __restrict__ R,
                       const float* __restrict__ g, const float* __restrict__ b,
                       float* __restrict__ Y, hlf* __restrict__ Yh)
{
    const int row = blockIdx.x;
    const float* px = X + (size_t)row * D_EMB;
    const float* pr = R + (size_t)row * D_EMB;
    const int tid = threadIdx.x;
    float v[4];
    float s = 0.f, s2 = 0.f;
    #pragma unroll
    for (int i = 0; i < 4; i++) {
        int c = tid + i*256;
        v[i] = px[c] + pr[c];
        s += v[i]; s2 += v[i]*v[i];
    }
    #pragma unroll
    for (int o = 16; o; o >>= 1) {
        s  += __shfl_xor_sync(0xffffffffu, s,  o);
        s2 += __shfl_xor_sync(0xffffffffu, s2, o);
    }
    __shared__ float sh[8], sh2[8];
    if ((tid & 31) == 0) { sh[tid >> 5] = s; sh2[tid >> 5] = s2; }
    __syncthreads();
    s = 0.f; s2 = 0.f;
    #pragma unroll
    for (int i = 0; i < 8; i++) { s += sh[i]; s2 += sh2[i]; }
    const float mean = s * (1.f / D_EMB);
    const float var  = s2 * (1.f / D_EMB) - mean * mean;
    const float rstd = rsqrtf(var + 1e-5f);
    #pragma unroll
    for (int i = 0; i < 4; i++) {
        int c = tid + i*256;
        float y = (v[i] - mean) * rstd * g[c] + b[c];
        Y[(size_t)row * D_EMB + c] = y;
        if (Yh) Yh[(size_t)row * D_EMB + c] = __float2half(y);
    }
}

// ======================================================================================
extern "C" void kernel_launch(void* const* d_in, const int* in_sizes, int n_in,
                              void* d_out, int out_size)
{
    const float* trg  = (const float*)d_in[0];
    const float* src  = (const float*)d_in[1];
    const float* Wq1  = (const float*)d_in[4];
    const float* bq1  = (const float*)d_in[5];
    const float* Wo1  = (const float*)d_in[6];
    const float* bo1  = (const float*)d_in[7];
    const float* Wq2  = (const float*)d_in[8];
    const float* bq2  = (const float*)d_in[9];
    const float* Wo2  = (const float*)d_in[10];
    const float* bo2  = (const float*)d_in[11];
    const float* Wff1 = (const float*)d_in[12];
    const float* bff1 = (const float*)d_in[13];
    const float* Wff2 = (const float*)d_in[14];
    const float* bff2 = (const float*)d_in[15];
    const float* ln1g = (const float*)d_in[16];
    const float* ln1b = (const float*)d_in[17];
    const float* ln2g = (const float*)d_in[18];
    const float* ln2b = (const float*)d_in[19];
    const float* ln3g = (const float*)d_in[20];
    const float* ln3b = (const float*)d_in[21];
    float* out = (float*)d_out;

    float *Q1, *KV, *TMP, *X1, *X2;
    cudaGetSymbolAddress((void**)&Q1,  g_Q1);
    cudaGetSymbolAddress((void**)&KV,  g_KV);
    cudaGetSymbolAddress((void**)&TMP, g_TMP);
    cudaGetSymbolAddress((void**)&X1,  g_X1);
    cudaGetSymbolAddress((void**)&X2,  g_X2);
    hlf *trgH,*srcH,*Q1H,*Q2H,*KVH,*ATH,*X1H,*X2H,*HH,*VTH;
    hlf *WqT1H,*WoT1H,*WqT2H,*WoT2H,*Wff1TH,*Wff2TH;
    cudaGetSymbolAddress((void**)&trgH, g_trgH);
    cudaGetSymbolAddress((void**)&srcH, g_srcH);
    cudaGetSymbolAddress((void**)&Q1H,  g_Q1H);
    cudaGetSymbolAddress((void**)&Q2H,  g_Q2H);
    cudaGetSymbolAddress((void**)&KVH,  g_KVH);
    cudaGetSymbolAddress((void**)&ATH,  g_ATH);
    cudaGetSymbolAddress((void**)&X1H,  g_X1H);
    cudaGetSymbolAddress((void**)&X2H,  g_X2H);
    cudaGetSymbolAddress((void**)&HH,   g_HH);
    cudaGetSymbolAddress((void**)&VTH,  g_VTH);
    cudaGetSymbolAddress((void**)&WqT1H, g_WqT1H);
    cudaGetSymbolAddress((void**)&WoT1H, g_WoT1H);
    cudaGetSymbolAddress((void**)&WqT2H, g_WqT2H);
    cudaGetSymbolAddress((void**)&WoT2H, g_WoT2H);
    cudaGetSymbolAddress((void**)&Wff1TH, g_Wff1TH);
    cudaGetSymbolAddress((void**)&Wff2TH, g_Wff2TH);

    const int SMG = 2 * 36864;   // 73728 -> 2 CTAs/SM
    cudaFuncSetAttribute(mma_gemm<true ,true >, cudaFuncAttributeMaxDynamicSharedMemorySize, SMG);
    cudaFuncSetAttribute(mma_gemm<false,true >, cudaFuncAttributeMaxDynamicSharedMemorySize, SMG);
    cudaFuncSetAttribute(mma_gemm<true ,false>, cudaFuncAttributeMaxDynamicSharedMemorySize, SMG);
    cudaFuncSetAttribute(flash_attn, cudaFuncAttributeMaxDynamicSharedMemorySize, FLASH_SMEM);

    const dim3 t32(32, 32);
    const dim3 blk(256);
    const dim3 gP (D_EMB / 128, ROWS / 128);        // 8 x 32
    const dim3 gF1(D_FF / 128, ROWS / 128);         // 32 x 32
    const dim3 gFA(SEQ / 128, NB*HEADS);            // 16 x 32
    const dim3 gVT(SEQ / 32, HD / 32, NB*HEADS);

    cvt_hi<<<(ROWS*D_EMB/4 + 255)/256, 256>>>(trg, trgH, (size_t)ROWS*D_EMB/4);
    cvt_hi<<<(ROWS*D_EMB/4 + 255)/256, 256>>>(src, srcH, (size_t)ROWS*D_EMB/4);
    transpose_cvt<<<dim3(32, 32), t32>>>(Wq1, WqT1H, D_EMB, D_EMB);

    // ---- self-attention: shared Wq1 on trg => qp==kp==vp, one projection
    mma_gemm<true ,true ><<<gP, blk, SMG>>>(trgH, D_EMB, WqT1H, D_EMB,
                                            Q1, Q1H, D_EMB, bq1, D_EMB, 0);
    vt_build_cvt<<<gVT, t32>>>(Q1, VTH);
    flash_attn<<<gFA, blk, FLASH_SMEM>>>(Q1H, Q1H, VTH, ATH);
    transpose_cvt<<<dim3(32, 32), t32>>>(Wo1, WoT1H, D_EMB, D_EMB);
    mma_gemm<true ,false><<<gP, blk, SMG>>>(ATH, D_EMB, WoT1H, D_EMB,
                                            TMP, nullptr, D_EMB, bo1, D_EMB, 0);
    add_ln<<<ROWS, 256>>>(trg, TMP, ln1g, ln1b, X1, X1H);

    // ---- cross-attention: K and V share the same projection of encoded_src
    transpose_cvt<<<dim3(32, 32), t32>>>(Wq2, WqT2H, D_EMB, D_EMB);
    mma_gemm<false,true ><<<gP, blk, SMG>>>(X1H, D_EMB, WqT2H, D_EMB,
                                            nullptr, Q2H, D_EMB, bq2, D_EMB, 0);
    mma_gemm<true ,true ><<<gP, blk, SMG>>>(srcH, D_EMB, WqT2H, D_EMB,
                                            KV, KVH, D_EMB, bq2, D_EMB, 0);
    vt_build_cvt<<<gVT, t32>>>(KV, VTH);
    flash_attn<<<gFA, blk, FLASH_SMEM>>>(Q2H, KVH, VTH, ATH);
    transpose_cvt<<<dim3(32, 32), t32>>>(Wo2, WoT2H, D_EMB, D_EMB);
    mma_gemm<true ,false><<<gP, blk, SMG>>>(ATH, D_EMB, WoT2H, D_EMB,
                                            TMP, nullptr, D_EMB, bo2, D_EMB, 0);
    add_ln<<<ROWS, 256>>>(X1, TMP, ln2g, ln2b, X2, X2H);

    // ---- FFN
    transpose_cvt<<<dim3(128, 32), t32>>>(Wff1, Wff1TH, D_EMB, D_FF);
    mma_gemm<false,true ><<<gF1, blk, SMG>>>(X2H, D_EMB, Wff1TH, D_EMB,
                                             nullptr, HH, D_FF, bff1, D_EMB, 1);
    transpose_cvt<<<dim3(32, 128), t32>>>(Wff2, Wff2TH, D_FF, D_EMB);
    mma_gemm<true ,false><<<gP, blk, SMG>>>(HH, D_FF, Wff2TH, D_FF,
                                            TMP, nullptr, D_EMB, bff2, D_FF, 0);
    add_ln<<<ROWS, 256>>>(X2, TMP, ln3g, ln3b, out, nullptr);
}

// round 12
// speedup vs baseline: 2.6341x; 1.0129x over previous
#include <cuda_runtime.h>
#include <cuda_fp16.h>
#include <cstdint>
#include <math.h>

#define D_EMB 1024
#define HEADS 16
#define HD    64
#define SEQ   2048
#define NB    2
#define ROWS  (NB*SEQ)   // 4096
#define D_FF  4096

typedef __half hlf;

// ---------------- scratch (__device__ globals; no allocations allowed) ----------------
__device__ float g_TMP[(size_t)ROWS*D_EMB];
__device__ float g_X1 [(size_t)ROWS*D_EMB];
__device__ float g_X2 [(size_t)ROWS*D_EMB];
__device__ hlf g_trgH[(size_t)ROWS*D_EMB];
__device__ hlf g_srcH[(size_t)ROWS*D_EMB];
__device__ hlf g_Q1H [(size_t)ROWS*D_EMB];
__device__ hlf g_Q2H [(size_t)ROWS*D_EMB];
__device__ hlf g_KVH [(size_t)ROWS*D_EMB];
__device__ hlf g_ATH [(size_t)ROWS*D_EMB];
__device__ hlf g_X1H [(size_t)ROWS*D_EMB];
__device__ hlf g_X2H [(size_t)ROWS*D_EMB];
__device__ hlf g_HH  [(size_t)ROWS*D_FF];
__device__ hlf g_VTH [(size_t)NB*HEADS*HD*SEQ];
__device__ hlf g_WqT1H[(size_t)D_EMB*D_EMB];
__device__ hlf g_WoT1H[(size_t)D_EMB*D_EMB];
__device__ hlf g_WqT2H[(size_t)D_EMB*D_EMB];
__device__ hlf g_WoT2H[(size_t)D_EMB*D_EMB];
__device__ hlf g_Wff1TH[(size_t)D_EMB*D_FF];
__device__ hlf g_Wff2TH[(size_t)D_EMB*D_FF];

// ---------------- small helpers -------------------------------------------------------
__device__ __forceinline__ uint32_t pack_h(hlf a, hlf b) {
    __half2 t = __halves2half2(a, b);
    return *reinterpret_cast<uint32_t*>(&t);
}
__device__ __forceinline__ uint32_t smem_u32(const void* p) {
    uint32_t a;
    asm("{ .reg .u64 t; cvta.to.shared.u64 t, %1; cvt.u32.u64 %0, t; }" : "=r"(a) : "l"(p));
    return a;
}
__device__ __forceinline__ void mma16816(float* c, const uint32_t* a, const uint32_t* b) {
    asm volatile("mma.sync.aligned.m16n8k16.row.col.f32.f16.f16.f32 "
        "{%0,%1,%2,%3}, {%4,%5,%6,%7}, {%8,%9}, {%0,%1,%2,%3};"
        : "+f"(c[0]), "+f"(c[1]), "+f"(c[2]), "+f"(c[3])
        : "r"(a[0]), "r"(a[1]), "r"(a[2]), "r"(a[3]), "r"(b[0]), "r"(b[1]));
}
__device__ __forceinline__ void ldm_x4(uint32_t& r0, uint32_t& r1, uint32_t& r2, uint32_t& r3,
                                       uint32_t addr) {
    asm volatile("ldmatrix.sync.aligned.m8n8.x4.shared.b16 {%0,%1,%2,%3}, [%4];"
        : "=r"(r0), "=r"(r1), "=r"(r2), "=r"(r3) : "r"(addr));
}
#define CP16(dst, src) asm volatile("cp.async.cg.shared.global [%0], [%1], 16;" :: "r"(dst), "l"(src))
#define CP_COMMIT()    asm volatile("cp.async.commit_group;")
#define CP_WAIT0()     asm volatile("cp.async.wait_group 0;")
#define CP_WAIT1()     asm volatile("cp.async.wait_group 1;")

// ======================= tensor-core NT GEMM: C[M,N] = A[M,K] @ B[N,K]^T ==============
// Plain fp16 single pass. BM=128, BN=128, BK=64. 3-stage cp.async pipeline (prefetch
// distance 2 hides L2 latency), ONE barrier per chunk. 2 CTAs/SM (221KB smem total).
template<bool WC32, bool WC16>
__global__ __launch_bounds__(256, 2)
void mma_gemm(const hlf* __restrict__ Ah, int lda,
              const hlf* __restrict__ Bh, int ldb,
              float* __restrict__ C32, hlf* __restrict__ C16h,
              int ldc, const float* __restrict__ bias, int K, int relu)
{
    constexpr int BN   = 128;
    constexpr int NT   = 8;
    constexpr int RSTR = 144;               // 128B data + 16B pad
    constexpr int AS   = 128 * RSTR;        // 18432
    constexpr int BS   = BN * RSTR;         // 18432
    constexpr int STG  = AS + BS;           // 36864; x3 = 110592

    extern __shared__ __align__(16) char dsm[];
    const uint32_t sb = smem_u32(dsm);

    const int tid = threadIdx.x;
    const int lane = tid & 31, wid = tid >> 5;
    const int wm = wid & 3, wn = wid >> 2;
    const int g = lane >> 2, tig = lane & 3;
    const int lrow = lane & 7, seg = lane >> 3;

    const int bm = blockIdx.y * 128, bn = blockIdx.x * BN;

    float acc[2][NT][4];
    #pragma unroll
    for (int mt = 0; mt < 2; mt++)
        #pragma unroll
        for (int nt = 0; nt < NT; nt++)
            #pragma unroll
            for (int j = 0; j < 4; j++) acc[mt][nt][j] = 0.f;

    const int nc = K >> 6;                  // K chunks of 64

    auto load_stage = [&](int c) {
        const int k0 = c << 6;
        const uint32_t st = sb + (c % 3) * STG;
        #pragma unroll
        for (int i = 0; i < 4; i++) {       // A: 128 rows x 8 segs of 16B
            int idx = tid + i * 256;
            int r = idx >> 3, sg = idx & 7;
            CP16(st + r * RSTR + sg * 16, Ah + (size_t)(bm + r) * lda + k0 + sg * 8);
        }
        #pragma unroll
        for (int i = 0; i < 4; i++) {       // B: 128 rows x 8 segs
            int idx = tid + i * 256;
            int r = idx >> 3, sg = idx & 7;
            CP16(st + AS + r * RSTR + sg * 16, Bh + (size_t)(bn + r) * ldb + k0 + sg * 8);
        }
    };

    load_stage(0); CP_COMMIT();
    load_stage(1); CP_COMMIT();

    for (int c = 0; c < nc; c++) {
        if (c + 1 < nc) CP_WAIT1(); else CP_WAIT0();
        __syncthreads();                    // chunk c data visible; chunk c-1 reads done
        if (c + 2 < nc) { load_stage(c + 2); CP_COMMIT(); }

        const uint32_t st = sb + (c % 3) * STG;
        const uint32_t pA = st, pB = st + AS;

        #pragma unroll
        for (int k16 = 0; k16 < 4; k16++) {
            const uint32_t koff = k16 * 32 + (seg >> 1) * 16;
            uint32_t a[2][4];
            #pragma unroll
            for (int mt = 0; mt < 2; mt++) {
                uint32_t ro = (uint32_t)(wm * 32 + mt * 16 + (seg & 1) * 8 + lrow) * RSTR + koff;
                ldm_x4(a[mt][0], a[mt][1], a[mt][2], a[mt][3], pA + ro);
            }
            uint32_t b[NT][2];
            #pragma unroll
            for (int np = 0; np < NT / 2; np++) {
                uint32_t ro = (uint32_t)(wn * 64 + np * 16 + (seg & 1) * 8 + lrow) * RSTR + koff;
                uint32_t r0, r1, r2, r3;
                ldm_x4(r0, r1, r2, r3, pB + ro);
                b[2*np][0] = r0; b[2*np][1] = r2; b[2*np+1][0] = r1; b[2*np+1][1] = r3;
            }
            #pragma unroll
            for (int nt = 0; nt < NT; nt++)
                #pragma unroll
                for (int mt = 0; mt < 2; mt++)
                    mma16816(acc[mt][nt], a[mt], b[nt]);
        }
    }

    #pragma unroll
    for (int mt = 0; mt < 2; mt++) {
        #pragma unroll
        for (int nt = 0; nt < NT; nt++) {
            int row = bm + wm * 32 + mt * 16 + g;
            int col = bn + wn * 64 + nt * 8 + tig * 2;
            float b0 = 0.f, b1 = 0.f;
            if (bias) { b0 = __ldg(bias + col); b1 = __ldg(bias + col + 1); }
            float v0 = acc[mt][nt][0] + b0, v1 = acc[mt][nt][1] + b1;
            float v2 = acc[mt][nt][2] + b0, v3 = acc[mt][nt][3] + b1;
            if (relu) {
                v0 = fmaxf(v0, 0.f); v1 = fmaxf(v1, 0.f);
                v2 = fmaxf(v2, 0.f); v3 = fmaxf(v3, 0.f);
            }
            size_t o0 = (size_t)row * ldc + col, o1 = (size_t)(row + 8) * ldc + col;
            if (WC32) {
                *(float2*)(C32 + o0) = make_float2(v0, v1);
                *(float2*)(C32 + o1) = make_float2(v2, v3);
            }
            if (WC16) {
                *(uint32_t*)(C16h + o0) = pack_h(__float2half(v0), __float2half(v1));
                *(uint32_t*)(C16h + o1) = pack_h(__float2half(v2), __float2half(v3));
            }
        }
    }
}

// ======================= fused flash attention (fp16 single pass) =====================
// smem: Q 18432 | K x2 stages 36864 | V 17408 | P 34816 | red 1024 = 108544 -> 2 CTAs/SM
#define FQR 144
#define FPR 272
#define oQ  0
#define oK0 18432
#define oV  55296
#define oP  72704
#define oRed 107520
#define FLASH_SMEM 108544

__global__ __launch_bounds__(256, 2)
void flash_attn(const hlf* __restrict__ Qh,
                const hlf* __restrict__ Kh,
                const hlf* __restrict__ Vth,
                hlf* __restrict__ Oh)
{
    extern __shared__ __align__(16) char dsm[];
    const uint32_t sb = smem_u32(dsm);
    float* red = (float*)(dsm + oRed);

    const int tid = threadIdx.x;
    const int lane = tid & 31, wid = tid >> 5;
    const int wm = wid & 3, wn = wid >> 2;       // 4 x 2 warps
    const int g = lane >> 2, tig = lane & 3;
    const int lrow = lane & 7, seg = lane >> 3;

    const int z = blockIdx.y, n = z >> 4, h = z & 15;
    const int q0 = blockIdx.x * 128;
    const size_t qkbase = (size_t)n * SEQ * D_EMB + h * HD;
    const size_t vbase  = (size_t)z * HD * SEQ;

    // ---- preload Q + K tile 0 ----
    #pragma unroll
    for (int i = 0; i < 4; i++) {
        int idx = tid + i * 256;                  // 1024 slots: 128 rows x 8 segs
        int r = idx >> 3, sg = idx & 7;
        uint32_t so = r * FQR + sg * 16;
        CP16(sb + oQ + so, Qh + qkbase + (size_t)(q0 + r) * D_EMB + sg * 8);
        CP16(sb + oK0 + so, Kh + qkbase + (size_t)r * D_EMB + sg * 8);
    }
    CP_COMMIT();

    float m_prev[4], lsum[4], acc_o[2][4][4];
    #pragma unroll
    for (int i = 0; i < 4; i++) { m_prev[i] = -1e30f; lsum[i] = 0.f; }
    #pragma unroll
    for (int mt = 0; mt < 2; mt++)
        #pragma unroll
        for (int nt = 0; nt < 4; nt++)
            #pragma unroll
            for (int j = 0; j < 4; j++) acc_o[mt][nt][j] = 0.f;

    int myrow[4];
    #pragma unroll
    for (int mt = 0; mt < 2; mt++)
        #pragma unroll
        for (int hf = 0; hf < 2; hf++)
            myrow[mt*2+hf] = wm * 32 + mt * 16 + hf * 8 + g;

    for (int t = 0; t < 16; t++) {
        const int kv0 = t * 128;
        CP_WAIT0();
        __syncthreads();

        // V(t)
        #pragma unroll
        for (int i = 0; i < 4; i++) {
            int idx = tid + i * 256;              // 1024 slots: 64 rows x 16 segs
            int r = idx >> 4, sg = idx & 15;
            CP16(sb + oV + r * FPR + sg * 16, Vth + vbase + (size_t)r * SEQ + kv0 + sg * 8);
        }
        CP_COMMIT();
        // K(t+1) prefetch (clamped)
        {
            int tn = (t + 1 < 16) ? t + 1 : 15;
            uint32_t kst = oK0 + ((t + 1) & 1) * 18432;
            #pragma unroll
            for (int i = 0; i < 4; i++) {
                int idx = tid + i * 256;
                int r = idx >> 3, sg = idx & 7;
                CP16(sb + kst + r * FQR + sg * 16,
                     Kh + qkbase + (size_t)(tn * 128 + r) * D_EMB + sg * 8);
            }
        }
        CP_COMMIT();

        // ---- scores: S = Q @ K(t)^T ----
        float s[2][8][4];
        #pragma unroll
        for (int mt = 0; mt < 2; mt++)
            #pragma unroll
            for (int nt = 0; nt < 8; nt++)
                #pragma unroll
                for (int j = 0; j < 4; j++) s[mt][nt][j] = 0.f;

        const uint32_t kst = sb + oK0 + (t & 1) * 18432;
        #pragma unroll
        for (int k16 = 0; k16 < 4; k16++) {
            const uint32_t koff = k16 * 32 + (seg >> 1) * 16;
            uint32_t a[2][4];
            #pragma unroll
            for (int mt = 0; mt < 2; mt++) {
                uint32_t ro = (uint32_t)(wm * 32 + mt * 16 + (seg & 1) * 8 + lrow) * FQR + koff;
                ldm_x4(a[mt][0], a[mt][1], a[mt][2], a[mt][3], sb + oQ + ro);
            }
            uint32_t b[8][2];
            #pragma unroll
            for (int np = 0; np < 4; np++) {
                uint32_t ro = (uint32_t)(wn * 64 + np * 16 + (seg & 1) * 8 + lrow) * FQR + koff;
                uint32_t r0, r1, r2, r3;
                ldm_x4(r0, r1, r2, r3, kst + ro);
                b[2*np][0] = r0; b[2*np][1] = r2; b[2*np+1][0] = r1; b[2*np+1][1] = r3;
            }
            #pragma unroll
            for (int nt = 0; nt < 8; nt++)
                #pragma unroll
                for (int mt = 0; mt < 2; mt++)
                    mma16816(s[mt][nt], a[mt], b[nt]);
        }

        // ---- online softmax (fp32), scale 0.125 ----
        float mloc[4];
        #pragma unroll
        for (int i = 0; i < 4; i++) mloc[i] = -1e30f;
        #pragma unroll
        for (int mt = 0; mt < 2; mt++)
            #pragma unroll
            for (int nt = 0; nt < 8; nt++)
                #pragma unroll
                for (int hf = 0; hf < 2; hf++)
                    mloc[mt*2+hf] = fmaxf(mloc[mt*2+hf], fmaxf(s[mt][nt][hf*2], s[mt][nt][hf*2+1]));
        #pragma unroll
        for (int i = 0; i < 4; i++) {
            mloc[i] = fmaxf(mloc[i], __shfl_xor_sync(0xffffffffu, mloc[i], 1));
            mloc[i] = fmaxf(mloc[i], __shfl_xor_sync(0xffffffffu, mloc[i], 2));
        }
        if (tig == 0) {
            #pragma unroll
            for (int i = 0; i < 4; i++) red[wn * 128 + myrow[i]] = mloc[i];
        }
        __syncthreads();
        float m_new[4], alpha[4];
        #pragma unroll
        for (int i = 0; i < 4; i++) {
            float mr = fmaxf(red[myrow[i]], red[128 + myrow[i]]);
            float mn = fmaxf(m_prev[i], mr * 0.125f);
            alpha[i] = __expf(m_prev[i] - mn);
            m_new[i] = mn;
        }
        __syncthreads();

        float sl[4] = {0.f, 0.f, 0.f, 0.f};
        #pragma unroll
        for (int mt = 0; mt < 2; mt++)
            #pragma unroll
            for (int nt = 0; nt < 8; nt++)
                #pragma unroll
                for (int hf = 0; hf < 2; hf++) {
                    float p0 = __expf(s[mt][nt][hf*2]   * 0.125f - m_new[mt*2+hf]);
                    float p1 = __expf(s[mt][nt][hf*2+1] * 0.125f - m_new[mt*2+hf]);
                    s[mt][nt][hf*2] = p0; s[mt][nt][hf*2+1] = p1;
                    sl[mt*2+hf] += p0 + p1;
                }
        #pragma unroll
        for (int i = 0; i < 4; i++) {
            sl[i] += __shfl_xor_sync(0xffffffffu, sl[i], 1);
            sl[i] += __shfl_xor_sync(0xffffffffu, sl[i], 2);
        }
        if (tig == 0) {
            #pragma unroll
            for (int i = 0; i < 4; i++) red[wn * 128 + myrow[i]] = sl[i];
        }
        __syncthreads();
        #pragma unroll
        for (int i = 0; i < 4; i++) {
            lsum[i] = lsum[i] * alpha[i] + red[myrow[i]] + red[128 + myrow[i]];
            m_prev[i] = m_new[i];
        }
        #pragma unroll
        for (int mt = 0; mt < 2; mt++)
            #pragma unroll
            for (int nt = 0; nt < 4; nt++)
                #pragma unroll
                for (int hf = 0; hf < 2; hf++) {
                    acc_o[mt][nt][hf*2]   *= alpha[mt*2+hf];
                    acc_o[mt][nt][hf*2+1] *= alpha[mt*2+hf];
                }
        // P -> smem (fp16)
        #pragma unroll
        for (int mt = 0; mt < 2; mt++)
            #pragma unroll
            for (int nt = 0; nt < 8; nt++)
                #pragma unroll
                for (int hf = 0; hf < 2; hf++) {
                    int row = wm * 32 + mt * 16 + hf * 8 + g;
                    int colb = (wn * 64 + nt * 8 + tig * 2) * 2;
                    *(uint32_t*)(dsm + oP + row * FPR + colb) =
                        pack_h(__float2half(s[mt][nt][hf*2]), __float2half(s[mt][nt][hf*2+1]));
                }
        CP_WAIT1();        // V(t) complete (K(t+1) still in flight)
        __syncthreads();

        // ---- O += P @ V ----
        #pragma unroll
        for (int k16 = 0; k16 < 8; k16++) {
            const uint32_t koff = k16 * 32 + (seg >> 1) * 16;
            uint32_t a[2][4];
            #pragma unroll
            for (int mt = 0; mt < 2; mt++) {
                uint32_t ro = (uint32_t)(wm * 32 + mt * 16 + (seg & 1) * 8 + lrow) * FPR + koff;
                ldm_x4(a[mt][0], a[mt][1], a[mt][2], a[mt][3], sb + oP + ro);
            }
            uint32_t b[4][2];
            #pragma unroll
            for (int np = 0; np < 2; np++) {
                uint32_t ro = (uint32_t)(wn * 32 + np * 16 + (seg & 1) * 8 + lrow) * FPR + koff;
                uint32_t r0, r1, r2, r3;
                ldm_x4(r0, r1, r2, r3, sb + oV + ro);
                b[2*np][0] = r0; b[2*np][1] = r2; b[2*np+1][0] = r1; b[2*np+1][1] = r3;
            }
            #pragma unroll
            for (int nt = 0; nt < 4; nt++)
                #pragma unroll
                for (int mt = 0; mt < 2; mt++)
                    mma16816(acc_o[mt][nt], a[mt], b[nt]);
        }
    }

    // ---- epilogue: O / l -> fp16 ----
    #pragma unroll
    for (int mt = 0; mt < 2; mt++)
        #pragma unroll
        for (int hf = 0; hf < 2; hf++) {
            int i = mt * 2 + hf;
            int row = myrow[i];
            float inv = 1.f / lsum[i];
            #pragma unroll
            for (int nt = 0; nt < 4; nt++) {
                float c0 = acc_o[mt][nt][hf*2]   * inv;
                float c1 = acc_o[mt][nt][hf*2+1] * inv;
                int col = wn * 32 + nt * 8 + tig * 2;
                size_t go = qkbase + (size_t)(q0 + row) * D_EMB + col;
                *(uint32_t*)(Oh + go) = pack_h(__float2half(c0), __float2half(c1));
            }
        }
}

// ======================= support kernels ==============================================
__global__ void cvt_hi(const float* __restrict__ in, hlf* __restrict__ oh, size_t n4)
{
    size_t i = (size_t)blockIdx.x * blockDim.x + threadIdx.x;
    if (i >= n4) return;
    float4 v = *(const float4*)(in + i * 4);
    *(uint2*)(oh + i * 4) = make_uint2(pack_h(__float2half(v.x), __float2half(v.y)),
                                       pack_h(__float2half(v.z), __float2half(v.w)));
}

__global__ void transpose_cvt(const float* __restrict__ in, hlf* __restrict__ oh,
                              int R, int C)
{
    __shared__ float t[32][33];
    int r0 = blockIdx.y * 32, c0 = blockIdx.x * 32;
    t[threadIdx.y][threadIdx.x] = in[(size_t)(r0 + threadIdx.y) * C + c0 + threadIdx.x];
    __syncthreads();
    oh[(size_t)(c0 + threadIdx.y) * R + r0 + threadIdx.x] = __float2half(t[threadIdx.x][threadIdx.y]);
}

// VT[z][d][s] = Vh[n][s][h*64+d] (fp16 -> fp16 transpose per head)
__global__ void vt_build_h(const hlf* __restrict__ Vh, hlf* __restrict__ VTh)
{
    __shared__ hlf t[32][34];
    int z = blockIdx.z, n = z >> 4, h = z & 15;
    int s0 = blockIdx.x * 32, d0 = blockIdx.y * 32;
    t[threadIdx.y][threadIdx.x] =
        Vh[(size_t)n * SEQ * D_EMB + (size_t)(s0 + threadIdx.y) * D_EMB + h * HD + d0 + threadIdx.x];
    __syncthreads();
    VTh[((size_t)z * HD + d0 + threadIdx.y) * SEQ + s0 + threadIdx.x] = t[threadIdx.x][threadIdx.y];
}

__global__ void add_ln(const float* __restrict__ X, const float* __restrict__ R,
                       const float* __restrict__ g, const float* __restrict__ b,
                       float* __restrict__ Y, hlf* __restrict__ Yh)
{
    const int row = blockIdx.x;
    const float* px = X + (size_t)row * D_EMB;
    const float* pr = R + (size_t)row * D_EMB;
    const int tid = threadIdx.x;
    float v[4];
    float s = 0.f, s2 = 0.f;
    #pragma unroll
    for (int i = 0; i < 4; i++) {
        int c = tid + i*256;
        v[i] = px[c] + pr[c];
        s += v[i]; s2 += v[i]*v[i];
    }
    #pragma unroll
    for (int o = 16; o; o >>= 1) {
        s  += __shfl_xor_sync(0xffffffffu, s,  o);
        s2 += __shfl_xor_sync(0xffffffffu, s2, o);
    }
    __shared__ float sh[8], sh2[8];
    if ((tid & 31) == 0) { sh[tid >> 5] = s; sh2[tid >> 5] = s2; }
    __syncthreads();
    s = 0.f; s2 = 0.f;
    #pragma unroll
    for (int i = 0; i < 8; i++) { s += sh[i]; s2 += sh2[i]; }
    const float mean = s * (1.f / D_EMB);
    const float var  = s2 * (1.f / D_EMB) - mean * mean;
    const float rstd = rsqrtf(var + 1e-5f);
    #pragma unroll
    for (int i = 0; i < 4; i++) {
        int c = tid + i*256;
        float y = (v[i] - mean) * rstd * g[c] + b[c];
        Y[(size_t)row * D_EMB + c] = y;
        if (Yh) Yh[(size_t)row * D_EMB + c] = __float2half(y);
    }
}

// ======================================================================================
extern "C" void kernel_launch(void* const* d_in, const int* in_sizes, int n_in,
                              void* d_out, int out_size)
{
    const float* trg  = (const float*)d_in[0];
    const float* src  = (const float*)d_in[1];
    const float* Wq1  = (const float*)d_in[4];
    const float* bq1  = (const float*)d_in[5];
    const float* Wo1  = (const float*)d_in[6];
    const float* bo1  = (const float*)d_in[7];
    const float* Wq2  = (const float*)d_in[8];
    const float* bq2  = (const float*)d_in[9];
    const float* Wo2  = (const float*)d_in[10];
    const float* bo2  = (const float*)d_in[11];
    const float* Wff1 = (const float*)d_in[12];
    const float* bff1 = (const float*)d_in[13];
    const float* Wff2 = (const float*)d_in[14];
    const float* bff2 = (const float*)d_in[15];
    const float* ln1g = (const float*)d_in[16];
    const float* ln1b = (const float*)d_in[17];
    const float* ln2g = (const float*)d_in[18];
    const float* ln2b = (const float*)d_in[19];
    const float* ln3g = (const float*)d_in[20];
    const float* ln3b = (const float*)d_in[21];
    float* out = (float*)d_out;

    float *TMP, *X1, *X2;
    cudaGetSymbolAddress((void**)&TMP, g_TMP);
    cudaGetSymbolAddress((void**)&X1,  g_X1);
    cudaGetSymbolAddress((void**)&X2,  g_X2);
    hlf *trgH,*srcH,*Q1H,*Q2H,*KVH,*ATH,*X1H,*X2H,*HH,*VTH;
    hlf *WqT1H,*WoT1H,*WqT2H,*WoT2H,*Wff1TH,*Wff2TH;
    cudaGetSymbolAddress((void**)&trgH, g_trgH);
    cudaGetSymbolAddress((void**)&srcH, g_srcH);
    cudaGetSymbolAddress((void**)&Q1H,  g_Q1H);
    cudaGetSymbolAddress((void**)&Q2H,  g_Q2H);
    cudaGetSymbolAddress((void**)&KVH,  g_KVH);
    cudaGetSymbolAddress((void**)&ATH,  g_ATH);
    cudaGetSymbolAddress((void**)&X1H,  g_X1H);
    cudaGetSymbolAddress((void**)&X2H,  g_X2H);
    cudaGetSymbolAddress((void**)&HH,   g_HH);
    cudaGetSymbolAddress((void**)&VTH,  g_VTH);
    cudaGetSymbolAddress((void**)&WqT1H, g_WqT1H);
    cudaGetSymbolAddress((void**)&WoT1H, g_WoT1H);
    cudaGetSymbolAddress((void**)&WqT2H, g_WqT2H);
    cudaGetSymbolAddress((void**)&WoT2H, g_WoT2H);
    cudaGetSymbolAddress((void**)&Wff1TH, g_Wff1TH);
    cudaGetSymbolAddress((void**)&Wff2TH, g_Wff2TH);

    const int SMG = 3 * 36864;   // 110592; 2 CTAs/SM = 221184 <= 228KB
    cudaFuncSetAttribute(mma_gemm<false,true >, cudaFuncAttributeMaxDynamicSharedMemorySize, SMG);
    cudaFuncSetAttribute(mma_gemm<true ,false>, cudaFuncAttributeMaxDynamicSharedMemorySize, SMG);
    cudaFuncSetAttribute(flash_attn, cudaFuncAttributeMaxDynamicSharedMemorySize, FLASH_SMEM);

    const dim3 t32(32, 32);
    const dim3 blk(256);
    const dim3 gP (D_EMB / 128, ROWS / 128);        // 8 x 32
    const dim3 gF1(D_FF / 128, ROWS / 128);         // 32 x 32
    const dim3 gFA(SEQ / 128, NB*HEADS);            // 16 x 32
    const dim3 gVT(SEQ / 32, HD / 32, NB*HEADS);

    cvt_hi<<<(ROWS*D_EMB/4 + 255)/256, 256>>>(trg, trgH, (size_t)ROWS*D_EMB/4);
    cvt_hi<<<(ROWS*D_EMB/4 + 255)/256, 256>>>(src, srcH, (size_t)ROWS*D_EMB/4);
    transpose_cvt<<<dim3(32, 32), t32>>>(Wq1, WqT1H, D_EMB, D_EMB);

    // ---- self-attention: shared Wq1 on trg => qp==kp==vp, one projection
    mma_gemm<false,true ><<<gP, blk, SMG>>>(trgH, D_EMB, WqT1H, D_EMB,
                                            nullptr, Q1H, D_EMB, bq1, D_EMB, 0);
    vt_build_h<<<gVT, t32>>>(Q1H, VTH);
    flash_attn<<<gFA, blk, FLASH_SMEM>>>(Q1H, Q1H, VTH, ATH);
    transpose_cvt<<<dim3(32, 32), t32>>>(Wo1, WoT1H, D_EMB, D_EMB);
    mma_gemm<true ,false><<<gP, blk, SMG>>>(ATH, D_EMB, WoT1H, D_EMB,
                                            TMP, nullptr, D_EMB, bo1, D_EMB, 0);
    add_ln<<<ROWS, 256>>>(trg, TMP, ln1g, ln1b, X1, X1H);

    // ---- cross-attention: K and V share the same projection of encoded_src
    transpose_cvt<<<dim3(32, 32), t32>>>(Wq2, WqT2H, D_EMB, D_EMB);
    mma_gemm<false,true ><<<gP, blk, SMG>>>(X1H, D_EMB, WqT2H, D_EMB,
                                            nullptr, Q2H, D_EMB, bq2, D_EMB, 0);
    mma_gemm<false,true ><<<gP, blk, SMG>>>(srcH, D_EMB, WqT2H, D_EMB,
                                            nullptr, KVH, D_EMB, bq2, D_EMB, 0);
    vt_build_h<<<gVT, t32>>>(KVH, VTH);
    flash_attn<<<gFA, blk, FLASH_SMEM>>>(Q2H, KVH, VTH, ATH);
    transpose_cvt<<<dim3(32, 32), t32>>>(Wo2, WoT2H, D_EMB, D_EMB);
    mma_gemm<true ,false><<<gP, blk, SMG>>>(ATH, D_EMB, WoT2H, D_EMB,
                                            TMP, nullptr, D_EMB, bo2, D_EMB, 0);
    add_ln<<<ROWS, 256>>>(X1, TMP, ln2g, ln2b, X2, X2H);

    // ---- FFN
    transpose_cvt<<<dim3(128, 32), t32>>>(Wff1, Wff1TH, D_EMB, D_FF);
    mma_gemm<false,true ><<<gF1, blk, SMG>>>(X2H, D_EMB, Wff1TH, D_EMB,
                                             nullptr, HH, D_FF, bff1, D_EMB, 1);
    transpose_cvt<<<dim3(32, 128), t32>>>(Wff2, Wff2TH, D_FF, D_EMB);
    mma_gemm<true ,false><<<gP, blk, SMG>>>(HH, D_FF, Wff2TH, D_FF,
                                            TMP, nullptr, D_EMB, bff2, D_FF, 0);
    add_ln<<<ROWS, 256>>>(X2, TMP, ln3g, ln3b, out, nullptr);
}

// round 13
// speedup vs baseline: 2.7341x; 1.0380x over previous
#include <cuda_runtime.h>
#include <cuda_fp16.h>
#include <cstdint>
#include <math.h>

#define D_EMB 1024
#define HEADS 16
#define HD    64
#define SEQ   2048
#define NB    2
#define ROWS  (NB*SEQ)   // 4096
#define D_FF  4096

typedef __half hlf;

// ---------------- scratch (__device__ globals; no allocations allowed) ----------------
__device__ float g_TMP[(size_t)ROWS*D_EMB];
__device__ float g_X1 [(size_t)ROWS*D_EMB];
__device__ float g_X2 [(size_t)ROWS*D_EMB];
__device__ hlf g_trgH[(size_t)ROWS*D_EMB];
__device__ hlf g_srcH[(size_t)ROWS*D_EMB];
__device__ hlf g_Q1H [(size_t)ROWS*D_EMB];
__device__ hlf g_Q2H [(size_t)ROWS*D_EMB];
__device__ hlf g_KVH [(size_t)ROWS*D_EMB];
__device__ hlf g_ATH [(size_t)ROWS*D_EMB];
__device__ hlf g_X1H [(size_t)ROWS*D_EMB];
__device__ hlf g_X2H [(size_t)ROWS*D_EMB];
__device__ hlf g_HH  [(size_t)ROWS*D_FF];
__device__ hlf g_VTH [(size_t)NB*HEADS*HD*SEQ];
__device__ hlf g_WqT1H[(size_t)D_EMB*D_EMB];
__device__ hlf g_WoT1H[(size_t)D_EMB*D_EMB];
__device__ hlf g_WqT2H[(size_t)D_EMB*D_EMB];
__device__ hlf g_WoT2H[(size_t)D_EMB*D_EMB];
__device__ hlf g_Wff1TH[(size_t)D_EMB*D_FF];
__device__ hlf g_Wff2TH[(size_t)D_EMB*D_FF];

// ---------------- small helpers -------------------------------------------------------
__device__ __forceinline__ uint32_t pack_h(hlf a, hlf b) {
    __half2 t = __halves2half2(a, b);
    return *reinterpret_cast<uint32_t*>(&t);
}
__device__ __forceinline__ uint32_t pack_hf(float a, float b) {
    __half2 t = __floats2half2_rn(a, b);
    return *reinterpret_cast<uint32_t*>(&t);
}
__device__ __forceinline__ uint32_t smem_u32(const void* p) {
    uint32_t a;
    asm("{ .reg .u64 t; cvta.to.shared.u64 t, %1; cvt.u32.u64 %0, t; }" : "=r"(a) : "l"(p));
    return a;
}
__device__ __forceinline__ void mma16816(float* c, const uint32_t* a, const uint32_t* b) {
    asm volatile("mma.sync.aligned.m16n8k16.row.col.f32.f16.f16.f32 "
        "{%0,%1,%2,%3}, {%4,%5,%6,%7}, {%8,%9}, {%0,%1,%2,%3};"
        : "+f"(c[0]), "+f"(c[1]), "+f"(c[2]), "+f"(c[3])
        : "r"(a[0]), "r"(a[1]), "r"(a[2]), "r"(a[3]), "r"(b[0]), "r"(b[1]));
}
__device__ __forceinline__ void ldm_x4(uint32_t& r0, uint32_t& r1, uint32_t& r2, uint32_t& r3,
                                       uint32_t addr) {
    asm volatile("ldmatrix.sync.aligned.m8n8.x4.shared.b16 {%0,%1,%2,%3}, [%4];"
        : "=r"(r0), "=r"(r1), "=r"(r2), "=r"(r3) : "r"(addr));
}
#define CP16(dst, src) asm volatile("cp.async.cg.shared.global [%0], [%1], 16;" :: "r"(dst), "l"(src))
#define CP_COMMIT()    asm volatile("cp.async.commit_group;")
#define CP_WAIT0()     asm volatile("cp.async.wait_group 0;")
#define CP_WAIT1()     asm volatile("cp.async.wait_group 1;")

// ======================= tensor-core NT GEMM: C[M,N] = A[M,K] @ B[N,K]^T ==============
// Plain fp16 single pass. BM=128, BN=128, BK=64. 3-stage cp.async pipeline,
// ONE barrier per chunk. 2 CTAs/SM. (proven round-12 config)
template<bool WC32, bool WC16>
__global__ __launch_bounds__(256, 2)
void mma_gemm(const hlf* __restrict__ Ah, int lda,
              const hlf* __restrict__ Bh, int ldb,
              float* __restrict__ C32, hlf* __restrict__ C16h,
              int ldc, const float* __restrict__ bias, int K, int relu)
{
    constexpr int BN   = 128;
    constexpr int NT   = 8;
    constexpr int RSTR = 144;
    constexpr int AS   = 128 * RSTR;
    constexpr int BS   = BN * RSTR;
    constexpr int STG  = AS + BS;           // 36864; x3 = 110592

    extern __shared__ __align__(16) char dsm[];
    const uint32_t sb = smem_u32(dsm);

    const int tid = threadIdx.x;
    const int lane = tid & 31, wid = tid >> 5;
    const int wm = wid & 3, wn = wid >> 2;
    const int g = lane >> 2, tig = lane & 3;
    const int lrow = lane & 7, seg = lane >> 3;

    const int bm = blockIdx.y * 128, bn = blockIdx.x * BN;

    float acc[2][NT][4];
    #pragma unroll
    for (int mt = 0; mt < 2; mt++)
        #pragma unroll
        for (int nt = 0; nt < NT; nt++)
            #pragma unroll
            for (int j = 0; j < 4; j++) acc[mt][nt][j] = 0.f;

    const int nc = K >> 6;

    auto load_stage = [&](int c) {
        const int k0 = c << 6;
        const uint32_t st = sb + (c % 3) * STG;
        #pragma unroll
        for (int i = 0; i < 4; i++) {
            int idx = tid + i * 256;
            int r = idx >> 3, sg = idx & 7;
            CP16(st + r * RSTR + sg * 16, Ah + (size_t)(bm + r) * lda + k0 + sg * 8);
        }
        #pragma unroll
        for (int i = 0; i < 4; i++) {
            int idx = tid + i * 256;
            int r = idx >> 3, sg = idx & 7;
            CP16(st + AS + r * RSTR + sg * 16, Bh + (size_t)(bn + r) * ldb + k0 + sg * 8);
        }
    };

    load_stage(0); CP_COMMIT();
    load_stage(1); CP_COMMIT();

    for (int c = 0; c < nc; c++) {
        if (c + 1 < nc) CP_WAIT1(); else CP_WAIT0();
        __syncthreads();
        if (c + 2 < nc) { load_stage(c + 2); CP_COMMIT(); }

        const uint32_t st = sb + (c % 3) * STG;
        const uint32_t pA = st, pB = st + AS;

        #pragma unroll
        for (int k16 = 0; k16 < 4; k16++) {
            const uint32_t koff = k16 * 32 + (seg >> 1) * 16;
            uint32_t a[2][4];
            #pragma unroll
            for (int mt = 0; mt < 2; mt++) {
                uint32_t ro = (uint32_t)(wm * 32 + mt * 16 + (seg & 1) * 8 + lrow) * RSTR + koff;
                ldm_x4(a[mt][0], a[mt][1], a[mt][2], a[mt][3], pA + ro);
            }
            uint32_t b[NT][2];
            #pragma unroll
            for (int np = 0; np < NT / 2; np++) {
                uint32_t ro = (uint32_t)(wn * 64 + np * 16 + (seg & 1) * 8 + lrow) * RSTR + koff;
                uint32_t r0, r1, r2, r3;
                ldm_x4(r0, r1, r2, r3, pB + ro);
                b[2*np][0] = r0; b[2*np][1] = r2; b[2*np+1][0] = r1; b[2*np+1][1] = r3;
            }
            #pragma unroll
            for (int nt = 0; nt < NT; nt++)
                #pragma unroll
                for (int mt = 0; mt < 2; mt++)
                    mma16816(acc[mt][nt], a[mt], b[nt]);
        }
    }

    #pragma unroll
    for (int mt = 0; mt < 2; mt++) {
        #pragma unroll
        for (int nt = 0; nt < NT; nt++) {
            int row = bm + wm * 32 + mt * 16 + g;
            int col = bn + wn * 64 + nt * 8 + tig * 2;
            float b0 = 0.f, b1 = 0.f;
            if (bias) { b0 = __ldg(bias + col); b1 = __ldg(bias + col + 1); }
            float v0 = acc[mt][nt][0] + b0, v1 = acc[mt][nt][1] + b1;
            float v2 = acc[mt][nt][2] + b0, v3 = acc[mt][nt][3] + b1;
            if (relu) {
                v0 = fmaxf(v0, 0.f); v1 = fmaxf(v1, 0.f);
                v2 = fmaxf(v2, 0.f); v3 = fmaxf(v3, 0.f);
            }
            size_t o0 = (size_t)row * ldc + col, o1 = (size_t)(row + 8) * ldc + col;
            if (WC32) {
                *(float2*)(C32 + o0) = make_float2(v0, v1);
                *(float2*)(C32 + o1) = make_float2(v2, v3);
            }
            if (WC16) {
                *(uint32_t*)(C16h + o0) = pack_hf(v0, v1);
                *(uint32_t*)(C16h + o1) = pack_hf(v2, v3);
            }
        }
    }
}

// ======================= flash attention: warp-autonomous, register P =================
// Each warp owns 16 q-rows x full 128-col score tile: softmax is warp-local (shfl over
// the 4-lane col group, no smem/barriers), P stays in registers and repacks directly
// into A-fragments for P@V. Only 2 __syncthreads per kv tile (K visible / V visible).
// smem: Q 18432 | K x2 36864 | V 17408 = 72704 -> 2 CTAs/SM.
#define FQR 144
#define FVR 272
#define oQ  0
#define oK0 18432
#define oV  55296
#define FLASH_SMEM 72704

__global__ __launch_bounds__(256, 2)
void flash_attn(const hlf* __restrict__ Qh,
                const hlf* __restrict__ Kh,
                const hlf* __restrict__ Vth,
                hlf* __restrict__ Oh)
{
    extern __shared__ __align__(16) char dsm[];
    const uint32_t sb = smem_u32(dsm);

    const int tid = threadIdx.x;
    const int lane = tid & 31, wid = tid >> 5;
    const int g = lane >> 2, tig = lane & 3;
    const int lrow = lane & 7, seg = lane >> 3;
    const int qrow0 = wid * 16;                  // each warp: 16 q-rows

    const int z = blockIdx.y, n = z >> 4, h = z & 15;
    const int q0 = blockIdx.x * 128;
    const size_t qkbase = (size_t)n * SEQ * D_EMB + h * HD;
    const size_t vbase  = (size_t)z * HD * SEQ;

    // ---- preload Q + K tile 0 (group 0) ----
    #pragma unroll
    for (int i = 0; i < 4; i++) {
        int idx = tid + i * 256;                  // 1024 slots: 128 rows x 8 segs
        int r = idx >> 3, sg = idx & 7;
        uint32_t so = r * FQR + sg * 16;
        CP16(sb + oQ + so, Qh + qkbase + (size_t)(q0 + r) * D_EMB + sg * 8);
        CP16(sb + oK0 + so, Kh + qkbase + (size_t)r * D_EMB + sg * 8);
    }
    CP_COMMIT();

    float m_prev[2], lsum[2], acc_o[8][4];
    m_prev[0] = m_prev[1] = -1e30f;
    lsum[0] = lsum[1] = 0.f;
    #pragma unroll
    for (int nt = 0; nt < 8; nt++)
        #pragma unroll
        for (int j = 0; j < 4; j++) acc_o[nt][j] = 0.f;

    for (int t = 0; t < 16; t++) {
        const int kv0 = t * 128;
        CP_WAIT0();            // K(t) landed (own thread's part)
        __syncthreads();       // all warps' K(t) parts visible; all done reading V(t-1)

        // issue V(t) (single buffer; safe after barrier above)
        #pragma unroll
        for (int i = 0; i < 4; i++) {
            int idx = tid + i * 256;              // 1024 slots: 64 rows x 16 segs
            int r = idx >> 4, sg = idx & 15;
            CP16(sb + oV + r * FVR + sg * 16, Vth + vbase + (size_t)r * SEQ + kv0 + sg * 8);
        }
        CP_COMMIT();
        // issue K(t+1) into other K buffer (clamped on last tile)
        {
            int tn = (t + 1 < 16) ? t + 1 : 15;
            uint32_t kst = oK0 + ((t + 1) & 1) * 18432;
            #pragma unroll
            for (int i = 0; i < 4; i++) {
                int idx = tid + i * 256;
                int r = idx >> 3, sg = idx & 7;
                CP16(sb + kst + r * FQR + sg * 16,
                     Kh + qkbase + (size_t)(tn * 128 + r) * D_EMB + sg * 8);
            }
        }
        CP_COMMIT();

        // ---- scores: S[16 x 128] = Q_warp @ K(t)^T ----
        float s[16][4];
        #pragma unroll
        for (int nt = 0; nt < 16; nt++)
            #pragma unroll
            for (int j = 0; j < 4; j++) s[nt][j] = 0.f;

        const uint32_t kst = sb + oK0 + (t & 1) * 18432;
        #pragma unroll
        for (int k16 = 0; k16 < 4; k16++) {
            const uint32_t koff = k16 * 32 + (seg >> 1) * 16;
            uint32_t a[4];
            {
                uint32_t ro = (uint32_t)(qrow0 + (seg & 1) * 8 + lrow) * FQR + koff;
                ldm_x4(a[0], a[1], a[2], a[3], sb + oQ + ro);
            }
            #pragma unroll
            for (int np = 0; np < 8; np++) {
                uint32_t ro = (uint32_t)(np * 16 + (seg & 1) * 8 + lrow) * FQR + koff;
                uint32_t r0, r1, r2, r3;
                ldm_x4(r0, r1, r2, r3, kst + ro);
                uint32_t b0[2] = { r0, r2 }, b1[2] = { r1, r3 };
                mma16816(s[2*np],     a, b0);
                mma16816(s[2*np + 1], a, b1);
            }
        }

        // ---- online softmax (warp-local; rows qrow0+g and qrow0+8+g) ----
        float mloc[2] = { -1e30f, -1e30f };
        #pragma unroll
        for (int nt = 0; nt < 16; nt++) {
            mloc[0] = fmaxf(mloc[0], fmaxf(s[nt][0], s[nt][1]));
            mloc[1] = fmaxf(mloc[1], fmaxf(s[nt][2], s[nt][3]));
        }
        #pragma unroll
        for (int i = 0; i < 2; i++) {
            mloc[i] = fmaxf(mloc[i], __shfl_xor_sync(0xffffffffu, mloc[i], 1));
            mloc[i] = fmaxf(mloc[i], __shfl_xor_sync(0xffffffffu, mloc[i], 2));
        }
        float m_new[2], alpha[2];
        #pragma unroll
        for (int i = 0; i < 2; i++) {
            float mn = fmaxf(m_prev[i], mloc[i] * 0.125f);
            alpha[i] = __expf(m_prev[i] - mn);
            m_new[i] = mn;
            m_prev[i] = mn;
        }
        float sl[2] = { 0.f, 0.f };
        #pragma unroll
        for (int nt = 0; nt < 16; nt++) {
            float p0 = __expf(s[nt][0] * 0.125f - m_new[0]);
            float p1 = __expf(s[nt][1] * 0.125f - m_new[0]);
            float p2 = __expf(s[nt][2] * 0.125f - m_new[1]);
            float p3 = __expf(s[nt][3] * 0.125f - m_new[1]);
            s[nt][0] = p0; s[nt][1] = p1; s[nt][2] = p2; s[nt][3] = p3;
            sl[0] += p0 + p1; sl[1] += p2 + p3;
        }
        #pragma unroll
        for (int i = 0; i < 2; i++) {
            sl[i] += __shfl_xor_sync(0xffffffffu, sl[i], 1);
            sl[i] += __shfl_xor_sync(0xffffffffu, sl[i], 2);
            lsum[i] = lsum[i] * alpha[i] + sl[i];
        }
        // rescale O
        #pragma unroll
        for (int nt = 0; nt < 8; nt++) {
            acc_o[nt][0] *= alpha[0]; acc_o[nt][1] *= alpha[0];
            acc_o[nt][2] *= alpha[1]; acc_o[nt][3] *= alpha[1];
        }
        // pack P: score c-frags (tiles 2kc, 2kc+1) -> A-frag for k16 chunk kc
        uint32_t pa[8][4];
        #pragma unroll
        for (int kc = 0; kc < 8; kc++) {
            pa[kc][0] = pack_hf(s[2*kc][0],     s[2*kc][1]);
            pa[kc][1] = pack_hf(s[2*kc][2],     s[2*kc][3]);
            pa[kc][2] = pack_hf(s[2*kc + 1][0], s[2*kc + 1][1]);
            pa[kc][3] = pack_hf(s[2*kc + 1][2], s[2*kc + 1][3]);
        }

        CP_WAIT1();            // V(t) landed (K(t+1) still in flight)
        __syncthreads();       // all warps' V(t) parts visible

        // ---- O[16 x 64] += P @ V   (V^T tile in smem: [64 dim][128 kv]) ----
        #pragma unroll
        for (int kc = 0; kc < 8; kc++) {
            const uint32_t koff = kc * 32 + (seg >> 1) * 16;
            #pragma unroll
            for (int np = 0; np < 4; np++) {
                uint32_t ro = (uint32_t)(np * 16 + (seg & 1) * 8 + lrow) * FVR + koff;
                uint32_t r0, r1, r2, r3;
                ldm_x4(r0, r1, r2, r3, sb + oV + ro);
                uint32_t b0[2] = { r0, r2 }, b1[2] = { r1, r3 };
                mma16816(acc_o[2*np],     pa[kc], b0);
                mma16816(acc_o[2*np + 1], pa[kc], b1);
            }
        }
    }

    // ---- epilogue: O / l -> fp16 ----
    #pragma unroll
    for (int hf = 0; hf < 2; hf++) {
        int row = qrow0 + hf * 8 + g;
        float inv = 1.f / lsum[hf];
        #pragma unroll
        for (int nt = 0; nt < 8; nt++) {
            float c0 = acc_o[nt][hf*2]   * inv;
            float c1 = acc_o[nt][hf*2+1] * inv;
            int col = nt * 8 + tig * 2;
            size_t go = qkbase + (size_t)(q0 + row) * D_EMB + col;
            *(uint32_t*)(Oh + go) = pack_hf(c0, c1);
        }
    }
}

// ======================= support kernels ==============================================
__global__ void cvt_hi(const float* __restrict__ in, hlf* __restrict__ oh, size_t n4)
{
    size_t i = (size_t)blockIdx.x * blockDim.x + threadIdx.x;
    if (i >= n4) return;
    float4 v = *(const float4*)(in + i * 4);
    *(uint2*)(oh + i * 4) = make_uint2(pack_hf(v.x, v.y), pack_hf(v.z, v.w));
}

__global__ void transpose_cvt(const float* __restrict__ in, hlf* __restrict__ oh,
                              int R, int C)
{
    __shared__ float t[32][33];
    int r0 = blockIdx.y * 32, c0 = blockIdx.x * 32;
    t[threadIdx.y][threadIdx.x] = in[(size_t)(r0 + threadIdx.y) * C + c0 + threadIdx.x];
    __syncthreads();
    oh[(size_t)(c0 + threadIdx.y) * R + r0 + threadIdx.x] = __float2half(t[threadIdx.x][threadIdx.y]);
}

// VT[z][d][s] = Vh[n][s][h*64+d] (fp16 -> fp16 transpose per head)
__global__ void vt_build_h(const hlf* __restrict__ Vh, hlf* __restrict__ VTh)
{
    __shared__ hlf t[32][34];
    int z = blockIdx.z, n = z >> 4, h = z & 15;
    int s0 = blockIdx.x * 32, d0 = blockIdx.y * 32;
    t[threadIdx.y][threadIdx.x] =
        Vh[(size_t)n * SEQ * D_EMB + (size_t)(s0 + threadIdx.y) * D_EMB + h * HD + d0 + threadIdx.x];
    __syncthreads();
    VTh[((size_t)z * HD + d0 + threadIdx.y) * SEQ + s0 + threadIdx.x] = t[threadIdx.x][threadIdx.y];
}

__global__ void add_ln(const float* __restrict__ X, const float* __restrict__ R,
                       const float* __restrict__ g, const float* __restrict__ b,
                       float* __restrict__ Y, hlf* __restrict__ Yh)
{
    const int row = blockIdx.x;
    const float* px = X + (size_t)row * D_EMB;
    const float* pr = R + (size_t)row * D_EMB;
    const int tid = threadIdx.x;
    float v[4];
    float s = 0.f, s2 = 0.f;
    #pragma unroll
    for (int i = 0; i < 4; i++) {
        int c = tid + i*256;
        v[i] = px[c] + pr[c];
        s += v[i]; s2 += v[i]*v[i];
    }
    #pragma unroll
    for (int o = 16; o; o >>= 1) {
        s  += __shfl_xor_sync(0xffffffffu, s,  o);
        s2 += __shfl_xor_sync(0xffffffffu, s2, o);
    }
    __shared__ float sh[8], sh2[8];
    if ((tid & 31) == 0) { sh[tid >> 5] = s; sh2[tid >> 5] = s2; }
    __syncthreads();
    s = 0.f; s2 = 0.f;
    #pragma unroll
    for (int i = 0; i < 8; i++) { s += sh[i]; s2 += sh2[i]; }
    const float mean = s * (1.f / D_EMB);
    const float var  = s2 * (1.f / D_EMB) - mean * mean;
    const float rstd = rsqrtf(var + 1e-5f);
    #pragma unroll
    for (int i = 0; i < 4; i++) {
        int c = tid + i*256;
        float y = (v[i] - mean) * rstd * g[c] + b[c];
        Y[(size_t)row * D_EMB + c] = y;
        if (Yh) Yh[(size_t)row * D_EMB + c] = __float2half(y);
    }
}

// ======================================================================================
extern "C" void kernel_launch(void* const* d_in, const int* in_sizes, int n_in,
                              void* d_out, int out_size)
{
    const float* trg  = (const float*)d_in[0];
    const float* src  = (const float*)d_in[1];
    const float* Wq1  = (const float*)d_in[4];
    const float* bq1  = (const float*)d_in[5];
    const float* Wo1  = (const float*)d_in[6];
    const float* bo1  = (const float*)d_in[7];
    const float* Wq2  = (const float*)d_in[8];
    const float* bq2  = (const float*)d_in[9];
    const float* Wo2  = (const float*)d_in[10];
    const float* bo2  = (const float*)d_in[11];
    const float* Wff1 = (const float*)d_in[12];
    const float* bff1 = (const float*)d_in[13];
    const float* Wff2 = (const float*)d_in[14];
    const float* bff2 = (const float*)d_in[15];
    const float* ln1g = (const float*)d_in[16];
    const float* ln1b = (const float*)d_in[17];
    const float* ln2g = (const float*)d_in[18];
    const float* ln2b = (const float*)d_in[19];
    const float* ln3g = (const float*)d_in[20];
    const float* ln3b = (const float*)d_in[21];
    float* out = (float*)d_out;

    float *TMP, *X1, *X2;
    cudaGetSymbolAddress((void**)&TMP, g_TMP);
    cudaGetSymbolAddress((void**)&X1,  g_X1);
    cudaGetSymbolAddress((void**)&X2,  g_X2);
    hlf *trgH,*srcH,*Q1H,*Q2H,*KVH,*ATH,*X1H,*X2H,*HH,*VTH;
    hlf *WqT1H,*WoT1H,*WqT2H,*WoT2H,*Wff1TH,*Wff2TH;
    cudaGetSymbolAddress((void**)&trgH, g_trgH);
    cudaGetSymbolAddress((void**)&srcH, g_srcH);
    cudaGetSymbolAddress((void**)&Q1H,  g_Q1H);
    cudaGetSymbolAddress((void**)&Q2H,  g_Q2H);
    cudaGetSymbolAddress((void**)&KVH,  g_KVH);
    cudaGetSymbolAddress((void**)&ATH,  g_ATH);
    cudaGetSymbolAddress((void**)&X1H,  g_X1H);
    cudaGetSymbolAddress((void**)&X2H,  g_X2H);
    cudaGetSymbolAddress((void**)&HH,   g_HH);
    cudaGetSymbolAddress((void**)&VTH,  g_VTH);
    cudaGetSymbolAddress((void**)&WqT1H, g_WqT1H);
    cudaGetSymbolAddress((void**)&WoT1H, g_WoT1H);
    cudaGetSymbolAddress((void**)&WqT2H, g_WqT2H);
    cudaGetSymbolAddress((void**)&WoT2H, g_WoT2H);
    cudaGetSymbolAddress((void**)&Wff1TH, g_Wff1TH);
    cudaGetSymbolAddress((void**)&Wff2TH, g_Wff2TH);

    const int SMG = 3 * 36864;   // 110592; 2 CTAs/SM
    cudaFuncSetAttribute(mma_gemm<false,true >, cudaFuncAttributeMaxDynamicSharedMemorySize, SMG);
    cudaFuncSetAttribute(mma_gemm<true ,false>, cudaFuncAttributeMaxDynamicSharedMemorySize, SMG);
    cudaFuncSetAttribute(flash_attn, cudaFuncAttributeMaxDynamicSharedMemorySize, FLASH_SMEM);

    const dim3 t32(32, 32);
    const dim3 blk(256);
    const dim3 gP (D_EMB / 128, ROWS / 128);        // 8 x 32
    const dim3 gF1(D_FF / 128, ROWS / 128);         // 32 x 32
    const dim3 gFA(SEQ / 128, NB*HEADS);            // 16 x 32
    const dim3 gVT(SEQ / 32, HD / 32, NB*HEADS);

    cvt_hi<<<(ROWS*D_EMB/4 + 255)/256, 256>>>(trg, trgH, (size_t)ROWS*D_EMB/4);
    cvt_hi<<<(ROWS*D_EMB/4 + 255)/256, 256>>>(src, srcH, (size_t)ROWS*D_EMB/4);
    transpose_cvt<<<dim3(32, 32), t32>>>(Wq1, WqT1H, D_EMB, D_EMB);

    // ---- self-attention: shared Wq1 on trg => qp==kp==vp, one projection
    mma_gemm<false,true ><<<gP, blk, SMG>>>(trgH, D_EMB, WqT1H, D_EMB,
                                            nullptr, Q1H, D_EMB, bq1, D_EMB, 0);
    vt_build_h<<<gVT, t32>>>(Q1H, VTH);
    flash_attn<<<gFA, blk, FLASH_SMEM>>>(Q1H, Q1H, VTH, ATH);
    transpose_cvt<<<dim3(32, 32), t32>>>(Wo1, WoT1H, D_EMB, D_EMB);
    mma_gemm<true ,false><<<gP, blk, SMG>>>(ATH, D_EMB, WoT1H, D_EMB,
                                            TMP, nullptr, D_EMB, bo1, D_EMB, 0);
    add_ln<<<ROWS, 256>>>(trg, TMP, ln1g, ln1b, X1, X1H);

    // ---- cross-attention: K and V share the same projection of encoded_src
    transpose_cvt<<<dim3(32, 32), t32>>>(Wq2, WqT2H, D_EMB, D_EMB);
    mma_gemm<false,true ><<<gP, blk, SMG>>>(X1H, D_EMB, WqT2H, D_EMB,
                                            nullptr, Q2H, D_EMB, bq2, D_EMB, 0);
    mma_gemm<false,true ><<<gP, blk, SMG>>>(srcH, D_EMB, WqT2H, D_EMB,
                                            nullptr, KVH, D_EMB, bq2, D_EMB, 0);
    vt_build_h<<<gVT, t32>>>(KVH, VTH);
    flash_attn<<<gFA, blk, FLASH_SMEM>>>(Q2H, KVH, VTH, ATH);
    transpose_cvt<<<dim3(32, 32), t32>>>(Wo2, WoT2H, D_EMB, D_EMB);
    mma_gemm<true ,false><<<gP, blk, SMG>>>(ATH, D_EMB, WoT2H, D_EMB,
                                            TMP, nullptr, D_EMB, bo2, D_EMB, 0);
    add_ln<<<ROWS, 256>>>(X1, TMP, ln2g, ln2b, X2, X2H);

    // ---- FFN
    transpose_cvt<<<dim3(128, 32), t32>>>(Wff1, Wff1TH, D_EMB, D_FF);
    mma_gemm<false,true ><<<gF1, blk, SMG>>>(X2H, D_EMB, Wff1TH, D_EMB,
                                             nullptr, HH, D_FF, bff1, D_EMB, 1);
    transpose_cvt<<<dim3(32, 128), t32>>>(Wff2, Wff2TH, D_FF, D_EMB);
    mma_gemm<true ,false><<<gP, blk, SMG>>>(HH, D_FF, Wff2TH, D_FF,
                                            TMP, nullptr, D_EMB, bff2, D_FF, 0);
    add_ln<<<ROWS, 256>>>(X2, TMP, ln3g, ln3b, out, nullptr);
}